// round 12
// baseline (speedup 1.0000x reference)
#include <cuda_runtime.h>
#include <cuda_fp16.h>
#include <math.h>
#include <stdint.h>

// ---------------- problem constants ----------------
#define DIMC    768
#define HEADS   12
#define HDIM    64
#define WS      14
#define NTOK    196
#define MLPD    3072
#define BATCH   4
#define IMGH    64
#define IMGW    64
#define NWIN    100
#define NROWS_WIN (NWIN*NTOK)        // 19600
#define NROWS_IMG (BATCH*IMGH*IMGW)  // 16384
#define SCALE_F 0.125f
#define EPS_F   1e-6f

// ---------------- scratch ----------------
__device__ float   g_xnhwc[BATCH*IMGH*IMGW*DIMC];
__device__ __half  g_xwin [NROWS_WIN*DIMC];
__device__ __half  g_qkv  [NROWS_WIN*3*DIMC];
__device__ __half  g_attno[NROWS_WIN*DIMC];
__device__ float   g_proj [NROWS_WIN*DIMC];
__device__ float   g_x1   [NROWS_IMG*DIMC];
__device__ __half  g_yln  [NROWS_IMG*DIMC];
__device__ __half  g_h1   [NROWS_IMG*MLPD];
__device__ float   g_y2   [NROWS_IMG*DIMC];
// transposed weights (K-major B operands: Bt[n][k]), fp16
__device__ __half  g_qkvT [3*DIMC*DIMC];
__device__ __half  g_projT[DIMC*DIMC];
__device__ __half  g_fc1T [MLPD*DIMC];
__device__ __half  g_fc2T [DIMC*MLPD];

// ================= helpers =================
__device__ __forceinline__ uint32_t smem_u32(const void* p) {
    uint32_t a;
    asm("{ .reg .u64 t; cvta.to.shared.u64 t, %1; cvt.u32.u64 %0, t; }" : "=r"(a) : "l"(p));
    return a;
}
__device__ __forceinline__ void cp_async16(uint32_t dst, const void* src) {
    asm volatile("cp.async.cg.shared.global [%0], [%1], 16;" :: "r"(dst), "l"(src));
}
#define CP_COMMIT() asm volatile("cp.async.commit_group;" ::: "memory")
#define CP_WAIT(n)  asm volatile("cp.async.wait_group %0;" :: "n"(n) : "memory")

__device__ __forceinline__ void mma_f16(float* c, const uint32_t* a, const uint32_t* b) {
    asm volatile(
        "mma.sync.aligned.m16n8k16.row.col.f32.f16.f16.f32 "
        "{%0,%1,%2,%3}, {%4,%5,%6,%7}, {%8,%9}, {%0,%1,%2,%3};"
        : "+f"(c[0]), "+f"(c[1]), "+f"(c[2]), "+f"(c[3])
        : "r"(a[0]), "r"(a[1]), "r"(a[2]), "r"(a[3]), "r"(b[0]), "r"(b[1]));
}
__device__ __forceinline__ void ldmx4(uint32_t& r0, uint32_t& r1, uint32_t& r2, uint32_t& r3,
                                      uint32_t addr) {
    asm volatile("ldmatrix.sync.aligned.m8n8.x4.shared.b16 {%0,%1,%2,%3}, [%4];"
        : "=r"(r0), "=r"(r1), "=r"(r2), "=r"(r3) : "r"(addr));
}

// ================= fp16 mma.sync GEMM (R10-proven) =================
#define BM 128
#define BN 128
#define BKE 32
#define LDW 20
#define TBUF (BM*LDW)
#define GEMM_SMEM ((4*TBUF + 128) * 4)

__global__ void __launch_bounds__(256, 2)
k_mma_gemm(const __half* __restrict__ A, const __half* __restrict__ Bt,
           const float* __restrict__ bias, void* __restrict__ Cout,
           int M, int N, int K, int act, int outf16) {
    extern __shared__ float sm[];
    uint32_t* As = (uint32_t*)sm;
    uint32_t* Bs = As + 2*TBUF;
    float* sbias = sm + 4*TBUF;

    int tid = threadIdx.x, lane = tid & 31, wid = tid >> 5;
    int wm = wid >> 1, wn = wid & 1;
    int m0 = blockIdx.y * BM, n0 = blockIdx.x * BN;

    if (tid < 128) sbias[tid] = bias[n0 + tid];

    auto load_tile = [&](int kc, int bsel) {
        int k0 = kc * BKE;
        uint32_t* abuf = As + bsel * TBUF;
        uint32_t* bbuf = Bs + bsel * TBUF;
        #pragma unroll
        for (int it = 0; it < 2; it++) {
            int idx = tid + it * 256;
            int r = idx >> 2, c = idx & 3;
            int ar = m0 + r;
            const __half* asrc = A + (long)(ar < M ? ar : M - 1) * K + k0 + c * 8;
            cp_async16(smem_u32(abuf + r * LDW + c * 4), asrc);
            const __half* bsrc = Bt + (long)(n0 + r) * K + k0 + c * 8;
            cp_async16(smem_u32(bbuf + r * LDW + c * 4), bsrc);
        }
        CP_COMMIT();
    };

    int m8 = lane >> 3, r8 = lane & 7;
    uint32_t aoff[2], boff[4];
    #pragma unroll
    for (int mt = 0; mt < 2; mt++)
        aoff[mt] = (uint32_t)((wm * 32 + mt * 16 + (m8 & 1) * 8 + r8) * LDW + (m8 >> 1) * 4);
    #pragma unroll
    for (int p = 0; p < 4; p++)
        boff[p] = (uint32_t)((wn * 64 + p * 16 + (m8 >> 1) * 8 + r8) * LDW + (m8 & 1) * 4);
    uint32_t a_base = smem_u32(As);
    uint32_t b_base = smem_u32(Bs);

    float acc[2][8][4];
    #pragma unroll
    for (int mt = 0; mt < 2; mt++)
        #pragma unroll
        for (int nt = 0; nt < 8; nt++)
            #pragma unroll
            for (int j = 0; j < 4; j++) acc[mt][nt][j] = 0.f;

    const int NKC = K / BKE;
    load_tile(0, 0);
    for (int i = 0; i < NKC; i++) {
        int cur = i & 1;
        if (i + 1 < NKC) { load_tile(i + 1, cur ^ 1); CP_WAIT(1); }
        else             { CP_WAIT(0); }
        __syncthreads();
        uint32_t ab = a_base + cur * (TBUF * 4);
        uint32_t bb = b_base + cur * (TBUF * 4);
        #pragma unroll
        for (int ks = 0; ks < 2; ks++) {
            uint32_t af[2][4], bf[8][2];
            #pragma unroll
            for (int mt = 0; mt < 2; mt++)
                ldmx4(af[mt][0], af[mt][1], af[mt][2], af[mt][3],
                      ab + (aoff[mt] + ks * 8) * 4);
            #pragma unroll
            for (int p = 0; p < 4; p++)
                ldmx4(bf[2*p][0], bf[2*p][1], bf[2*p+1][0], bf[2*p+1][1],
                      bb + (boff[p] + ks * 8) * 4);
            #pragma unroll
            for (int mt = 0; mt < 2; mt++)
                #pragma unroll
                for (int nt = 0; nt < 8; nt++)
                    mma_f16(acc[mt][nt], af[mt], bf[nt]);
        }
        __syncthreads();
    }

    int rb = m0 + wm * 32 + (lane >> 2);
    int cb = wn * 64 + 2 * (lane & 3);
    #pragma unroll
    for (int mt = 0; mt < 2; mt++) {
        int r0 = rb + mt * 16, r1 = r0 + 8;
        #pragma unroll
        for (int nt = 0; nt < 8; nt++) {
            int cc = cb + nt * 8;
            float v0 = acc[mt][nt][0] + sbias[cc];
            float v1 = acc[mt][nt][1] + sbias[cc + 1];
            float v2 = acc[mt][nt][2] + sbias[cc];
            float v3 = acc[mt][nt][3] + sbias[cc + 1];
            if (act == 1) {
                v0 = 0.5f * v0 * (1.0f + erff(v0 * 0.70710678118654752f));
                v1 = 0.5f * v1 * (1.0f + erff(v1 * 0.70710678118654752f));
                v2 = 0.5f * v2 * (1.0f + erff(v2 * 0.70710678118654752f));
                v3 = 0.5f * v3 * (1.0f + erff(v3 * 0.70710678118654752f));
            }
            if (outf16) {
                __half* C = (__half*)Cout;
                if (r0 < M) *(__half2*)(C + (long)r0 * N + n0 + cc) = __floats2half2_rn(v0, v1);
                if (r1 < M) *(__half2*)(C + (long)r1 * N + n0 + cc) = __floats2half2_rn(v2, v3);
            } else {
                float* C = (float*)Cout;
                if (r0 < M) *(float2*)(C + (long)r0 * N + n0 + cc) = make_float2(v0, v1);
                if (r1 < M) *(float2*)(C + (long)r1 * N + n0 + cc) = make_float2(v2, v3);
            }
        }
    }
}

// ---------------- NCHW -> NHWC transpose ----------------
__global__ void k_transpose_in(const float* __restrict__ in, float* __restrict__ out) {
    __shared__ float tile[32][33];
    int b = blockIdx.z, c0 = blockIdx.y * 32, s0 = blockIdx.x * 32;
    const float* ib = in + (long)b * DIMC * 4096;
    float* ob = out + (long)b * 4096 * DIMC;
    int x = threadIdx.x, y = threadIdx.y;
    #pragma unroll
    for (int i = 0; i < 32; i += 8)
        tile[y + i][x] = ib[(long)(c0 + y + i) * 4096 + s0 + x];
    __syncthreads();
    #pragma unroll
    for (int i = 0; i < 32; i += 8)
        ob[(long)(s0 + y + i) * DIMC + c0 + x] = tile[x][y + i];
}

// ---------------- weight transpose to fp16 ----------------
__global__ void k_transpose_w(const float* __restrict__ in, __half* __restrict__ out,
                              int R, int C) {
    __shared__ float tile[32][33];
    int r0 = blockIdx.y * 32, c0 = blockIdx.x * 32;
    int x = threadIdx.x, y = threadIdx.y;
    #pragma unroll
    for (int i = 0; i < 32; i += 8)
        tile[y + i][x] = in[(long)(r0 + y + i) * C + c0 + x];
    __syncthreads();
    #pragma unroll
    for (int i = 0; i < 32; i += 8)
        out[(long)(c0 + y + i) * R + r0 + x] = __float2half_rn(tile[x][y + i]);
}

// ---------------- block reduction ----------------
__device__ __forceinline__ float block_sum_256(float v, float* red) {
    int tid = threadIdx.x;
    #pragma unroll
    for (int o = 16; o > 0; o >>= 1) v += __shfl_xor_sync(0xffffffffu, v, o);
    if ((tid & 31) == 0) red[tid >> 5] = v;
    __syncthreads();
    float r = 0.f;
    if (tid < 8) {
        r = red[tid];
        #pragma unroll
        for (int o = 4; o > 0; o >>= 1) r += __shfl_xor_sync(0xffu, r, o);
        if (tid == 0) red[0] = r;
    }
    __syncthreads();
    r = red[0];
    __syncthreads();
    return r;
}

// ---------------- LN1 + window partition (fp16 output) ----------------
__global__ void k_ln1_window(const float* __restrict__ xnhwc,
                             const float* __restrict__ w, const float* __restrict__ bs,
                             __half* __restrict__ xwin) {
    __shared__ float red[8];
    int idx = blockIdx.x;
    int win = idx / NTOK, t = idx % NTOK;
    int b = win / 25, wrem = win % 25;
    int gr = (wrem / 5) * WS + t / WS;
    int gc = (wrem % 5) * WS + t % WS;
    __half* orow = xwin + (long)idx * DIMC;
    int tid = threadIdx.x;
    if (gr >= IMGH || gc >= IMGW) {
        for (int c = tid; c < DIMC; c += 256) orow[c] = __float2half_rn(0.f);
        return;
    }
    const float* irow = xnhwc + ((long)b * 4096 + gr * IMGW + gc) * DIMC;
    float v[3], s = 0.f, s2 = 0.f;
    #pragma unroll
    for (int i = 0; i < 3; i++) { float x = irow[tid + i * 256]; v[i] = x; s += x; s2 += x * x; }
    float tot = block_sum_256(s, red);
    float tot2 = block_sum_256(s2, red);
    float mu = tot * (1.f / DIMC);
    float rstd = rsqrtf(tot2 * (1.f / DIMC) - mu * mu + EPS_F);
    #pragma unroll
    for (int i = 0; i < 3; i++) {
        int c = tid + i * 256;
        orow[c] = __float2half_rn((v[i] - mu) * rstd * w[c] + bs[c]);
    }
}

// ---------------- fused: window unpartition + residual + LN2 ----------------
__global__ void k_scatter_ln2(const float* __restrict__ xnhwc, const float* __restrict__ proj,
                              const float* __restrict__ w, const float* __restrict__ bs,
                              float* __restrict__ x1, __half* __restrict__ yln) {
    __shared__ float red[8];
    int row = blockIdx.x;
    int b = row >> 12, sp = row & 4095;
    int r = sp >> 6, cw = sp & 63;
    int win = b * 25 + (r / WS) * 5 + (cw / WS);
    int t = (r % WS) * WS + (cw % WS);
    const float* prow = proj + ((long)win * NTOK + t) * DIMC;
    const float* xrow = xnhwc + (long)row * DIMC;
    float* orow = x1 + (long)row * DIMC;
    __half* lrow = yln + (long)row * DIMC;
    int tid = threadIdx.x;
    float v[3], s = 0.f, s2 = 0.f;
    #pragma unroll
    for (int i = 0; i < 3; i++) {
        int c = tid + i * 256;
        float x = xrow[c] + prow[c];
        orow[c] = x;
        v[i] = x; s += x; s2 += x * x;
    }
    float tot = block_sum_256(s, red);
    float tot2 = block_sum_256(s2, red);
    float mu = tot * (1.f / DIMC);
    float rstd = rsqrtf(tot2 * (1.f / DIMC) - mu * mu + EPS_F);
    #pragma unroll
    for (int i = 0; i < 3; i++) {
        int c = tid + i * 256;
        lrow[c] = __float2half_rn((v[i] - mu) * rstd * w[c] + bs[c]);
    }
}

// ---------------- fused windowed attention: 2 threads per query --------------
// qkv fp16 in; K/V fp32 smem; dot products use 4 independent accumulators
// (reassociated) to break the 32-deep serial FMA chain.
#define RELSTRIDE 65
#define QSTRIDE   17
#define ATTN_THREADS 392
#define ATTN_SMEM ((2*NTOK*HDIM + 2*27*RELSTRIDE + 2*NTOK*QSTRIDE) * sizeof(float))

__global__ void __launch_bounds__(ATTN_THREADS, 1)
k_attn(const __half* __restrict__ qkv,
       const float* __restrict__ rel_pos_h,
       const float* __restrict__ rel_pos_w,
       __half* __restrict__ attnout) {
    extern __shared__ float smn[];
    float* Ks   = smn;
    float* Vs   = smn + NTOK * HDIM;
    float* RHsm = smn + 2 * NTOK * HDIM;
    float* RWsm = RHsm + 27 * RELSTRIDE;
    float* RHq  = RWsm + 27 * RELSTRIDE;
    float* RWq  = RHq + NTOK * QSTRIDE;

    int bidx = blockIdx.x;
    int win = bidx / HEADS, head = bidx % HEADS;
    int tid = threadIdx.x;
    const __half* qkv_win = qkv + (long)win * NTOK * (3 * DIMC);

    for (int i = tid; i < NTOK * 8; i += ATTN_THREADS) {
        int t = i >> 3, c = i & 7;
        const __half2* ksrc = (const __half2*)(qkv_win + (long)t * (3 * DIMC) + DIMC + head * HDIM + c * 8);
        const __half2* vsrc = (const __half2*)(qkv_win + (long)t * (3 * DIMC) + 2 * DIMC + head * HDIM + c * 8);
        float* kdst = Ks + t * HDIM + c * 8;
        float* vdst = Vs + t * HDIM + c * 8;
        #pragma unroll
        for (int j = 0; j < 4; j++) {
            float2 kf = __half22float2(ksrc[j]);
            float2 vf = __half22float2(vsrc[j]);
            kdst[2*j] = kf.x; kdst[2*j+1] = kf.y;
            vdst[2*j] = vf.x; vdst[2*j+1] = vf.y;
        }
    }
    for (int i = tid; i < 27 * HDIM; i += ATTN_THREADS) {
        int r = i >> 6, d = i & 63;
        RHsm[r * RELSTRIDE + d] = rel_pos_h[i];
        RWsm[r * RELSTRIDE + d] = rel_pos_w[i];
    }
    __syncthreads();

    int q = tid >> 1, half = tid & 1;
    int qh = q / WS, qw = q % WS;
    unsigned pmask = ((tid & ~31) == 384) ? 0x000000ffu : 0xffffffffu;

    float qv[32];
    {
        const __half* qp = qkv_win + (long)q * (3 * DIMC) + head * HDIM + half * 32;
        #pragma unroll
        for (int d = 0; d < 32; d += 2) {
            float2 f = __half22float2(*(const __half2*)(qp + d));
            qv[d] = f.x; qv[d+1] = f.y;
        }
    }

    // rel-pos biases: 4 independent accumulator chains each
    #pragma unroll
    for (int kh = 0; kh < WS; kh++) {
        const float* ph = &RHsm[(qh - kh + WS - 1) * RELSTRIDE + half * 32];
        const float* pw = &RWsm[(qw - kh + WS - 1) * RELSTRIDE + half * 32];
        float h0 = 0.f, h1 = 0.f, h2 = 0.f, h3 = 0.f;
        float w0 = 0.f, w1 = 0.f, w2 = 0.f, w3 = 0.f;
        #pragma unroll
        for (int d = 0; d < 32; d += 4) {
            h0 = fmaf(qv[d+0], ph[d+0], h0); h1 = fmaf(qv[d+1], ph[d+1], h1);
            h2 = fmaf(qv[d+2], ph[d+2], h2); h3 = fmaf(qv[d+3], ph[d+3], h3);
            w0 = fmaf(qv[d+0], pw[d+0], w0); w1 = fmaf(qv[d+1], pw[d+1], w1);
            w2 = fmaf(qv[d+2], pw[d+2], w2); w3 = fmaf(qv[d+3], pw[d+3], w3);
        }
        float sh = (h0 + h1) + (h2 + h3);
        float sw = (w0 + w1) + (w2 + w3);
        sh += __shfl_xor_sync(pmask, sh, 1);
        sw += __shfl_xor_sync(pmask, sw, 1);
        if (half == 0) { RHq[q * QSTRIDE + kh] = sh; RWq[q * QSTRIDE + kh] = sw; }
    }
    #pragma unroll
    for (int d = 0; d < 32; d++) qv[d] *= SCALE_F;
    __syncthreads();

    float m = -1e30f, l = 0.f;
    float acc[32];
    #pragma unroll
    for (int d = 0; d < 32; d++) acc[d] = 0.f;

    const float* rhq = RHq + q * QSTRIDE;
    const float* rwq = RWq + q * QSTRIDE;
    const float* KsH = Ks + half * 32;
    const float* VsH = Vs + half * 32;

    int kh = 0, kw = 0;
    for (int k = 0; k < NTOK; k++) {
        // QK dot: 4 independent accumulator chains (8 deep each)
        float p0 = 0.f, p1 = 0.f, p2 = 0.f, p3 = 0.f;
        const float4* kp = (const float4*)(KsH + k * HDIM);
        #pragma unroll
        for (int d4 = 0; d4 < 8; d4++) {
            float4 kv = kp[d4];
            p0 = fmaf(qv[d4*4+0], kv.x, p0); p1 = fmaf(qv[d4*4+1], kv.y, p1);
            p2 = fmaf(qv[d4*4+2], kv.z, p2); p3 = fmaf(qv[d4*4+3], kv.w, p3);
        }
        float part = (p0 + p1) + (p2 + p3);
        part += __shfl_xor_sync(pmask, part, 1);
        float s = rhq[kh] + rwq[kw] + part;
        if (++kw == WS) { kw = 0; kh++; }
        float p;
        if (s > m) {
            float corr = __expf(m - s);
            l *= corr;
            #pragma unroll
            for (int d = 0; d < 32; d++) acc[d] *= corr;
            m = s; p = 1.f;
        } else {
            p = __expf(s - m);
        }
        l += p;
        const float4* vp = (const float4*)(VsH + k * HDIM);
        #pragma unroll
        for (int d4 = 0; d4 < 8; d4++) {
            float4 vv = vp[d4];
            acc[d4*4+0] = fmaf(p, vv.x, acc[d4*4+0]);
            acc[d4*4+1] = fmaf(p, vv.y, acc[d4*4+1]);
            acc[d4*4+2] = fmaf(p, vv.z, acc[d4*4+2]);
            acc[d4*4+3] = fmaf(p, vv.w, acc[d4*4+3]);
        }
    }
    float inv = 1.f / l;
    __half* op = attnout + ((long)win * NTOK + q) * DIMC + head * HDIM + half * 32;
    #pragma unroll
    for (int d = 0; d < 32; d++) op[d] = __float2half_rn(acc[d] * inv);
}

// ---------------- final: x1 + mlp_out, NHWC -> NCHW ----------------
__global__ void k_final(const float* __restrict__ x1, const float* __restrict__ y2,
                        float* __restrict__ out) {
    __shared__ float tile[32][33];
    int b = blockIdx.z, s0 = blockIdx.x * 32, c0 = blockIdx.y * 32;
    int x = threadIdx.x, y = threadIdx.y;
    #pragma unroll
    for (int i = 0; i < 32; i += 8) {
        long row = (long)b * 4096 + s0 + y + i;
        tile[y + i][x] = x1[row * DIMC + c0 + x] + y2[row * DIMC + c0 + x];
    }
    __syncthreads();
    #pragma unroll
    for (int i = 0; i < 32; i += 8)
        out[((long)b * DIMC + c0 + y + i) * 4096 + s0 + x] = tile[x][y + i];
}

// ---------------- launcher ----------------
extern "C" void kernel_launch(void* const* d_in, const int* in_sizes, int n_in,
                              void* d_out, int out_size) {
    const float* hidden = (const float*)d_in[0];
    const float* ln1_w = (const float*)d_in[1];
    const float* ln1_b = (const float*)d_in[2];
    const float* qkv_w = (const float*)d_in[3];
    const float* qkv_b = (const float*)d_in[4];
    const float* proj_w = (const float*)d_in[5];
    const float* proj_b = (const float*)d_in[6];
    const float* relh = (const float*)d_in[7];
    const float* relw = (const float*)d_in[8];
    const float* ln2_w = (const float*)d_in[9];
    const float* ln2_b = (const float*)d_in[10];
    const float* fc1_w = (const float*)d_in[11];
    const float* fc1_b = (const float*)d_in[12];
    const float* fc2_w = (const float*)d_in[13];
    const float* fc2_b = (const float*)d_in[14];
    float* out = (float*)d_out;

    float *xnhwc, *proj, *x1, *y2;
    __half *xwin, *qkv, *attno, *yln, *h1, *qkvT, *projT, *fc1T, *fc2T;
    cudaGetSymbolAddress((void**)&xnhwc, g_xnhwc);
    cudaGetSymbolAddress((void**)&xwin, g_xwin);
    cudaGetSymbolAddress((void**)&qkv, g_qkv);
    cudaGetSymbolAddress((void**)&attno, g_attno);
    cudaGetSymbolAddress((void**)&proj, g_proj);
    cudaGetSymbolAddress((void**)&x1, g_x1);
    cudaGetSymbolAddress((void**)&yln, g_yln);
    cudaGetSymbolAddress((void**)&h1, g_h1);
    cudaGetSymbolAddress((void**)&y2, g_y2);
    cudaGetSymbolAddress((void**)&qkvT, g_qkvT);
    cudaGetSymbolAddress((void**)&projT, g_projT);
    cudaGetSymbolAddress((void**)&fc1T, g_fc1T);
    cudaGetSymbolAddress((void**)&fc2T, g_fc2T);

    cudaFuncSetAttribute(k_attn, cudaFuncAttributeMaxDynamicSharedMemorySize, (int)ATTN_SMEM);
    cudaFuncSetAttribute(k_mma_gemm, cudaFuncAttributeMaxDynamicSharedMemorySize, GEMM_SMEM);

    dim3 tb(32, 8);
    // 1) qkv weight transpose
    k_transpose_w<<<dim3(3 * DIMC / 32, DIMC / 32), tb>>>(qkv_w, qkvT, DIMC, 3 * DIMC);
    // 2) NCHW -> NHWC
    k_transpose_in<<<dim3(128, 24, BATCH), tb>>>(hidden, xnhwc);
    // 3) LN1 + window partition (fp16)
    k_ln1_window<<<NROWS_WIN, 256>>>(xnhwc, ln1_w, ln1_b, xwin);
    // 4) proj weight transpose
    k_transpose_w<<<dim3(DIMC / 32, DIMC / 32), tb>>>(proj_w, projT, DIMC, DIMC);
    // 5) fc1 weight transpose
    k_transpose_w<<<dim3(MLPD / 32, DIMC / 32), tb>>>(fc1_w, fc1T, DIMC, MLPD);
    // 6) QKV GEMM: (19600,768) x (768,2304) -> fp16
    k_mma_gemm<<<dim3(3 * DIMC / 128, (NROWS_WIN + 127) / 128), 256, GEMM_SMEM>>>(
        xwin, qkvT, qkv_b, qkv, NROWS_WIN, 3 * DIMC, DIMC, 0, 1);
    // 7) fc2 weight transpose
    k_transpose_w<<<dim3(DIMC / 32, MLPD / 32), tb>>>(fc2_w, fc2T, MLPD, DIMC);
    // 8) attention (fp16 in, fp16 out)
    k_attn<<<NWIN * HEADS, ATTN_THREADS, ATTN_SMEM>>>(qkv, relh, relw, attno);
    // 9) proj: (19600,768) x (768,768) -> fp32
    k_mma_gemm<<<dim3(DIMC / 128, (NROWS_WIN + 127) / 128), 256, GEMM_SMEM>>>(
        attno, projT, proj_b, proj, NROWS_WIN, DIMC, DIMC, 0, 0);
    // 10) unpartition + residual + LN2 (x1 fp32, yln fp16)
    k_scatter_ln2<<<NROWS_IMG, 256>>>(xnhwc, proj, ln2_w, ln2_b, x1, yln);
    // 11) FC1 + GELU: (16384,768) x (768,3072) -> fp16
    k_mma_gemm<<<dim3(MLPD / 128, NROWS_IMG / 128), 256, GEMM_SMEM>>>(
        yln, fc1T, fc1_b, h1, NROWS_IMG, MLPD, DIMC, 1, 1);
    // 12) FC2: (16384,3072) x (3072,768) -> fp32
    k_mma_gemm<<<dim3(DIMC / 128, NROWS_IMG / 128), 256, GEMM_SMEM>>>(
        h1, fc2T, fc2_b, y2, NROWS_IMG, DIMC, MLPD, 0, 0);
    // 13) residual + NHWC -> NCHW
    k_final<<<dim3(128, 24, BATCH), tb>>>(x1, y2, out);
}

// round 13
// speedup vs baseline: 1.1244x; 1.1244x over previous
#include <cuda_runtime.h>
#include <cuda_fp16.h>
#include <math.h>
#include <stdint.h>

// ---------------- problem constants ----------------
#define DIMC    768
#define HEADS   12
#define HDIM    64
#define WS      14
#define NTOK    196
#define MLPD    3072
#define BATCH   4
#define IMGH    64
#define IMGW    64
#define NWIN    100
#define NROWS_WIN (NWIN*NTOK)        // 19600
#define NROWS_IMG (BATCH*IMGH*IMGW)  // 16384
#define NBH     (NWIN*HEADS)         // 1200
#define SLD     224                  // padded S row length (>=196, mult of 32)
#define SCALE_F 0.125f
#define EPS_F   1e-6f

// ---------------- scratch ----------------
__device__ float   g_xnhwc[BATCH*IMGH*IMGW*DIMC];
__device__ __half  g_xwin [NROWS_WIN*DIMC];
__device__ __half  g_qkv  [NROWS_WIN*3*DIMC];
__device__ __half  g_S    [(long)NBH*NTOK*SLD];        // scores -> probs (in place)
__device__ __half  g_Vt   [(long)NBH*HDIM*SLD];        // V transposed, zero-padded
__device__ __half  g_attno[NROWS_WIN*DIMC];
__device__ float   g_proj [NROWS_WIN*DIMC];
__device__ float   g_x1   [NROWS_IMG*DIMC];
__device__ __half  g_yln  [NROWS_IMG*DIMC];
__device__ __half  g_h1   [NROWS_IMG*MLPD];
__device__ float   g_y2   [NROWS_IMG*DIMC];
__device__ __half  g_qkvT [3*DIMC*DIMC];
__device__ __half  g_projT[DIMC*DIMC];
__device__ __half  g_fc1T [MLPD*DIMC];
__device__ __half  g_fc2T [DIMC*MLPD];

// ================= helpers =================
__device__ __forceinline__ uint32_t smem_u32(const void* p) {
    uint32_t a;
    asm("{ .reg .u64 t; cvta.to.shared.u64 t, %1; cvt.u32.u64 %0, t; }" : "=r"(a) : "l"(p));
    return a;
}
__device__ __forceinline__ void cp_async16(uint32_t dst, const void* src) {
    asm volatile("cp.async.cg.shared.global [%0], [%1], 16;" :: "r"(dst), "l"(src));
}
#define CP_COMMIT() asm volatile("cp.async.commit_group;" ::: "memory")
#define CP_WAIT(n)  asm volatile("cp.async.wait_group %0;" :: "n"(n) : "memory")

__device__ __forceinline__ void mma_f16(float* c, const uint32_t* a, const uint32_t* b) {
    asm volatile(
        "mma.sync.aligned.m16n8k16.row.col.f32.f16.f16.f32 "
        "{%0,%1,%2,%3}, {%4,%5,%6,%7}, {%8,%9}, {%0,%1,%2,%3};"
        : "+f"(c[0]), "+f"(c[1]), "+f"(c[2]), "+f"(c[3])
        : "r"(a[0]), "r"(a[1]), "r"(a[2]), "r"(a[3]), "r"(b[0]), "r"(b[1]));
}
__device__ __forceinline__ void ldmx4(uint32_t& r0, uint32_t& r1, uint32_t& r2, uint32_t& r3,
                                      uint32_t addr) {
    asm volatile("ldmatrix.sync.aligned.m8n8.x4.shared.b16 {%0,%1,%2,%3}, [%4];"
        : "=r"(r0), "=r"(r1), "=r"(r2), "=r"(r3) : "r"(addr));
}

// ================= fp16 mma.sync GEMM (R10-proven) =================
#define BM 128
#define BN 128
#define BKE 32
#define LDW 20
#define TBUF (BM*LDW)
#define GEMM_SMEM ((4*TBUF + 128) * 4)

__global__ void __launch_bounds__(256, 2)
k_mma_gemm(const __half* __restrict__ A, const __half* __restrict__ Bt,
           const float* __restrict__ bias, void* __restrict__ Cout,
           int M, int N, int K, int act, int outf16) {
    extern __shared__ float sm[];
    uint32_t* As = (uint32_t*)sm;
    uint32_t* Bs = As + 2*TBUF;
    float* sbias = sm + 4*TBUF;

    int tid = threadIdx.x, lane = tid & 31, wid = tid >> 5;
    int wm = wid >> 1, wn = wid & 1;
    int m0 = blockIdx.y * BM, n0 = blockIdx.x * BN;

    if (tid < 128) sbias[tid] = bias[n0 + tid];

    auto load_tile = [&](int kc, int bsel) {
        int k0 = kc * BKE;
        uint32_t* abuf = As + bsel * TBUF;
        uint32_t* bbuf = Bs + bsel * TBUF;
        #pragma unroll
        for (int it = 0; it < 2; it++) {
            int idx = tid + it * 256;
            int r = idx >> 2, c = idx & 3;
            int ar = m0 + r;
            const __half* asrc = A + (long)(ar < M ? ar : M - 1) * K + k0 + c * 8;
            cp_async16(smem_u32(abuf + r * LDW + c * 4), asrc);
            const __half* bsrc = Bt + (long)(n0 + r) * K + k0 + c * 8;
            cp_async16(smem_u32(bbuf + r * LDW + c * 4), bsrc);
        }
        CP_COMMIT();
    };

    int m8 = lane >> 3, r8 = lane & 7;
    uint32_t aoff[2], boff[4];
    #pragma unroll
    for (int mt = 0; mt < 2; mt++)
        aoff[mt] = (uint32_t)((wm * 32 + mt * 16 + (m8 & 1) * 8 + r8) * LDW + (m8 >> 1) * 4);
    #pragma unroll
    for (int p = 0; p < 4; p++)
        boff[p] = (uint32_t)((wn * 64 + p * 16 + (m8 >> 1) * 8 + r8) * LDW + (m8 & 1) * 4);
    uint32_t a_base = smem_u32(As);
    uint32_t b_base = smem_u32(Bs);

    float acc[2][8][4];
    #pragma unroll
    for (int mt = 0; mt < 2; mt++)
        #pragma unroll
        for (int nt = 0; nt < 8; nt++)
            #pragma unroll
            for (int j = 0; j < 4; j++) acc[mt][nt][j] = 0.f;

    const int NKC = K / BKE;
    load_tile(0, 0);
    for (int i = 0; i < NKC; i++) {
        int cur = i & 1;
        if (i + 1 < NKC) { load_tile(i + 1, cur ^ 1); CP_WAIT(1); }
        else             { CP_WAIT(0); }
        __syncthreads();
        uint32_t ab = a_base + cur * (TBUF * 4);
        uint32_t bb = b_base + cur * (TBUF * 4);
        #pragma unroll
        for (int ks = 0; ks < 2; ks++) {
            uint32_t af[2][4], bf[8][2];
            #pragma unroll
            for (int mt = 0; mt < 2; mt++)
                ldmx4(af[mt][0], af[mt][1], af[mt][2], af[mt][3],
                      ab + (aoff[mt] + ks * 8) * 4);
            #pragma unroll
            for (int p = 0; p < 4; p++)
                ldmx4(bf[2*p][0], bf[2*p][1], bf[2*p+1][0], bf[2*p+1][1],
                      bb + (boff[p] + ks * 8) * 4);
            #pragma unroll
            for (int mt = 0; mt < 2; mt++)
                #pragma unroll
                for (int nt = 0; nt < 8; nt++)
                    mma_f16(acc[mt][nt], af[mt], bf[nt]);
        }
        __syncthreads();
    }

    int rb = m0 + wm * 32 + (lane >> 2);
    int cb = wn * 64 + 2 * (lane & 3);
    #pragma unroll
    for (int mt = 0; mt < 2; mt++) {
        int r0 = rb + mt * 16, r1 = r0 + 8;
        #pragma unroll
        for (int nt = 0; nt < 8; nt++) {
            int cc = cb + nt * 8;
            float v0 = acc[mt][nt][0] + sbias[cc];
            float v1 = acc[mt][nt][1] + sbias[cc + 1];
            float v2 = acc[mt][nt][2] + sbias[cc];
            float v3 = acc[mt][nt][3] + sbias[cc + 1];
            if (act == 1) {
                v0 = 0.5f * v0 * (1.0f + erff(v0 * 0.70710678118654752f));
                v1 = 0.5f * v1 * (1.0f + erff(v1 * 0.70710678118654752f));
                v2 = 0.5f * v2 * (1.0f + erff(v2 * 0.70710678118654752f));
                v3 = 0.5f * v3 * (1.0f + erff(v3 * 0.70710678118654752f));
            }
            if (outf16) {
                __half* C = (__half*)Cout;
                if (r0 < M) *(__half2*)(C + (long)r0 * N + n0 + cc) = __floats2half2_rn(v0, v1);
                if (r1 < M) *(__half2*)(C + (long)r1 * N + n0 + cc) = __floats2half2_rn(v2, v3);
            } else {
                float* C = (float*)Cout;
                if (r0 < M) *(float2*)(C + (long)r0 * N + n0 + cc) = make_float2(v0, v1);
                if (r1 < M) *(float2*)(C + (long)r1 * N + n0 + cc) = make_float2(v2, v3);
            }
        }
    }
}

// ================= batched QK^T GEMM: S[196,224] = Q @ K^T per (win,head) =====
__global__ void __launch_bounds__(256, 2)
k_qk_gemm(const __half* __restrict__ qkv, __half* __restrict__ S) {
    extern __shared__ float sm[];
    uint32_t* As = (uint32_t*)sm;
    uint32_t* Bs = As + 2*TBUF;

    int tid = threadIdx.x, lane = tid & 31, wid = tid >> 5;
    int wm = wid >> 1, wn = wid & 1;
    int m0 = blockIdx.y * BM, n0 = blockIdx.x * BN;
    int bz = blockIdx.z;
    int win = bz / HEADS, head = bz % HEADS;
    const __half* Qb = qkv + (long)win * NTOK * (3 * DIMC) + head * HDIM;
    const __half* Kb = Qb + DIMC;
    __half* Sb = S + (long)bz * NTOK * SLD;

    auto load_tile = [&](int kc, int bsel) {
        int k0 = kc * BKE;
        uint32_t* abuf = As + bsel * TBUF;
        uint32_t* bbuf = Bs + bsel * TBUF;
        #pragma unroll
        for (int it = 0; it < 2; it++) {
            int idx = tid + it * 256;
            int r = idx >> 2, c = idx & 3;
            int ar = m0 + r; ar = ar < NTOK ? ar : NTOK - 1;
            cp_async16(smem_u32(abuf + r * LDW + c * 4), Qb + (long)ar * (3 * DIMC) + k0 + c * 8);
            int br = n0 + r; br = br < NTOK ? br : NTOK - 1;
            cp_async16(smem_u32(bbuf + r * LDW + c * 4), Kb + (long)br * (3 * DIMC) + k0 + c * 8);
        }
        CP_COMMIT();
    };

    int m8 = lane >> 3, r8 = lane & 7;
    uint32_t aoff[2], boff[4];
    #pragma unroll
    for (int mt = 0; mt < 2; mt++)
        aoff[mt] = (uint32_t)((wm * 32 + mt * 16 + (m8 & 1) * 8 + r8) * LDW + (m8 >> 1) * 4);
    #pragma unroll
    for (int p = 0; p < 4; p++)
        boff[p] = (uint32_t)((wn * 64 + p * 16 + (m8 >> 1) * 8 + r8) * LDW + (m8 & 1) * 4);
    uint32_t a_base = smem_u32(As);
    uint32_t b_base = smem_u32(Bs);

    float acc[2][8][4];
    #pragma unroll
    for (int mt = 0; mt < 2; mt++)
        #pragma unroll
        for (int nt = 0; nt < 8; nt++)
            #pragma unroll
            for (int j = 0; j < 4; j++) acc[mt][nt][j] = 0.f;

    load_tile(0, 0);
    #pragma unroll
    for (int i = 0; i < 2; i++) {               // K = 64 -> 2 chunks
        int cur = i & 1;
        if (i + 1 < 2) { load_tile(1, 1); CP_WAIT(1); }
        else           { CP_WAIT(0); }
        __syncthreads();
        uint32_t ab = a_base + cur * (TBUF * 4);
        uint32_t bb = b_base + cur * (TBUF * 4);
        #pragma unroll
        for (int ks = 0; ks < 2; ks++) {
            uint32_t af[2][4], bf[8][2];
            #pragma unroll
            for (int mt = 0; mt < 2; mt++)
                ldmx4(af[mt][0], af[mt][1], af[mt][2], af[mt][3],
                      ab + (aoff[mt] + ks * 8) * 4);
            #pragma unroll
            for (int p = 0; p < 4; p++)
                ldmx4(bf[2*p][0], bf[2*p][1], bf[2*p+1][0], bf[2*p+1][1],
                      bb + (boff[p] + ks * 8) * 4);
            #pragma unroll
            for (int mt = 0; mt < 2; mt++)
                #pragma unroll
                for (int nt = 0; nt < 8; nt++)
                    mma_f16(acc[mt][nt], af[mt], bf[nt]);
        }
        __syncthreads();
    }

    int rb = m0 + wm * 32 + (lane >> 2);
    int cb = wn * 64 + 2 * (lane & 3);
    #pragma unroll
    for (int mt = 0; mt < 2; mt++) {
        int r0 = rb + mt * 16, r1 = r0 + 8;
        #pragma unroll
        for (int nt = 0; nt < 8; nt++) {
            int cc = n0 + cb + nt * 8;
            if (cc + 1 < SLD) {
                if (r0 < NTOK) *(__half2*)(Sb + (long)r0 * SLD + cc) =
                    __floats2half2_rn(acc[mt][nt][0], acc[mt][nt][1]);
                if (r1 < NTOK) *(__half2*)(Sb + (long)r1 * SLD + cc) =
                    __floats2half2_rn(acc[mt][nt][2], acc[mt][nt][3]);
            }
        }
    }
}

// ================= V transpose prep: Vt[64,224] per (win,head), zero pad ======
#define LDV 66
__global__ void __launch_bounds__(256)
k_vt(const __half* __restrict__ qkv, __half* __restrict__ Vt) {
    __shared__ __half smv[NTOK * LDV];
    int bz = blockIdx.x;
    int win = bz / HEADS, head = bz % HEADS;
    const __half* Vb = qkv + (long)win * NTOK * (3 * DIMC) + 2 * DIMC + head * HDIM;
    int tid = threadIdx.x;
    for (int i = tid; i < NTOK * HDIM; i += 256) {
        int t = i >> 6, d = i & 63;
        smv[t * LDV + d] = Vb[(long)t * (3 * DIMC) + d];
    }
    __syncthreads();
    __half* out = Vt + (long)bz * HDIM * SLD;
    for (int o = tid; o < HDIM * SLD; o += 256) {
        int n = o / SLD, k = o - n * SLD;
        out[o] = (k < NTOK) ? smv[k * LDV + n] : __float2half_rn(0.f);
    }
}

// ================= softmax + rel-pos bias, in place S -> P ===================
#define RELSTRIDE 65
__global__ void __launch_bounds__(392, 2)
k_softmax(__half* __restrict__ S, const __half* __restrict__ qkv,
          const float* __restrict__ rel_pos_h, const float* __restrict__ rel_pos_w) {
    __shared__ float RH[27 * RELSTRIDE];
    __shared__ float RW[27 * RELSTRIDE];
    int bz = blockIdx.x;
    int win = bz / HEADS, head = bz % HEADS;
    int tid = threadIdx.x;
    for (int i = tid; i < 27 * HDIM; i += 392) {
        int r = i >> 6, d = i & 63;
        RH[r * RELSTRIDE + d] = rel_pos_h[i];
        RW[r * RELSTRIDE + d] = rel_pos_w[i];
    }
    __syncthreads();

    int q = tid >> 1, half = tid & 1;
    int qh = q / WS, qw = q % WS;
    unsigned pmask = ((tid & ~31) == 384) ? 0x000000ffu : 0xffffffffu;

    float qv[32];
    {
        const __half* qp = qkv + (long)win * NTOK * (3 * DIMC) + (long)q * (3 * DIMC)
                           + head * HDIM + half * 32;
        #pragma unroll
        for (int d = 0; d < 32; d += 2) {
            float2 f = __half22float2(*(const __half2*)(qp + d));
            qv[d] = f.x; qv[d + 1] = f.y;
        }
    }

    float rh[WS], rw[WS];
    #pragma unroll
    for (int kh = 0; kh < WS; kh++) {
        const float* ph = &RH[(qh - kh + WS - 1) * RELSTRIDE + half * 32];
        const float* pw = &RW[(qw - kh + WS - 1) * RELSTRIDE + half * 32];
        float sh = 0.f, sw = 0.f;
        #pragma unroll
        for (int d = 0; d < 32; d++) { sh = fmaf(qv[d], ph[d], sh); sw = fmaf(qv[d], pw[d], sw); }
        sh += __shfl_xor_sync(pmask, sh, 1);
        sw += __shfl_xor_sync(pmask, sw, 1);
        rh[kh] = sh; rw[kh] = sw;   // both lanes hold full sums
    }

    __half* Srow = S + (long)bz * NTOK * SLD + (long)q * SLD;
    // pass 1: own-half max & sum (cols half*112 .. half*112+111)
    float m = -1e30f, l = 0.f;
    {
        int kh = 8 * half, kw = 0;
        for (int j = 0; j < 112; j++) {
            int col = half * 112 + j;
            if (col < NTOK) {
                float s = __half2float(Srow[col]) * SCALE_F + rh[kh] + rw[kw];
                if (s > m) { l = l * __expf(m - s) + 1.f; m = s; }
                else       { l += __expf(s - m); }
            }
            if (++kw == WS) { kw = 0; kh++; }
        }
    }
    // combine the two halves
    float mo = __shfl_xor_sync(pmask, m, 1);
    float lo = __shfl_xor_sync(pmask, l, 1);
    float mj = fmaxf(m, mo);
    float lj = l * __expf(m - mj) + lo * __expf(mo - mj);
    float inv = 1.f / lj;
    // pass 2: write normalized probs (zero the pad tail)
    {
        int kh = 8 * half, kw = 0;
        for (int j = 0; j < 112; j++) {
            int col = half * 112 + j;
            if (col < NTOK) {
                float s = __half2float(Srow[col]) * SCALE_F + rh[kh] + rw[kw];
                Srow[col] = __float2half_rn(__expf(s - mj) * inv);
            } else {
                Srow[col] = __float2half_rn(0.f);
            }
            if (++kw == WS) { kw = 0; kh++; }
        }
    }
}

// ================= batched PV GEMM: attno[196,64] = P[196,224] @ Vt[64,224]^T ==
#define TBUFA (BM*LDW)
#define TBUFB (64*LDW)
#define PV_SMEM ((2*TBUFA + 2*TBUFB) * 4)

__global__ void __launch_bounds__(256, 2)
k_pv_gemm(const __half* __restrict__ S, const __half* __restrict__ Vt,
          __half* __restrict__ attno) {
    extern __shared__ float sm[];
    uint32_t* As = (uint32_t*)sm;
    uint32_t* Bs = As + 2*TBUFA;

    int tid = threadIdx.x, lane = tid & 31, wid = tid >> 5;
    int m0 = blockIdx.y * BM;
    int bz = blockIdx.z;
    int win = bz / HEADS, head = bz % HEADS;
    const __half* Pb = S + (long)bz * NTOK * SLD;
    const __half* Vb = Vt + (long)bz * HDIM * SLD;
    __half* Cb = attno + (long)win * NTOK * DIMC + head * HDIM;

    auto load_tile = [&](int kc, int bsel) {
        int k0 = kc * BKE;
        uint32_t* abuf = As + bsel * TBUFA;
        uint32_t* bbuf = Bs + bsel * TBUFB;
        #pragma unroll
        for (int it = 0; it < 2; it++) {
            int idx = tid + it * 256;
            int r = idx >> 2, c = idx & 3;
            int ar = m0 + r; ar = ar < NTOK ? ar : NTOK - 1;
            cp_async16(smem_u32(abuf + r * LDW + c * 4), Pb + (long)ar * SLD + k0 + c * 8);
        }
        {   // B: 64 rows x 4 chunks = 256
            int r = tid >> 2, c = tid & 3;
            cp_async16(smem_u32(bbuf + r * LDW + c * 4), Vb + (long)r * SLD + k0 + c * 8);
        }
        CP_COMMIT();
    };

    int m8 = lane >> 3, r8 = lane & 7;
    uint32_t aoff = (uint32_t)((wid * 16 + (m8 & 1) * 8 + r8) * LDW + (m8 >> 1) * 4);
    uint32_t boff[4];
    #pragma unroll
    for (int p = 0; p < 4; p++)
        boff[p] = (uint32_t)((p * 16 + (m8 >> 1) * 8 + r8) * LDW + (m8 & 1) * 4);
    uint32_t a_base = smem_u32(As);
    uint32_t b_base = smem_u32(Bs);

    float acc[8][4];
    #pragma unroll
    for (int nt = 0; nt < 8; nt++)
        #pragma unroll
        for (int j = 0; j < 4; j++) acc[nt][j] = 0.f;

    const int NKC = SLD / BKE;   // 7
    load_tile(0, 0);
    for (int i = 0; i < NKC; i++) {
        int cur = i & 1;
        if (i + 1 < NKC) { load_tile(i + 1, cur ^ 1); CP_WAIT(1); }
        else             { CP_WAIT(0); }
        __syncthreads();
        uint32_t ab = a_base + cur * (TBUFA * 4);
        uint32_t bb = b_base + cur * (TBUFB * 4);
        #pragma unroll
        for (int ks = 0; ks < 2; ks++) {
            uint32_t af[4], bf[8][2];
            ldmx4(af[0], af[1], af[2], af[3], ab + (aoff + ks * 8) * 4);
            #pragma unroll
            for (int p = 0; p < 4; p++)
                ldmx4(bf[2*p][0], bf[2*p][1], bf[2*p+1][0], bf[2*p+1][1],
                      bb + (boff[p] + ks * 8) * 4);
            #pragma unroll
            for (int nt = 0; nt < 8; nt++)
                mma_f16(acc[nt], af, bf[nt]);
        }
        __syncthreads();
    }

    int r0 = m0 + wid * 16 + (lane >> 2), r1 = r0 + 8;
    int cb = 2 * (lane & 3);
    #pragma unroll
    for (int nt = 0; nt < 8; nt++) {
        int cc = cb + nt * 8;
        if (r0 < NTOK) *(__half2*)(Cb + (long)r0 * DIMC + cc) =
            __floats2half2_rn(acc[nt][0], acc[nt][1]);
        if (r1 < NTOK) *(__half2*)(Cb + (long)r1 * DIMC + cc) =
            __floats2half2_rn(acc[nt][2], acc[nt][3]);
    }
}

// ---------------- NCHW -> NHWC transpose ----------------
__global__ void k_transpose_in(const float* __restrict__ in, float* __restrict__ out) {
    __shared__ float tile[32][33];
    int b = blockIdx.z, c0 = blockIdx.y * 32, s0 = blockIdx.x * 32;
    const float* ib = in + (long)b * DIMC * 4096;
    float* ob = out + (long)b * 4096 * DIMC;
    int x = threadIdx.x, y = threadIdx.y;
    #pragma unroll
    for (int i = 0; i < 32; i += 8)
        tile[y + i][x] = ib[(long)(c0 + y + i) * 4096 + s0 + x];
    __syncthreads();
    #pragma unroll
    for (int i = 0; i < 32; i += 8)
        ob[(long)(s0 + y + i) * DIMC + c0 + x] = tile[x][y + i];
}

// ---------------- weight transpose to fp16 ----------------
__global__ void k_transpose_w(const float* __restrict__ in, __half* __restrict__ out,
                              int R, int C) {
    __shared__ float tile[32][33];
    int r0 = blockIdx.y * 32, c0 = blockIdx.x * 32;
    int x = threadIdx.x, y = threadIdx.y;
    #pragma unroll
    for (int i = 0; i < 32; i += 8)
        tile[y + i][x] = in[(long)(r0 + y + i) * C + c0 + x];
    __syncthreads();
    #pragma unroll
    for (int i = 0; i < 32; i += 8)
        out[(long)(c0 + y + i) * R + r0 + x] = __float2half_rn(tile[x][y + i]);
}

// ---------------- block reduction ----------------
__device__ __forceinline__ float block_sum_256(float v, float* red) {
    int tid = threadIdx.x;
    #pragma unroll
    for (int o = 16; o > 0; o >>= 1) v += __shfl_xor_sync(0xffffffffu, v, o);
    if ((tid & 31) == 0) red[tid >> 5] = v;
    __syncthreads();
    float r = 0.f;
    if (tid < 8) {
        r = red[tid];
        #pragma unroll
        for (int o = 4; o > 0; o >>= 1) r += __shfl_xor_sync(0xffu, r, o);
        if (tid == 0) red[0] = r;
    }
    __syncthreads();
    r = red[0];
    __syncthreads();
    return r;
}

// ---------------- LN1 + window partition (fp16 output) ----------------
__global__ void k_ln1_window(const float* __restrict__ xnhwc,
                             const float* __restrict__ w, const float* __restrict__ bs,
                             __half* __restrict__ xwin) {
    __shared__ float red[8];
    int idx = blockIdx.x;
    int win = idx / NTOK, t = idx % NTOK;
    int b = win / 25, wrem = win % 25;
    int gr = (wrem / 5) * WS + t / WS;
    int gc = (wrem % 5) * WS + t % WS;
    __half* orow = xwin + (long)idx * DIMC;
    int tid = threadIdx.x;
    if (gr >= IMGH || gc >= IMGW) {
        for (int c = tid; c < DIMC; c += 256) orow[c] = __float2half_rn(0.f);
        return;
    }
    const float* irow = xnhwc + ((long)b * 4096 + gr * IMGW + gc) * DIMC;
    float v[3], s = 0.f, s2 = 0.f;
    #pragma unroll
    for (int i = 0; i < 3; i++) { float x = irow[tid + i * 256]; v[i] = x; s += x; s2 += x * x; }
    float tot = block_sum_256(s, red);
    float tot2 = block_sum_256(s2, red);
    float mu = tot * (1.f / DIMC);
    float rstd = rsqrtf(tot2 * (1.f / DIMC) - mu * mu + EPS_F);
    #pragma unroll
    for (int i = 0; i < 3; i++) {
        int c = tid + i * 256;
        orow[c] = __float2half_rn((v[i] - mu) * rstd * w[c] + bs[c]);
    }
}

// ---------------- fused: window unpartition + residual + LN2 ----------------
__global__ void k_scatter_ln2(const float* __restrict__ xnhwc, const float* __restrict__ proj,
                              const float* __restrict__ w, const float* __restrict__ bs,
                              float* __restrict__ x1, __half* __restrict__ yln) {
    __shared__ float red[8];
    int row = blockIdx.x;
    int b = row >> 12, sp = row & 4095;
    int r = sp >> 6, cw = sp & 63;
    int win = b * 25 + (r / WS) * 5 + (cw / WS);
    int t = (r % WS) * WS + (cw % WS);
    const float* prow = proj + ((long)win * NTOK + t) * DIMC;
    const float* xrow = xnhwc + (long)row * DIMC;
    float* orow = x1 + (long)row * DIMC;
    __half* lrow = yln + (long)row * DIMC;
    int tid = threadIdx.x;
    float v[3], s = 0.f, s2 = 0.f;
    #pragma unroll
    for (int i = 0; i < 3; i++) {
        int c = tid + i * 256;
        float x = xrow[c] + prow[c];
        orow[c] = x;
        v[i] = x; s += x; s2 += x * x;
    }
    float tot = block_sum_256(s, red);
    float tot2 = block_sum_256(s2, red);
    float mu = tot * (1.f / DIMC);
    float rstd = rsqrtf(tot2 * (1.f / DIMC) - mu * mu + EPS_F);
    #pragma unroll
    for (int i = 0; i < 3; i++) {
        int c = tid + i * 256;
        lrow[c] = __float2half_rn((v[i] - mu) * rstd * w[c] + bs[c]);
    }
}

// ---------------- final: x1 + mlp_out, NHWC -> NCHW ----------------
__global__ void k_final(const float* __restrict__ x1, const float* __restrict__ y2,
                        float* __restrict__ out) {
    __shared__ float tile[32][33];
    int b = blockIdx.z, s0 = blockIdx.x * 32, c0 = blockIdx.y * 32;
    int x = threadIdx.x, y = threadIdx.y;
    #pragma unroll
    for (int i = 0; i < 32; i += 8) {
        long row = (long)b * 4096 + s0 + y + i;
        tile[y + i][x] = x1[row * DIMC + c0 + x] + y2[row * DIMC + c0 + x];
    }
    __syncthreads();
    #pragma unroll
    for (int i = 0; i < 32; i += 8)
        out[((long)b * DIMC + c0 + y + i) * 4096 + s0 + x] = tile[x][y + i];
}

// ---------------- launcher ----------------
extern "C" void kernel_launch(void* const* d_in, const int* in_sizes, int n_in,
                              void* d_out, int out_size) {
    const float* hidden = (const float*)d_in[0];
    const float* ln1_w = (const float*)d_in[1];
    const float* ln1_b = (const float*)d_in[2];
    const float* qkv_w = (const float*)d_in[3];
    const float* qkv_b = (const float*)d_in[4];
    const float* proj_w = (const float*)d_in[5];
    const float* proj_b = (const float*)d_in[6];
    const float* relh = (const float*)d_in[7];
    const float* relw = (const float*)d_in[8];
    const float* ln2_w = (const float*)d_in[9];
    const float* ln2_b = (const float*)d_in[10];
    const float* fc1_w = (const float*)d_in[11];
    const float* fc1_b = (const float*)d_in[12];
    const float* fc2_w = (const float*)d_in[13];
    const float* fc2_b = (const float*)d_in[14];
    float* out = (float*)d_out;

    float *xnhwc, *proj, *x1, *y2;
    __half *xwin, *qkv, *S, *Vt, *attno, *yln, *h1, *qkvT, *projT, *fc1T, *fc2T;
    cudaGetSymbolAddress((void**)&xnhwc, g_xnhwc);
    cudaGetSymbolAddress((void**)&xwin, g_xwin);
    cudaGetSymbolAddress((void**)&qkv, g_qkv);
    cudaGetSymbolAddress((void**)&S, g_S);
    cudaGetSymbolAddress((void**)&Vt, g_Vt);
    cudaGetSymbolAddress((void**)&attno, g_attno);
    cudaGetSymbolAddress((void**)&proj, g_proj);
    cudaGetSymbolAddress((void**)&x1, g_x1);
    cudaGetSymbolAddress((void**)&yln, g_yln);
    cudaGetSymbolAddress((void**)&h1, g_h1);
    cudaGetSymbolAddress((void**)&y2, g_y2);
    cudaGetSymbolAddress((void**)&qkvT, g_qkvT);
    cudaGetSymbolAddress((void**)&projT, g_projT);
    cudaGetSymbolAddress((void**)&fc1T, g_fc1T);
    cudaGetSymbolAddress((void**)&fc2T, g_fc2T);

    cudaFuncSetAttribute(k_mma_gemm, cudaFuncAttributeMaxDynamicSharedMemorySize, GEMM_SMEM);
    cudaFuncSetAttribute(k_qk_gemm, cudaFuncAttributeMaxDynamicSharedMemorySize, GEMM_SMEM);
    cudaFuncSetAttribute(k_pv_gemm, cudaFuncAttributeMaxDynamicSharedMemorySize, PV_SMEM);

    dim3 tb(32, 8);
    // weight transposes
    k_transpose_w<<<dim3(3 * DIMC / 32, DIMC / 32), tb>>>(qkv_w, qkvT, DIMC, 3 * DIMC);
    k_transpose_w<<<dim3(DIMC / 32, DIMC / 32), tb>>>(proj_w, projT, DIMC, DIMC);
    k_transpose_w<<<dim3(MLPD / 32, DIMC / 32), tb>>>(fc1_w, fc1T, DIMC, MLPD);
    k_transpose_w<<<dim3(DIMC / 32, MLPD / 32), tb>>>(fc2_w, fc2T, MLPD, DIMC);

    // NCHW -> NHWC, LN1+window
    k_transpose_in<<<dim3(128, 24, BATCH), tb>>>(hidden, xnhwc);
    k_ln1_window<<<NROWS_WIN, 256>>>(xnhwc, ln1_w, ln1_b, xwin);
    // QKV GEMM -> fp16
    k_mma_gemm<<<dim3(3 * DIMC / 128, (NROWS_WIN + 127) / 128), 256, GEMM_SMEM>>>(
        xwin, qkvT, qkv_b, qkv, NROWS_WIN, 3 * DIMC, DIMC, 0, 1);
    // attention: V transpose, QK^T, softmax, PV
    k_vt<<<NBH, 256>>>(qkv, Vt);
    k_qk_gemm<<<dim3(2, 2, NBH), 256, GEMM_SMEM>>>(qkv, S);
    k_softmax<<<NBH, 392>>>(S, qkv, relh, relw);
    k_pv_gemm<<<dim3(1, 2, NBH), 256, PV_SMEM>>>(S, Vt, attno);
    // proj -> fp32
    k_mma_gemm<<<dim3(DIMC / 128, (NROWS_WIN + 127) / 128), 256, GEMM_SMEM>>>(
        attno, projT, proj_b, proj, NROWS_WIN, DIMC, DIMC, 0, 0);
    // residual + LN2
    k_scatter_ln2<<<NROWS_IMG, 256>>>(xnhwc, proj, ln2_w, ln2_b, x1, yln);
    // FC1 + GELU -> fp16
    k_mma_gemm<<<dim3(MLPD / 128, NROWS_IMG / 128), 256, GEMM_SMEM>>>(
        yln, fc1T, fc1_b, h1, NROWS_IMG, MLPD, DIMC, 1, 1);
    // FC2 -> fp32
    k_mma_gemm<<<dim3(DIMC / 128, NROWS_IMG / 128), 256, GEMM_SMEM>>>(
        h1, fc2T, fc2_b, y2, NROWS_IMG, DIMC, MLPD, 0, 0);
    // residual + NHWC -> NCHW
    k_final<<<dim3(128, 24, BATCH), tb>>>(x1, y2, out);
}

// round 14
// speedup vs baseline: 1.1789x; 1.0485x over previous
#include <cuda_runtime.h>
#include <cuda_fp16.h>
#include <math.h>
#include <stdint.h>

// ---------------- problem constants ----------------
#define DIMC    768
#define HEADS   12
#define HDIM    64
#define WS      14
#define NTOK    196
#define MLPD    3072
#define BATCH   4
#define IMGH    64
#define IMGW    64
#define NWIN    100
#define NROWS_WIN (NWIN*NTOK)        // 19600
#define NROWS_IMG (BATCH*IMGH*IMGW)  // 16384
#define NBH     (NWIN*HEADS)         // 1200
#define SLD     224                  // padded S row length
#define SCALE_F 0.125f
#define EPS_F   1e-6f

// ---------------- scratch ----------------
__device__ float   g_xnhwc[BATCH*IMGH*IMGW*DIMC];
__device__ __half  g_xwin [NROWS_WIN*DIMC];
__device__ __half  g_qkv  [NROWS_WIN*3*DIMC];
__device__ __half  g_S    [(long)NBH*NTOK*SLD];
__device__ __half  g_Vt   [(long)NBH*HDIM*SLD];
__device__ __half  g_attno[NROWS_WIN*DIMC];
__device__ float   g_proj [NROWS_WIN*DIMC];
__device__ float   g_x1   [NROWS_IMG*DIMC];
__device__ __half  g_yln  [NROWS_IMG*DIMC];
__device__ __half  g_h1   [NROWS_IMG*MLPD];
__device__ float   g_y2   [NROWS_IMG*DIMC];
__device__ __half  g_qkvT [3*DIMC*DIMC];
__device__ __half  g_projT[DIMC*DIMC];
__device__ __half  g_fc1T [MLPD*DIMC];
__device__ __half  g_fc2T [DIMC*MLPD];

// ================= helpers =================
__device__ __forceinline__ uint32_t smem_u32(const void* p) {
    uint32_t a;
    asm("{ .reg .u64 t; cvta.to.shared.u64 t, %1; cvt.u32.u64 %0, t; }" : "=r"(a) : "l"(p));
    return a;
}
__device__ __forceinline__ void cp_async16(uint32_t dst, const void* src) {
    asm volatile("cp.async.cg.shared.global [%0], [%1], 16;" :: "r"(dst), "l"(src));
}
#define CP_COMMIT() asm volatile("cp.async.commit_group;" ::: "memory")
#define CP_WAIT(n)  asm volatile("cp.async.wait_group %0;" :: "n"(n) : "memory")

__device__ __forceinline__ void mma_f16(float* c, const uint32_t* a, const uint32_t* b) {
    asm volatile(
        "mma.sync.aligned.m16n8k16.row.col.f32.f16.f16.f32 "
        "{%0,%1,%2,%3}, {%4,%5,%6,%7}, {%8,%9}, {%0,%1,%2,%3};"
        : "+f"(c[0]), "+f"(c[1]), "+f"(c[2]), "+f"(c[3])
        : "r"(a[0]), "r"(a[1]), "r"(a[2]), "r"(a[3]), "r"(b[0]), "r"(b[1]));
}
__device__ __forceinline__ void ldmx4(uint32_t& r0, uint32_t& r1, uint32_t& r2, uint32_t& r3,
                                      uint32_t addr) {
    asm volatile("ldmatrix.sync.aligned.m8n8.x4.shared.b16 {%0,%1,%2,%3}, [%4];"
        : "=r"(r0), "=r"(r1), "=r"(r2), "=r"(r3) : "r"(addr));
}

// ================= fp16 mma.sync GEMM: BKE=64 K-chunks =================
#define BM 128
#define BN 128
#define BKE2 64                      // K elements per chunk (main GEMM)
#define LDW2 36                      // 32 data words + 4 pad
#define TBUF2 (BM*LDW2)
#define GEMM_SMEM ((4*TBUF2 + 128) * 4)

__global__ void __launch_bounds__(256, 2)
k_mma_gemm(const __half* __restrict__ A, const __half* __restrict__ Bt,
           const float* __restrict__ bias, void* __restrict__ Cout,
           int M, int N, int K, int act, int outf16) {
    extern __shared__ float sm[];
    uint32_t* As = (uint32_t*)sm;
    uint32_t* Bs = As + 2*TBUF2;
    float* sbias = sm + 4*TBUF2;

    int tid = threadIdx.x, lane = tid & 31, wid = tid >> 5;
    int wm = wid >> 1, wn = wid & 1;
    int m0 = blockIdx.y * BM, n0 = blockIdx.x * BN;

    if (tid < 128) sbias[tid] = bias[n0 + tid];

    auto load_tile = [&](int kc, int bsel) {
        int k0 = kc * BKE2;
        uint32_t* abuf = As + bsel * TBUF2;
        uint32_t* bbuf = Bs + bsel * TBUF2;
        #pragma unroll
        for (int it = 0; it < 4; it++) {      // 1024 16B-chunks per 128x64 tile
            int idx = tid + it * 256;
            int r = idx >> 3, c = idx & 7;
            int ar = m0 + r;
            const __half* asrc = A + (long)(ar < M ? ar : M - 1) * K + k0 + c * 8;
            cp_async16(smem_u32(abuf + r * LDW2 + c * 4), asrc);
            const __half* bsrc = Bt + (long)(n0 + r) * K + k0 + c * 8;
            cp_async16(smem_u32(bbuf + r * LDW2 + c * 4), bsrc);
        }
        CP_COMMIT();
    };

    int m8 = lane >> 3, r8 = lane & 7;
    uint32_t aoff[2], boff[4];
    #pragma unroll
    for (int mt = 0; mt < 2; mt++)
        aoff[mt] = (uint32_t)((wm * 32 + mt * 16 + (m8 & 1) * 8 + r8) * LDW2 + (m8 >> 1) * 4);
    #pragma unroll
    for (int p = 0; p < 4; p++)
        boff[p] = (uint32_t)((wn * 64 + p * 16 + (m8 >> 1) * 8 + r8) * LDW2 + (m8 & 1) * 4);
    uint32_t a_base = smem_u32(As);
    uint32_t b_base = smem_u32(Bs);

    float acc[2][8][4];
    #pragma unroll
    for (int mt = 0; mt < 2; mt++)
        #pragma unroll
        for (int nt = 0; nt < 8; nt++)
            #pragma unroll
            for (int j = 0; j < 4; j++) acc[mt][nt][j] = 0.f;

    const int NKC = K / BKE2;
    load_tile(0, 0);
    for (int i = 0; i < NKC; i++) {
        int cur = i & 1;
        if (i + 1 < NKC) { load_tile(i + 1, cur ^ 1); CP_WAIT(1); }
        else             { CP_WAIT(0); }
        __syncthreads();
        uint32_t ab = a_base + cur * (TBUF2 * 4);
        uint32_t bb = b_base + cur * (TBUF2 * 4);
        #pragma unroll
        for (int ks = 0; ks < 4; ks++) {      // four K=16 steps per 64-elt chunk
            uint32_t af[2][4], bf[8][2];
            #pragma unroll
            for (int mt = 0; mt < 2; mt++)
                ldmx4(af[mt][0], af[mt][1], af[mt][2], af[mt][3],
                      ab + (aoff[mt] + ks * 8) * 4);
            #pragma unroll
            for (int p = 0; p < 4; p++)
                ldmx4(bf[2*p][0], bf[2*p][1], bf[2*p+1][0], bf[2*p+1][1],
                      bb + (boff[p] + ks * 8) * 4);
            #pragma unroll
            for (int mt = 0; mt < 2; mt++)
                #pragma unroll
                for (int nt = 0; nt < 8; nt++)
                    mma_f16(acc[mt][nt], af[mt], bf[nt]);
        }
        __syncthreads();
    }

    int rb = m0 + wm * 32 + (lane >> 2);
    int cb = wn * 64 + 2 * (lane & 3);
    #pragma unroll
    for (int mt = 0; mt < 2; mt++) {
        int r0 = rb + mt * 16, r1 = r0 + 8;
        #pragma unroll
        for (int nt = 0; nt < 8; nt++) {
            int cc = cb + nt * 8;
            float v0 = acc[mt][nt][0] + sbias[cc];
            float v1 = acc[mt][nt][1] + sbias[cc + 1];
            float v2 = acc[mt][nt][2] + sbias[cc];
            float v3 = acc[mt][nt][3] + sbias[cc + 1];
            if (act == 1) {
                v0 = 0.5f * v0 * (1.0f + erff(v0 * 0.70710678118654752f));
                v1 = 0.5f * v1 * (1.0f + erff(v1 * 0.70710678118654752f));
                v2 = 0.5f * v2 * (1.0f + erff(v2 * 0.70710678118654752f));
                v3 = 0.5f * v3 * (1.0f + erff(v3 * 0.70710678118654752f));
            }
            if (outf16) {
                __half* C = (__half*)Cout;
                if (r0 < M) *(__half2*)(C + (long)r0 * N + n0 + cc) = __floats2half2_rn(v0, v1);
                if (r1 < M) *(__half2*)(C + (long)r1 * N + n0 + cc) = __floats2half2_rn(v2, v3);
            } else {
                float* C = (float*)Cout;
                if (r0 < M) *(float2*)(C + (long)r0 * N + n0 + cc) = make_float2(v0, v1);
                if (r1 < M) *(float2*)(C + (long)r1 * N + n0 + cc) = make_float2(v2, v3);
            }
        }
    }
}

// ================= attention kernels (R13-proven, BKE=32 / LDW=20) ===========
#define BKE 32
#define LDW 20
#define TBUF (BM*LDW)
#define QK_SMEM ((4*TBUF + 128) * 4)

__global__ void __launch_bounds__(256, 2)
k_qk_gemm(const __half* __restrict__ qkv, __half* __restrict__ S) {
    extern __shared__ float sm[];
    uint32_t* As = (uint32_t*)sm;
    uint32_t* Bs = As + 2*TBUF;

    int tid = threadIdx.x, lane = tid & 31, wid = tid >> 5;
    int wm = wid >> 1, wn = wid & 1;
    int m0 = blockIdx.y * BM, n0 = blockIdx.x * BN;
    int bz = blockIdx.z;
    int win = bz / HEADS, head = bz % HEADS;
    const __half* Qb = qkv + (long)win * NTOK * (3 * DIMC) + head * HDIM;
    const __half* Kb = Qb + DIMC;
    __half* Sb = S + (long)bz * NTOK * SLD;

    auto load_tile = [&](int kc, int bsel) {
        int k0 = kc * BKE;
        uint32_t* abuf = As + bsel * TBUF;
        uint32_t* bbuf = Bs + bsel * TBUF;
        #pragma unroll
        for (int it = 0; it < 2; it++) {
            int idx = tid + it * 256;
            int r = idx >> 2, c = idx & 3;
            int ar = m0 + r; ar = ar < NTOK ? ar : NTOK - 1;
            cp_async16(smem_u32(abuf + r * LDW + c * 4), Qb + (long)ar * (3 * DIMC) + k0 + c * 8);
            int br = n0 + r; br = br < NTOK ? br : NTOK - 1;
            cp_async16(smem_u32(bbuf + r * LDW + c * 4), Kb + (long)br * (3 * DIMC) + k0 + c * 8);
        }
        CP_COMMIT();
    };

    int m8 = lane >> 3, r8 = lane & 7;
    uint32_t aoff[2], boff[4];
    #pragma unroll
    for (int mt = 0; mt < 2; mt++)
        aoff[mt] = (uint32_t)((wm * 32 + mt * 16 + (m8 & 1) * 8 + r8) * LDW + (m8 >> 1) * 4);
    #pragma unroll
    for (int p = 0; p < 4; p++)
        boff[p] = (uint32_t)((wn * 64 + p * 16 + (m8 >> 1) * 8 + r8) * LDW + (m8 & 1) * 4);
    uint32_t a_base = smem_u32(As);
    uint32_t b_base = smem_u32(Bs);

    float acc[2][8][4];
    #pragma unroll
    for (int mt = 0; mt < 2; mt++)
        #pragma unroll
        for (int nt = 0; nt < 8; nt++)
            #pragma unroll
            for (int j = 0; j < 4; j++) acc[mt][nt][j] = 0.f;

    load_tile(0, 0);
    #pragma unroll
    for (int i = 0; i < 2; i++) {
        int cur = i & 1;
        if (i + 1 < 2) { load_tile(1, 1); CP_WAIT(1); }
        else           { CP_WAIT(0); }
        __syncthreads();
        uint32_t ab = a_base + cur * (TBUF * 4);
        uint32_t bb = b_base + cur * (TBUF * 4);
        #pragma unroll
        for (int ks = 0; ks < 2; ks++) {
            uint32_t af[2][4], bf[8][2];
            #pragma unroll
            for (int mt = 0; mt < 2; mt++)
                ldmx4(af[mt][0], af[mt][1], af[mt][2], af[mt][3],
                      ab + (aoff[mt] + ks * 8) * 4);
            #pragma unroll
            for (int p = 0; p < 4; p++)
                ldmx4(bf[2*p][0], bf[2*p][1], bf[2*p+1][0], bf[2*p+1][1],
                      bb + (boff[p] + ks * 8) * 4);
            #pragma unroll
            for (int mt = 0; mt < 2; mt++)
                #pragma unroll
                for (int nt = 0; nt < 8; nt++)
                    mma_f16(acc[mt][nt], af[mt], bf[nt]);
        }
        __syncthreads();
    }

    int rb = m0 + wm * 32 + (lane >> 2);
    int cb = wn * 64 + 2 * (lane & 3);
    #pragma unroll
    for (int mt = 0; mt < 2; mt++) {
        int r0 = rb + mt * 16, r1 = r0 + 8;
        #pragma unroll
        for (int nt = 0; nt < 8; nt++) {
            int cc = n0 + cb + nt * 8;
            if (cc + 1 < SLD) {
                if (r0 < NTOK) *(__half2*)(Sb + (long)r0 * SLD + cc) =
                    __floats2half2_rn(acc[mt][nt][0], acc[mt][nt][1]);
                if (r1 < NTOK) *(__half2*)(Sb + (long)r1 * SLD + cc) =
                    __floats2half2_rn(acc[mt][nt][2], acc[mt][nt][3]);
            }
        }
    }
}

// ================= V transpose prep ======
#define LDV 66
__global__ void __launch_bounds__(256)
k_vt(const __half* __restrict__ qkv, __half* __restrict__ Vt) {
    __shared__ __half smv[NTOK * LDV];
    int bz = blockIdx.x;
    int win = bz / HEADS, head = bz % HEADS;
    const __half* Vb = qkv + (long)win * NTOK * (3 * DIMC) + 2 * DIMC + head * HDIM;
    int tid = threadIdx.x;
    for (int i = tid; i < NTOK * HDIM; i += 256) {
        int t = i >> 6, d = i & 63;
        smv[t * LDV + d] = Vb[(long)t * (3 * DIMC) + d];
    }
    __syncthreads();
    __half* out = Vt + (long)bz * HDIM * SLD;
    for (int o = tid; o < HDIM * SLD; o += 256) {
        int n = o / SLD, k = o - n * SLD;
        out[o] = (k < NTOK) ? smv[k * LDV + n] : __float2half_rn(0.f);
    }
}

// ================= softmax + rel-pos bias ===================
#define RELSTRIDE 65
__global__ void __launch_bounds__(392, 2)
k_softmax(__half* __restrict__ S, const __half* __restrict__ qkv,
          const float* __restrict__ rel_pos_h, const float* __restrict__ rel_pos_w) {
    __shared__ float RH[27 * RELSTRIDE];
    __shared__ float RW[27 * RELSTRIDE];
    int bz = blockIdx.x;
    int win = bz / HEADS, head = bz % HEADS;
    int tid = threadIdx.x;
    for (int i = tid; i < 27 * HDIM; i += 392) {
        int r = i >> 6, d = i & 63;
        RH[r * RELSTRIDE + d] = rel_pos_h[i];
        RW[r * RELSTRIDE + d] = rel_pos_w[i];
    }
    __syncthreads();

    int q = tid >> 1, half = tid & 1;
    int qh = q / WS, qw = q % WS;
    unsigned pmask = ((tid & ~31) == 384) ? 0x000000ffu : 0xffffffffu;

    float qv[32];
    {
        const __half* qp = qkv + (long)win * NTOK * (3 * DIMC) + (long)q * (3 * DIMC)
                           + head * HDIM + half * 32;
        #pragma unroll
        for (int d = 0; d < 32; d += 2) {
            float2 f = __half22float2(*(const __half2*)(qp + d));
            qv[d] = f.x; qv[d + 1] = f.y;
        }
    }

    float rh[WS], rw[WS];
    #pragma unroll
    for (int kh = 0; kh < WS; kh++) {
        const float* ph = &RH[(qh - kh + WS - 1) * RELSTRIDE + half * 32];
        const float* pw = &RW[(qw - kh + WS - 1) * RELSTRIDE + half * 32];
        float sh = 0.f, sw = 0.f;
        #pragma unroll
        for (int d = 0; d < 32; d++) { sh = fmaf(qv[d], ph[d], sh); sw = fmaf(qv[d], pw[d], sw); }
        sh += __shfl_xor_sync(pmask, sh, 1);
        sw += __shfl_xor_sync(pmask, sw, 1);
        rh[kh] = sh; rw[kh] = sw;
    }

    __half* Srow = S + (long)bz * NTOK * SLD + (long)q * SLD;
    float m = -1e30f, l = 0.f;
    {
        int kh = 8 * half, kw = 0;
        for (int j = 0; j < 112; j++) {
            int col = half * 112 + j;
            if (col < NTOK) {
                float s = __half2float(Srow[col]) * SCALE_F + rh[kh] + rw[kw];
                if (s > m) { l = l * __expf(m - s) + 1.f; m = s; }
                else       { l += __expf(s - m); }
            }
            if (++kw == WS) { kw = 0; kh++; }
        }
    }
    float mo = __shfl_xor_sync(pmask, m, 1);
    float lo = __shfl_xor_sync(pmask, l, 1);
    float mj = fmaxf(m, mo);
    float lj = l * __expf(m - mj) + lo * __expf(mo - mj);
    float inv = 1.f / lj;
    {
        int kh = 8 * half, kw = 0;
        for (int j = 0; j < 112; j++) {
            int col = half * 112 + j;
            if (col < NTOK) {
                float s = __half2float(Srow[col]) * SCALE_F + rh[kh] + rw[kw];
                Srow[col] = __float2half_rn(__expf(s - mj) * inv);
            } else {
                Srow[col] = __float2half_rn(0.f);
            }
            if (++kw == WS) { kw = 0; kh++; }
        }
    }
}

// ================= batched PV GEMM ==
#define TBUFA (BM*LDW)
#define TBUFB (64*LDW)
#define PV_SMEM ((2*TBUFA + 2*TBUFB) * 4)

__global__ void __launch_bounds__(256, 2)
k_pv_gemm(const __half* __restrict__ S, const __half* __restrict__ Vt,
          __half* __restrict__ attno) {
    extern __shared__ float sm[];
    uint32_t* As = (uint32_t*)sm;
    uint32_t* Bs = As + 2*TBUFA;

    int tid = threadIdx.x, lane = tid & 31, wid = tid >> 5;
    int m0 = blockIdx.y * BM;
    int bz = blockIdx.z;
    int win = bz / HEADS, head = bz % HEADS;
    const __half* Pb = S + (long)bz * NTOK * SLD;
    const __half* Vb = Vt + (long)bz * HDIM * SLD;
    __half* Cb = attno + (long)win * NTOK * DIMC + head * HDIM;

    auto load_tile = [&](int kc, int bsel) {
        int k0 = kc * BKE;
        uint32_t* abuf = As + bsel * TBUFA;
        uint32_t* bbuf = Bs + bsel * TBUFB;
        #pragma unroll
        for (int it = 0; it < 2; it++) {
            int idx = tid + it * 256;
            int r = idx >> 2, c = idx & 3;
            int ar = m0 + r; ar = ar < NTOK ? ar : NTOK - 1;
            cp_async16(smem_u32(abuf + r * LDW + c * 4), Pb + (long)ar * SLD + k0 + c * 8);
        }
        {
            int r = tid >> 2, c = tid & 3;
            cp_async16(smem_u32(bbuf + r * LDW + c * 4), Vb + (long)r * SLD + k0 + c * 8);
        }
        CP_COMMIT();
    };

    int m8 = lane >> 3, r8 = lane & 7;
    uint32_t aoff = (uint32_t)((wid * 16 + (m8 & 1) * 8 + r8) * LDW + (m8 >> 1) * 4);
    uint32_t boff[4];
    #pragma unroll
    for (int p = 0; p < 4; p++)
        boff[p] = (uint32_t)((p * 16 + (m8 >> 1) * 8 + r8) * LDW + (m8 & 1) * 4);
    uint32_t a_base = smem_u32(As);
    uint32_t b_base = smem_u32(Bs);

    float acc[8][4];
    #pragma unroll
    for (int nt = 0; nt < 8; nt++)
        #pragma unroll
        for (int j = 0; j < 4; j++) acc[nt][j] = 0.f;

    const int NKC = SLD / BKE;   // 7
    load_tile(0, 0);
    for (int i = 0; i < NKC; i++) {
        int cur = i & 1;
        if (i + 1 < NKC) { load_tile(i + 1, cur ^ 1); CP_WAIT(1); }
        else             { CP_WAIT(0); }
        __syncthreads();
        uint32_t ab = a_base + cur * (TBUFA * 4);
        uint32_t bb = b_base + cur * (TBUFB * 4);
        #pragma unroll
        for (int ks = 0; ks < 2; ks++) {
            uint32_t af[4], bf[8][2];
            ldmx4(af[0], af[1], af[2], af[3], ab + (aoff + ks * 8) * 4);
            #pragma unroll
            for (int p = 0; p < 4; p++)
                ldmx4(bf[2*p][0], bf[2*p][1], bf[2*p+1][0], bf[2*p+1][1],
                      bb + (boff[p] + ks * 8) * 4);
            #pragma unroll
            for (int nt = 0; nt < 8; nt++)
                mma_f16(acc[nt], af, bf[nt]);
        }
        __syncthreads();
    }

    int r0 = m0 + wid * 16 + (lane >> 2), r1 = r0 + 8;
    int cb = 2 * (lane & 3);
    #pragma unroll
    for (int nt = 0; nt < 8; nt++) {
        int cc = cb + nt * 8;
        if (r0 < NTOK) *(__half2*)(Cb + (long)r0 * DIMC + cc) =
            __floats2half2_rn(acc[nt][0], acc[nt][1]);
        if (r1 < NTOK) *(__half2*)(Cb + (long)r1 * DIMC + cc) =
            __floats2half2_rn(acc[nt][2], acc[nt][3]);
    }
}

// ---------------- NCHW -> NHWC transpose ----------------
__global__ void k_transpose_in(const float* __restrict__ in, float* __restrict__ out) {
    __shared__ float tile[32][33];
    int b = blockIdx.z, c0 = blockIdx.y * 32, s0 = blockIdx.x * 32;
    const float* ib = in + (long)b * DIMC * 4096;
    float* ob = out + (long)b * 4096 * DIMC;
    int x = threadIdx.x, y = threadIdx.y;
    #pragma unroll
    for (int i = 0; i < 32; i += 8)
        tile[y + i][x] = ib[(long)(c0 + y + i) * 4096 + s0 + x];
    __syncthreads();
    #pragma unroll
    for (int i = 0; i < 32; i += 8)
        ob[(long)(s0 + y + i) * DIMC + c0 + x] = tile[x][y + i];
}

// ---------------- weight transpose to fp16 ----------------
__global__ void k_transpose_w(const float* __restrict__ in, __half* __restrict__ out,
                              int R, int C) {
    __shared__ float tile[32][33];
    int r0 = blockIdx.y * 32, c0 = blockIdx.x * 32;
    int x = threadIdx.x, y = threadIdx.y;
    #pragma unroll
    for (int i = 0; i < 32; i += 8)
        tile[y + i][x] = in[(long)(r0 + y + i) * C + c0 + x];
    __syncthreads();
    #pragma unroll
    for (int i = 0; i < 32; i += 8)
        out[(long)(c0 + y + i) * R + r0 + x] = __float2half_rn(tile[x][y + i]);
}

// ---------------- block reduction ----------------
__device__ __forceinline__ float block_sum_256(float v, float* red) {
    int tid = threadIdx.x;
    #pragma unroll
    for (int o = 16; o > 0; o >>= 1) v += __shfl_xor_sync(0xffffffffu, v, o);
    if ((tid & 31) == 0) red[tid >> 5] = v;
    __syncthreads();
    float r = 0.f;
    if (tid < 8) {
        r = red[tid];
        #pragma unroll
        for (int o = 4; o > 0; o >>= 1) r += __shfl_xor_sync(0xffu, r, o);
        if (tid == 0) red[0] = r;
    }
    __syncthreads();
    r = red[0];
    __syncthreads();
    return r;
}

// ---------------- LN1 + window partition (fp16 output) ----------------
__global__ void k_ln1_window(const float* __restrict__ xnhwc,
                             const float* __restrict__ w, const float* __restrict__ bs,
                             __half* __restrict__ xwin) {
    __shared__ float red[8];
    int idx = blockIdx.x;
    int win = idx / NTOK, t = idx % NTOK;
    int b = win / 25, wrem = win % 25;
    int gr = (wrem / 5) * WS + t / WS;
    int gc = (wrem % 5) * WS + t % WS;
    __half* orow = xwin + (long)idx * DIMC;
    int tid = threadIdx.x;
    if (gr >= IMGH || gc >= IMGW) {
        for (int c = tid; c < DIMC; c += 256) orow[c] = __float2half_rn(0.f);
        return;
    }
    const float* irow = xnhwc + ((long)b * 4096 + gr * IMGW + gc) * DIMC;
    float v[3], s = 0.f, s2 = 0.f;
    #pragma unroll
    for (int i = 0; i < 3; i++) { float x = irow[tid + i * 256]; v[i] = x; s += x; s2 += x * x; }
    float tot = block_sum_256(s, red);
    float tot2 = block_sum_256(s2, red);
    float mu = tot * (1.f / DIMC);
    float rstd = rsqrtf(tot2 * (1.f / DIMC) - mu * mu + EPS_F);
    #pragma unroll
    for (int i = 0; i < 3; i++) {
        int c = tid + i * 256;
        orow[c] = __float2half_rn((v[i] - mu) * rstd * w[c] + bs[c]);
    }
}

// ---------------- fused: window unpartition + residual + LN2 ----------------
__global__ void k_scatter_ln2(const float* __restrict__ xnhwc, const float* __restrict__ proj,
                              const float* __restrict__ w, const float* __restrict__ bs,
                              float* __restrict__ x1, __half* __restrict__ yln) {
    __shared__ float red[8];
    int row = blockIdx.x;
    int b = row >> 12, sp = row & 4095;
    int r = sp >> 6, cw = sp & 63;
    int win = b * 25 + (r / WS) * 5 + (cw / WS);
    int t = (r % WS) * WS + (cw % WS);
    const float* prow = proj + ((long)win * NTOK + t) * DIMC;
    const float* xrow = xnhwc + (long)row * DIMC;
    float* orow = x1 + (long)row * DIMC;
    __half* lrow = yln + (long)row * DIMC;
    int tid = threadIdx.x;
    float v[3], s = 0.f, s2 = 0.f;
    #pragma unroll
    for (int i = 0; i < 3; i++) {
        int c = tid + i * 256;
        float x = xrow[c] + prow[c];
        orow[c] = x;
        v[i] = x; s += x; s2 += x * x;
    }
    float tot = block_sum_256(s, red);
    float tot2 = block_sum_256(s2, red);
    float mu = tot * (1.f / DIMC);
    float rstd = rsqrtf(tot2 * (1.f / DIMC) - mu * mu + EPS_F);
    #pragma unroll
    for (int i = 0; i < 3; i++) {
        int c = tid + i * 256;
        lrow[c] = __float2half_rn((v[i] - mu) * rstd * w[c] + bs[c]);
    }
}

// ---------------- final: x1 + mlp_out, NHWC -> NCHW ----------------
__global__ void k_final(const float* __restrict__ x1, const float* __restrict__ y2,
                        float* __restrict__ out) {
    __shared__ float tile[32][33];
    int b = blockIdx.z, s0 = blockIdx.x * 32, c0 = blockIdx.y * 32;
    int x = threadIdx.x, y = threadIdx.y;
    #pragma unroll
    for (int i = 0; i < 32; i += 8) {
        long row = (long)b * 4096 + s0 + y + i;
        tile[y + i][x] = x1[row * DIMC + c0 + x] + y2[row * DIMC + c0 + x];
    }
    __syncthreads();
    #pragma unroll
    for (int i = 0; i < 32; i += 8)
        out[((long)b * DIMC + c0 + y + i) * 4096 + s0 + x] = tile[x][y + i];
}

// ---------------- launcher ----------------
extern "C" void kernel_launch(void* const* d_in, const int* in_sizes, int n_in,
                              void* d_out, int out_size) {
    const float* hidden = (const float*)d_in[0];
    const float* ln1_w = (const float*)d_in[1];
    const float* ln1_b = (const float*)d_in[2];
    const float* qkv_w = (const float*)d_in[3];
    const float* qkv_b = (const float*)d_in[4];
    const float* proj_w = (const float*)d_in[5];
    const float* proj_b = (const float*)d_in[6];
    const float* relh = (const float*)d_in[7];
    const float* relw = (const float*)d_in[8];
    const float* ln2_w = (const float*)d_in[9];
    const float* ln2_b = (const float*)d_in[10];
    const float* fc1_w = (const float*)d_in[11];
    const float* fc1_b = (const float*)d_in[12];
    const float* fc2_w = (const float*)d_in[13];
    const float* fc2_b = (const float*)d_in[14];
    float* out = (float*)d_out;

    float *xnhwc, *proj, *x1, *y2;
    __half *xwin, *qkv, *S, *Vt, *attno, *yln, *h1, *qkvT, *projT, *fc1T, *fc2T;
    cudaGetSymbolAddress((void**)&xnhwc, g_xnhwc);
    cudaGetSymbolAddress((void**)&xwin, g_xwin);
    cudaGetSymbolAddress((void**)&qkv, g_qkv);
    cudaGetSymbolAddress((void**)&S, g_S);
    cudaGetSymbolAddress((void**)&Vt, g_Vt);
    cudaGetSymbolAddress((void**)&attno, g_attno);
    cudaGetSymbolAddress((void**)&proj, g_proj);
    cudaGetSymbolAddress((void**)&x1, g_x1);
    cudaGetSymbolAddress((void**)&yln, g_yln);
    cudaGetSymbolAddress((void**)&h1, g_h1);
    cudaGetSymbolAddress((void**)&y2, g_y2);
    cudaGetSymbolAddress((void**)&qkvT, g_qkvT);
    cudaGetSymbolAddress((void**)&projT, g_projT);
    cudaGetSymbolAddress((void**)&fc1T, g_fc1T);
    cudaGetSymbolAddress((void**)&fc2T, g_fc2T);

    cudaFuncSetAttribute(k_mma_gemm, cudaFuncAttributeMaxDynamicSharedMemorySize, GEMM_SMEM);
    cudaFuncSetAttribute(k_qk_gemm, cudaFuncAttributeMaxDynamicSharedMemorySize, QK_SMEM);
    cudaFuncSetAttribute(k_pv_gemm, cudaFuncAttributeMaxDynamicSharedMemorySize, PV_SMEM);

    dim3 tb(32, 8);
    // weight transposes
    k_transpose_w<<<dim3(3 * DIMC / 32, DIMC / 32), tb>>>(qkv_w, qkvT, DIMC, 3 * DIMC);
    k_transpose_w<<<dim3(DIMC / 32, DIMC / 32), tb>>>(proj_w, projT, DIMC, DIMC);
    k_transpose_w<<<dim3(MLPD / 32, DIMC / 32), tb>>>(fc1_w, fc1T, DIMC, MLPD);
    k_transpose_w<<<dim3(DIMC / 32, MLPD / 32), tb>>>(fc2_w, fc2T, MLPD, DIMC);

    // NCHW -> NHWC, LN1+window
    k_transpose_in<<<dim3(128, 24, BATCH), tb>>>(hidden, xnhwc);
    k_ln1_window<<<NROWS_WIN, 256>>>(xnhwc, ln1_w, ln1_b, xwin);
    // QKV GEMM -> fp16
    k_mma_gemm<<<dim3(3 * DIMC / 128, (NROWS_WIN + 127) / 128), 256, GEMM_SMEM>>>(
        xwin, qkvT, qkv_b, qkv, NROWS_WIN, 3 * DIMC, DIMC, 0, 1);
    // attention: V transpose, QK^T, softmax, PV
    k_vt<<<NBH, 256>>>(qkv, Vt);
    k_qk_gemm<<<dim3(2, 2, NBH), 256, QK_SMEM>>>(qkv, S);
    k_softmax<<<NBH, 392>>>(S, qkv, relh, relw);
    k_pv_gemm<<<dim3(1, 2, NBH), 256, PV_SMEM>>>(S, Vt, attno);
    // proj -> fp32
    k_mma_gemm<<<dim3(DIMC / 128, (NROWS_WIN + 127) / 128), 256, GEMM_SMEM>>>(
        attno, projT, proj_b, proj, NROWS_WIN, DIMC, DIMC, 0, 0);
    // residual + LN2
    k_scatter_ln2<<<NROWS_IMG, 256>>>(xnhwc, proj, ln2_w, ln2_b, x1, yln);
    // FC1 + GELU -> fp16
    k_mma_gemm<<<dim3(MLPD / 128, NROWS_IMG / 128), 256, GEMM_SMEM>>>(
        yln, fc1T, fc1_b, h1, NROWS_IMG, MLPD, DIMC, 1, 1);
    // FC2 -> fp32
    k_mma_gemm<<<dim3(DIMC / 128, NROWS_IMG / 128), 256, GEMM_SMEM>>>(
        h1, fc2T, fc2_b, y2, NROWS_IMG, DIMC, MLPD, 0, 0);
    // residual + NHWC -> NCHW
    k_final<<<dim3(128, 24, BATCH), tb>>>(x1, y2, out);
}

// round 15
// speedup vs baseline: 1.5406x; 1.3068x over previous
#include <cuda_runtime.h>
#include <cuda_fp16.h>
#include <math.h>
#include <stdint.h>

// ---------------- problem constants ----------------
#define DIMC    768
#define HEADS   12
#define HDIM    64
#define WS      14
#define NTOK    196
#define MLPD    3072
#define BATCH   4
#define IMGH    64
#define IMGW    64
#define NWIN    100
#define NROWS_WIN (NWIN*NTOK)
#define NROWS_IMG (BATCH*IMGH*IMGW)
#define NBH     (NWIN*HEADS)
#define SLD     224
#define SCALE_F 0.125f
#define EPS_F   1e-6f

// ---------------- scratch ----------------
__device__ float   g_xnhwc[BATCH*IMGH*IMGW*DIMC];
__device__ __half  g_xwin [NROWS_WIN*DIMC];
__device__ __half  g_qkv  [NROWS_WIN*3*DIMC];
__device__ __half  g_S    [(long)NBH*NTOK*SLD];
__device__ __half  g_Vt   [(long)NBH*HDIM*SLD];
__device__ __half  g_attno[NROWS_WIN*DIMC];
__device__ __half  g_proj [NROWS_WIN*DIMC];      // fp16 now
__device__ float   g_x1   [NROWS_IMG*DIMC];
__device__ __half  g_yln  [NROWS_IMG*DIMC];
__device__ __half  g_h1   [NROWS_IMG*MLPD];
__device__ float   g_y2   [NROWS_IMG*DIMC];
__device__ __half  g_qkvT [3*DIMC*DIMC];
__device__ __half  g_projT[DIMC*DIMC];
__device__ __half  g_fc1T [MLPD*DIMC];
__device__ __half  g_fc2T [DIMC*MLPD];

// ================= helpers =================
__device__ __forceinline__ uint32_t smem_u32(const void* p) {
    uint32_t a;
    asm("{ .reg .u64 t; cvta.to.shared.u64 t, %1; cvt.u32.u64 %0, t; }" : "=r"(a) : "l"(p));
    return a;
}
__device__ __forceinline__ void cp_async16(uint32_t dst, const void* src) {
    asm volatile("cp.async.cg.shared.global [%0], [%1], 16;" :: "r"(dst), "l"(src));
}
#define CP_COMMIT() asm volatile("cp.async.commit_group;" ::: "memory")
#define CP_WAIT(n)  asm volatile("cp.async.wait_group %0;" :: "n"(n) : "memory")

__device__ __forceinline__ void mma_f16(float* c, const uint32_t* a, const uint32_t* b) {
    asm volatile(
        "mma.sync.aligned.m16n8k16.row.col.f32.f16.f16.f32 "
        "{%0,%1,%2,%3}, {%4,%5,%6,%7}, {%8,%9}, {%0,%1,%2,%3};"
        : "+f"(c[0]), "+f"(c[1]), "+f"(c[2]), "+f"(c[3])
        : "r"(a[0]), "r"(a[1]), "r"(a[2]), "r"(a[3]), "r"(b[0]), "r"(b[1]));
}
__device__ __forceinline__ void ldmx4(uint32_t& r0, uint32_t& r1, uint32_t& r2, uint32_t& r3,
                                      uint32_t addr) {
    asm volatile("ldmatrix.sync.aligned.m8n8.x4.shared.b16 {%0,%1,%2,%3}, [%4];"
        : "=r"(r0), "=r"(r1), "=r"(r2), "=r"(r3) : "r"(addr));
}

// ================= fp16 mma.sync GEMM: BKE=64 K-chunks, optional residual =====
#define BM 128
#define BN 128
#define BKE2 64
#define LDW2 36
#define TBUF2 (BM*LDW2)
#define GEMM_SMEM ((4*TBUF2 + 128) * 4)

__global__ void __launch_bounds__(256, 2)
k_mma_gemm(const __half* __restrict__ A, const __half* __restrict__ Bt,
           const float* __restrict__ bias, void* __restrict__ Cout,
           int M, int N, int K, int act, int outf16,
           const float* __restrict__ resid) {
    extern __shared__ float sm[];
    uint32_t* As = (uint32_t*)sm;
    uint32_t* Bs = As + 2*TBUF2;
    float* sbias = sm + 4*TBUF2;

    int tid = threadIdx.x, lane = tid & 31, wid = tid >> 5;
    int wm = wid >> 1, wn = wid & 1;
    int m0 = blockIdx.y * BM, n0 = blockIdx.x * BN;

    if (tid < 128) sbias[tid] = bias[n0 + tid];

    auto load_tile = [&](int kc, int bsel) {
        int k0 = kc * BKE2;
        uint32_t* abuf = As + bsel * TBUF2;
        uint32_t* bbuf = Bs + bsel * TBUF2;
        #pragma unroll
        for (int it = 0; it < 4; it++) {
            int idx = tid + it * 256;
            int r = idx >> 3, c = idx & 7;
            int ar = m0 + r;
            const __half* asrc = A + (long)(ar < M ? ar : M - 1) * K + k0 + c * 8;
            cp_async16(smem_u32(abuf + r * LDW2 + c * 4), asrc);
            const __half* bsrc = Bt + (long)(n0 + r) * K + k0 + c * 8;
            cp_async16(smem_u32(bbuf + r * LDW2 + c * 4), bsrc);
        }
        CP_COMMIT();
    };

    int m8 = lane >> 3, r8 = lane & 7;
    uint32_t aoff[2], boff[4];
    #pragma unroll
    for (int mt = 0; mt < 2; mt++)
        aoff[mt] = (uint32_t)((wm * 32 + mt * 16 + (m8 & 1) * 8 + r8) * LDW2 + (m8 >> 1) * 4);
    #pragma unroll
    for (int p = 0; p < 4; p++)
        boff[p] = (uint32_t)((wn * 64 + p * 16 + (m8 >> 1) * 8 + r8) * LDW2 + (m8 & 1) * 4);
    uint32_t a_base = smem_u32(As);
    uint32_t b_base = smem_u32(Bs);

    float acc[2][8][4];
    #pragma unroll
    for (int mt = 0; mt < 2; mt++)
        #pragma unroll
        for (int nt = 0; nt < 8; nt++)
            #pragma unroll
            for (int j = 0; j < 4; j++) acc[mt][nt][j] = 0.f;

    const int NKC = K / BKE2;
    load_tile(0, 0);
    for (int i = 0; i < NKC; i++) {
        int cur = i & 1;
        if (i + 1 < NKC) { load_tile(i + 1, cur ^ 1); CP_WAIT(1); }
        else             { CP_WAIT(0); }
        __syncthreads();
        uint32_t ab = a_base + cur * (TBUF2 * 4);
        uint32_t bb = b_base + cur * (TBUF2 * 4);
        #pragma unroll
        for (int ks = 0; ks < 4; ks++) {
            uint32_t af[2][4], bf[8][2];
            #pragma unroll
            for (int mt = 0; mt < 2; mt++)
                ldmx4(af[mt][0], af[mt][1], af[mt][2], af[mt][3],
                      ab + (aoff[mt] + ks * 8) * 4);
            #pragma unroll
            for (int p = 0; p < 4; p++)
                ldmx4(bf[2*p][0], bf[2*p][1], bf[2*p+1][0], bf[2*p+1][1],
                      bb + (boff[p] + ks * 8) * 4);
            #pragma unroll
            for (int mt = 0; mt < 2; mt++)
                #pragma unroll
                for (int nt = 0; nt < 8; nt++)
                    mma_f16(acc[mt][nt], af[mt], bf[nt]);
        }
        __syncthreads();
    }

    int rb = m0 + wm * 32 + (lane >> 2);
    int cb = wn * 64 + 2 * (lane & 3);
    #pragma unroll
    for (int mt = 0; mt < 2; mt++) {
        int r0 = rb + mt * 16, r1 = r0 + 8;
        #pragma unroll
        for (int nt = 0; nt < 8; nt++) {
            int cc = cb + nt * 8;
            float v0 = acc[mt][nt][0] + sbias[cc];
            float v1 = acc[mt][nt][1] + sbias[cc + 1];
            float v2 = acc[mt][nt][2] + sbias[cc];
            float v3 = acc[mt][nt][3] + sbias[cc + 1];
            if (act == 1) {
                v0 = 0.5f * v0 * (1.0f + erff(v0 * 0.70710678118654752f));
                v1 = 0.5f * v1 * (1.0f + erff(v1 * 0.70710678118654752f));
                v2 = 0.5f * v2 * (1.0f + erff(v2 * 0.70710678118654752f));
                v3 = 0.5f * v3 * (1.0f + erff(v3 * 0.70710678118654752f));
            }
            if (resid) {
                if (r0 < M) {
                    float2 rr = *(const float2*)(resid + (long)r0 * N + n0 + cc);
                    v0 += rr.x; v1 += rr.y;
                }
                if (r1 < M) {
                    float2 rr = *(const float2*)(resid + (long)r1 * N + n0 + cc);
                    v2 += rr.x; v3 += rr.y;
                }
            }
            if (outf16) {
                __half* C = (__half*)Cout;
                if (r0 < M) *(__half2*)(C + (long)r0 * N + n0 + cc) = __floats2half2_rn(v0, v1);
                if (r1 < M) *(__half2*)(C + (long)r1 * N + n0 + cc) = __floats2half2_rn(v2, v3);
            } else {
                float* C = (float*)Cout;
                if (r0 < M) *(float2*)(C + (long)r0 * N + n0 + cc) = make_float2(v0, v1);
                if (r1 < M) *(float2*)(C + (long)r1 * N + n0 + cc) = make_float2(v2, v3);
            }
        }
    }
}

// ================= attention kernels (BKE=32 / LDW=20) ===========
#define BKE 32
#define LDW 20
#define TBUF (BM*LDW)
#define QK_SMEM ((4*TBUF + 128) * 4)

__global__ void __launch_bounds__(256, 2)
k_qk_gemm(const __half* __restrict__ qkv, __half* __restrict__ S) {
    extern __shared__ float sm[];
    uint32_t* As = (uint32_t*)sm;
    uint32_t* Bs = As + 2*TBUF;

    int tid = threadIdx.x, lane = tid & 31, wid = tid >> 5;
    int wm = wid >> 1, wn = wid & 1;
    int m0 = blockIdx.y * BM, n0 = blockIdx.x * BN;
    int bz = blockIdx.z;
    int win = bz / HEADS, head = bz % HEADS;
    const __half* Qb = qkv + (long)win * NTOK * (3 * DIMC) + head * HDIM;
    const __half* Kb = Qb + DIMC;
    __half* Sb = S + (long)bz * NTOK * SLD;

    auto load_tile = [&](int kc, int bsel) {
        int k0 = kc * BKE;
        uint32_t* abuf = As + bsel * TBUF;
        uint32_t* bbuf = Bs + bsel * TBUF;
        #pragma unroll
        for (int it = 0; it < 2; it++) {
            int idx = tid + it * 256;
            int r = idx >> 2, c = idx & 3;
            int ar = m0 + r; ar = ar < NTOK ? ar : NTOK - 1;
            cp_async16(smem_u32(abuf + r * LDW + c * 4), Qb + (long)ar * (3 * DIMC) + k0 + c * 8);
            int br = n0 + r; br = br < NTOK ? br : NTOK - 1;
            cp_async16(smem_u32(bbuf + r * LDW + c * 4), Kb + (long)br * (3 * DIMC) + k0 + c * 8);
        }
        CP_COMMIT();
    };

    int m8 = lane >> 3, r8 = lane & 7;
    uint32_t aoff[2], boff[4];
    #pragma unroll
    for (int mt = 0; mt < 2; mt++)
        aoff[mt] = (uint32_t)((wm * 32 + mt * 16 + (m8 & 1) * 8 + r8) * LDW + (m8 >> 1) * 4);
    #pragma unroll
    for (int p = 0; p < 4; p++)
        boff[p] = (uint32_t)((wn * 64 + p * 16 + (m8 >> 1) * 8 + r8) * LDW + (m8 & 1) * 4);
    uint32_t a_base = smem_u32(As);
    uint32_t b_base = smem_u32(Bs);

    float acc[2][8][4];
    #pragma unroll
    for (int mt = 0; mt < 2; mt++)
        #pragma unroll
        for (int nt = 0; nt < 8; nt++)
            #pragma unroll
            for (int j = 0; j < 4; j++) acc[mt][nt][j] = 0.f;

    load_tile(0, 0);
    #pragma unroll
    for (int i = 0; i < 2; i++) {
        int cur = i & 1;
        if (i + 1 < 2) { load_tile(1, 1); CP_WAIT(1); }
        else           { CP_WAIT(0); }
        __syncthreads();
        uint32_t ab = a_base + cur * (TBUF * 4);
        uint32_t bb = b_base + cur * (TBUF * 4);
        #pragma unroll
        for (int ks = 0; ks < 2; ks++) {
            uint32_t af[2][4], bf[8][2];
            #pragma unroll
            for (int mt = 0; mt < 2; mt++)
                ldmx4(af[mt][0], af[mt][1], af[mt][2], af[mt][3],
                      ab + (aoff[mt] + ks * 8) * 4);
            #pragma unroll
            for (int p = 0; p < 4; p++)
                ldmx4(bf[2*p][0], bf[2*p][1], bf[2*p+1][0], bf[2*p+1][1],
                      bb + (boff[p] + ks * 8) * 4);
            #pragma unroll
            for (int mt = 0; mt < 2; mt++)
                #pragma unroll
                for (int nt = 0; nt < 8; nt++)
                    mma_f16(acc[mt][nt], af[mt], bf[nt]);
        }
        __syncthreads();
    }

    int rb = m0 + wm * 32 + (lane >> 2);
    int cb = wn * 64 + 2 * (lane & 3);
    #pragma unroll
    for (int mt = 0; mt < 2; mt++) {
        int r0 = rb + mt * 16, r1 = r0 + 8;
        #pragma unroll
        for (int nt = 0; nt < 8; nt++) {
            int cc = n0 + cb + nt * 8;
            if (cc + 1 < SLD) {
                if (r0 < NTOK) *(__half2*)(Sb + (long)r0 * SLD + cc) =
                    __floats2half2_rn(acc[mt][nt][0], acc[mt][nt][1]);
                if (r1 < NTOK) *(__half2*)(Sb + (long)r1 * SLD + cc) =
                    __floats2half2_rn(acc[mt][nt][2], acc[mt][nt][3]);
            }
        }
    }
}

// ================= V transpose prep (vectorized output) ======
#define LDV 66
__global__ void __launch_bounds__(256)
k_vt(const __half* __restrict__ qkv, __half* __restrict__ Vt) {
    __shared__ __half smv[NTOK * LDV];
    int bz = blockIdx.x;
    int win = bz / HEADS, head = bz % HEADS;
    const __half* Vb = qkv + (long)win * NTOK * (3 * DIMC) + 2 * DIMC + head * HDIM;
    int tid = threadIdx.x;
    for (int i = tid; i < NTOK * HDIM; i += 256) {
        int t = i >> 6, d = i & 63;
        smv[t * LDV + d] = Vb[(long)t * (3 * DIMC) + d];
    }
    __syncthreads();
    __half* out = Vt + (long)bz * HDIM * SLD;
    for (int o8 = tid; o8 < HDIM * SLD / 8; o8 += 256) {   // SLD%8==0, chunks don't cross rows
        int o = o8 * 8;
        int n = o / SLD, k = o - n * SLD;
        __half buf[8];
        #pragma unroll
        for (int j = 0; j < 8; j++)
            buf[j] = (k + j < NTOK) ? smv[(k + j) * LDV + n] : __float2half_rn(0.f);
        *(float4*)(out + o) = *(float4*)buf;
    }
}

// ================= softmax + rel-pos bias (vectorized S access) ==============
#define RELSTRIDE 65
__global__ void __launch_bounds__(392, 2)
k_softmax(__half* __restrict__ S, const __half* __restrict__ qkv,
          const float* __restrict__ rel_pos_h, const float* __restrict__ rel_pos_w) {
    __shared__ float RH[27 * RELSTRIDE];
    __shared__ float RW[27 * RELSTRIDE];
    int bz = blockIdx.x;
    int win = bz / HEADS, head = bz % HEADS;
    int tid = threadIdx.x;
    for (int i = tid; i < 27 * HDIM; i += 392) {
        int r = i >> 6, d = i & 63;
        RH[r * RELSTRIDE + d] = rel_pos_h[i];
        RW[r * RELSTRIDE + d] = rel_pos_w[i];
    }
    __syncthreads();

    int q = tid >> 1, half = tid & 1;
    int qh = q / WS, qw = q % WS;
    unsigned pmask = ((tid & ~31) == 384) ? 0x000000ffu : 0xffffffffu;

    float qv[32];
    {
        const __half* qp = qkv + (long)win * NTOK * (3 * DIMC) + (long)q * (3 * DIMC)
                           + head * HDIM + half * 32;
        #pragma unroll
        for (int d = 0; d < 32; d += 2) {
            float2 f = __half22float2(*(const __half2*)(qp + d));
            qv[d] = f.x; qv[d + 1] = f.y;
        }
    }

    float rh[WS], rw[WS];
    #pragma unroll
    for (int kh = 0; kh < WS; kh++) {
        const float* ph = &RH[(qh - kh + WS - 1) * RELSTRIDE + half * 32];
        const float* pw = &RW[(qw - kh + WS - 1) * RELSTRIDE + half * 32];
        float sh = 0.f, sw = 0.f;
        #pragma unroll
        for (int d = 0; d < 32; d++) { sh = fmaf(qv[d], ph[d], sh); sw = fmaf(qv[d], pw[d], sw); }
        sh += __shfl_xor_sync(pmask, sh, 1);
        sw += __shfl_xor_sync(pmask, sw, 1);
        rh[kh] = sh; rw[kh] = sw;
    }

    __half* Srow = S + (long)bz * NTOK * SLD + (long)q * SLD;
    // pass 1: own-half max & sum; vectorized 8-half loads
    float m = -1e30f, l = 0.f;
    {
        int kh = 8 * half, kw = 0;
        #pragma unroll
        for (int c8 = 0; c8 < 14; c8++) {
            int col0 = half * 112 + c8 * 8;
            __half hbuf[8];
            *(float4*)hbuf = *(const float4*)(Srow + col0);
            #pragma unroll
            for (int j = 0; j < 8; j++) {
                int col = col0 + j;
                if (col < NTOK) {
                    float s = __half2float(hbuf[j]) * SCALE_F + rh[kh] + rw[kw];
                    if (s > m) { l = l * __expf(m - s) + 1.f; m = s; }
                    else       { l += __expf(s - m); }
                }
                if (++kw == WS) { kw = 0; kh++; }
            }
        }
    }
    float mo = __shfl_xor_sync(pmask, m, 1);
    float lo = __shfl_xor_sync(pmask, l, 1);
    float mj = fmaxf(m, mo);
    float lj = l * __expf(m - mj) + lo * __expf(mo - mj);
    float inv = 1.f / lj;
    // pass 2: normalized probs, vectorized
    {
        int kh = 8 * half, kw = 0;
        #pragma unroll
        for (int c8 = 0; c8 < 14; c8++) {
            int col0 = half * 112 + c8 * 8;
            __half hbuf[8];
            *(float4*)hbuf = *(const float4*)(Srow + col0);
            __half obuf[8];
            #pragma unroll
            for (int j = 0; j < 8; j++) {
                int col = col0 + j;
                if (col < NTOK) {
                    float s = __half2float(hbuf[j]) * SCALE_F + rh[kh] + rw[kw];
                    obuf[j] = __float2half_rn(__expf(s - mj) * inv);
                } else {
                    obuf[j] = __float2half_rn(0.f);
                }
                if (++kw == WS) { kw = 0; kh++; }
            }
            *(float4*)(Srow + col0) = *(float4*)obuf;
        }
    }
}

// ================= batched PV GEMM ==
#define TBUFA (BM*LDW)
#define TBUFB (64*LDW)
#define PV_SMEM ((2*TBUFA + 2*TBUFB) * 4)

__global__ void __launch_bounds__(256, 2)
k_pv_gemm(const __half* __restrict__ S, const __half* __restrict__ Vt,
          __half* __restrict__ attno) {
    extern __shared__ float sm[];
    uint32_t* As = (uint32_t*)sm;
    uint32_t* Bs = As + 2*TBUFA;

    int tid = threadIdx.x, lane = tid & 31, wid = tid >> 5;
    int m0 = blockIdx.y * BM;
    int bz = blockIdx.z;
    int win = bz / HEADS, head = bz % HEADS;
    const __half* Pb = S + (long)bz * NTOK * SLD;
    const __half* Vb = Vt + (long)bz * HDIM * SLD;
    __half* Cb = attno + (long)win * NTOK * DIMC + head * HDIM;

    auto load_tile = [&](int kc, int bsel) {
        int k0 = kc * BKE;
        uint32_t* abuf = As + bsel * TBUFA;
        uint32_t* bbuf = Bs + bsel * TBUFB;
        #pragma unroll
        for (int it = 0; it < 2; it++) {
            int idx = tid + it * 256;
            int r = idx >> 2, c = idx & 3;
            int ar = m0 + r; ar = ar < NTOK ? ar : NTOK - 1;
            cp_async16(smem_u32(abuf + r * LDW + c * 4), Pb + (long)ar * SLD + k0 + c * 8);
        }
        {
            int r = tid >> 2, c = tid & 3;
            cp_async16(smem_u32(bbuf + r * LDW + c * 4), Vb + (long)r * SLD + k0 + c * 8);
        }
        CP_COMMIT();
    };

    int m8 = lane >> 3, r8 = lane & 7;
    uint32_t aoff = (uint32_t)((wid * 16 + (m8 & 1) * 8 + r8) * LDW + (m8 >> 1) * 4);
    uint32_t boff[4];
    #pragma unroll
    for (int p = 0; p < 4; p++)
        boff[p] = (uint32_t)((p * 16 + (m8 >> 1) * 8 + r8) * LDW + (m8 & 1) * 4);
    uint32_t a_base = smem_u32(As);
    uint32_t b_base = smem_u32(Bs);

    float acc[8][4];
    #pragma unroll
    for (int nt = 0; nt < 8; nt++)
        #pragma unroll
        for (int j = 0; j < 4; j++) acc[nt][j] = 0.f;

    const int NKC = SLD / BKE;
    load_tile(0, 0);
    for (int i = 0; i < NKC; i++) {
        int cur = i & 1;
        if (i + 1 < NKC) { load_tile(i + 1, cur ^ 1); CP_WAIT(1); }
        else             { CP_WAIT(0); }
        __syncthreads();
        uint32_t ab = a_base + cur * (TBUFA * 4);
        uint32_t bb = b_base + cur * (TBUFB * 4);
        #pragma unroll
        for (int ks = 0; ks < 2; ks++) {
            uint32_t af[4], bf[8][2];
            ldmx4(af[0], af[1], af[2], af[3], ab + (aoff + ks * 8) * 4);
            #pragma unroll
            for (int p = 0; p < 4; p++)
                ldmx4(bf[2*p][0], bf[2*p][1], bf[2*p+1][0], bf[2*p+1][1],
                      bb + (boff[p] + ks * 8) * 4);
            #pragma unroll
            for (int nt = 0; nt < 8; nt++)
                mma_f16(acc[nt], af, bf[nt]);
        }
        __syncthreads();
    }

    int r0 = m0 + wid * 16 + (lane >> 2), r1 = r0 + 8;
    int cb = 2 * (lane & 3);
    #pragma unroll
    for (int nt = 0; nt < 8; nt++) {
        int cc = cb + nt * 8;
        if (r0 < NTOK) *(__half2*)(Cb + (long)r0 * DIMC + cc) =
            __floats2half2_rn(acc[nt][0], acc[nt][1]);
        if (r1 < NTOK) *(__half2*)(Cb + (long)r1 * DIMC + cc) =
            __floats2half2_rn(acc[nt][2], acc[nt][3]);
    }
}

// ---------------- NCHW -> NHWC transpose ----------------
__global__ void k_transpose_in(const float* __restrict__ in, float* __restrict__ out) {
    __shared__ float tile[32][33];
    int b = blockIdx.z, c0 = blockIdx.y * 32, s0 = blockIdx.x * 32;
    const float* ib = in + (long)b * DIMC * 4096;
    float* ob = out + (long)b * 4096 * DIMC;
    int x = threadIdx.x, y = threadIdx.y;
    #pragma unroll
    for (int i = 0; i < 32; i += 8)
        tile[y + i][x] = ib[(long)(c0 + y + i) * 4096 + s0 + x];
    __syncthreads();
    #pragma unroll
    for (int i = 0; i < 32; i += 8)
        ob[(long)(s0 + y + i) * DIMC + c0 + x] = tile[x][y + i];
}

// ---------------- weight transpose to fp16 ----------------
__global__ void k_transpose_w(const float* __restrict__ in, __half* __restrict__ out,
                              int R, int C) {
    __shared__ float tile[32][33];
    int r0 = blockIdx.y * 32, c0 = blockIdx.x * 32;
    int x = threadIdx.x, y = threadIdx.y;
    #pragma unroll
    for (int i = 0; i < 32; i += 8)
        tile[y + i][x] = in[(long)(r0 + y + i) * C + c0 + x];
    __syncthreads();
    #pragma unroll
    for (int i = 0; i < 32; i += 8)
        out[(long)(c0 + y + i) * R + r0 + x] = __float2half_rn(tile[x][y + i]);
}

// ---------------- block reduction ----------------
__device__ __forceinline__ float block_sum_256(float v, float* red) {
    int tid = threadIdx.x;
    #pragma unroll
    for (int o = 16; o > 0; o >>= 1) v += __shfl_xor_sync(0xffffffffu, v, o);
    if ((tid & 31) == 0) red[tid >> 5] = v;
    __syncthreads();
    float r = 0.f;
    if (tid < 8) {
        r = red[tid];
        #pragma unroll
        for (int o = 4; o > 0; o >>= 1) r += __shfl_xor_sync(0xffu, r, o);
        if (tid == 0) red[0] = r;
    }
    __syncthreads();
    r = red[0];
    __syncthreads();
    return r;
}

// ---------------- LN1 + window partition (fp16 output) ----------------
__global__ void k_ln1_window(const float* __restrict__ xnhwc,
                             const float* __restrict__ w, const float* __restrict__ bs,
                             __half* __restrict__ xwin) {
    __shared__ float red[8];
    int idx = blockIdx.x;
    int win = idx / NTOK, t = idx % NTOK;
    int b = win / 25, wrem = win % 25;
    int gr = (wrem / 5) * WS + t / WS;
    int gc = (wrem % 5) * WS + t % WS;
    __half* orow = xwin + (long)idx * DIMC;
    int tid = threadIdx.x;
    if (gr >= IMGH || gc >= IMGW) {
        for (int c = tid; c < DIMC; c += 256) orow[c] = __float2half_rn(0.f);
        return;
    }
    const float* irow = xnhwc + ((long)b * 4096 + gr * IMGW + gc) * DIMC;
    float v[3], s = 0.f, s2 = 0.f;
    #pragma unroll
    for (int i = 0; i < 3; i++) { float x = irow[tid + i * 256]; v[i] = x; s += x; s2 += x * x; }
    float tot = block_sum_256(s, red);
    float tot2 = block_sum_256(s2, red);
    float mu = tot * (1.f / DIMC);
    float rstd = rsqrtf(tot2 * (1.f / DIMC) - mu * mu + EPS_F);
    #pragma unroll
    for (int i = 0; i < 3; i++) {
        int c = tid + i * 256;
        orow[c] = __float2half_rn((v[i] - mu) * rstd * w[c] + bs[c]);
    }
}

// ---------------- fused: window unpartition + residual + LN2 (proj fp16) ------
__global__ void k_scatter_ln2(const float* __restrict__ xnhwc, const __half* __restrict__ proj,
                              const float* __restrict__ w, const float* __restrict__ bs,
                              float* __restrict__ x1, __half* __restrict__ yln) {
    __shared__ float red[8];
    int row = blockIdx.x;
    int b = row >> 12, sp = row & 4095;
    int r = sp >> 6, cw = sp & 63;
    int win = b * 25 + (r / WS) * 5 + (cw / WS);
    int t = (r % WS) * WS + (cw % WS);
    const __half* prow = proj + ((long)win * NTOK + t) * DIMC;
    const float* xrow = xnhwc + (long)row * DIMC;
    float* orow = x1 + (long)row * DIMC;
    __half* lrow = yln + (long)row * DIMC;
    int tid = threadIdx.x;
    float v[3], s = 0.f, s2 = 0.f;
    #pragma unroll
    for (int i = 0; i < 3; i++) {
        int c = tid + i * 256;
        float x = xrow[c] + __half2float(prow[c]);
        orow[c] = x;
        v[i] = x; s += x; s2 += x * x;
    }
    float tot = block_sum_256(s, red);
    float tot2 = block_sum_256(s2, red);
    float mu = tot * (1.f / DIMC);
    float rstd = rsqrtf(tot2 * (1.f / DIMC) - mu * mu + EPS_F);
    #pragma unroll
    for (int i = 0; i < 3; i++) {
        int c = tid + i * 256;
        lrow[c] = __float2half_rn((v[i] - mu) * rstd * w[c] + bs[c]);
    }
}

// ---------------- final: y2 (already = x1 + mlp) NHWC -> NCHW ----------------
__global__ void k_final(const float* __restrict__ y2, float* __restrict__ out) {
    __shared__ float tile[32][33];
    int b = blockIdx.z, s0 = blockIdx.x * 32, c0 = blockIdx.y * 32;
    int x = threadIdx.x, y = threadIdx.y;
    #pragma unroll
    for (int i = 0; i < 32; i += 8) {
        long row = (long)b * 4096 + s0 + y + i;
        tile[y + i][x] = y2[row * DIMC + c0 + x];
    }
    __syncthreads();
    #pragma unroll
    for (int i = 0; i < 32; i += 8)
        out[((long)b * DIMC + c0 + y + i) * 4096 + s0 + x] = tile[x][y + i];
}

// ---------------- launcher ----------------
extern "C" void kernel_launch(void* const* d_in, const int* in_sizes, int n_in,
                              void* d_out, int out_size) {
    const float* hidden = (const float*)d_in[0];
    const float* ln1_w = (const float*)d_in[1];
    const float* ln1_b = (const float*)d_in[2];
    const float* qkv_w = (const float*)d_in[3];
    const float* qkv_b = (const float*)d_in[4];
    const float* proj_w = (const float*)d_in[5];
    const float* proj_b = (const float*)d_in[6];
    const float* relh = (const float*)d_in[7];
    const float* relw = (const float*)d_in[8];
    const float* ln2_w = (const float*)d_in[9];
    const float* ln2_b = (const float*)d_in[10];
    const float* fc1_w = (const float*)d_in[11];
    const float* fc1_b = (const float*)d_in[12];
    const float* fc2_w = (const float*)d_in[13];
    const float* fc2_b = (const float*)d_in[14];
    float* out = (float*)d_out;

    float *xnhwc, *x1, *y2;
    __half *xwin, *qkv, *S, *Vt, *attno, *proj, *yln, *h1, *qkvT, *projT, *fc1T, *fc2T;
    cudaGetSymbolAddress((void**)&xnhwc, g_xnhwc);
    cudaGetSymbolAddress((void**)&xwin, g_xwin);
    cudaGetSymbolAddress((void**)&qkv, g_qkv);
    cudaGetSymbolAddress((void**)&S, g_S);
    cudaGetSymbolAddress((void**)&Vt, g_Vt);
    cudaGetSymbolAddress((void**)&attno, g_attno);
    cudaGetSymbolAddress((void**)&proj, g_proj);
    cudaGetSymbolAddress((void**)&x1, g_x1);
    cudaGetSymbolAddress((void**)&yln, g_yln);
    cudaGetSymbolAddress((void**)&h1, g_h1);
    cudaGetSymbolAddress((void**)&y2, g_y2);
    cudaGetSymbolAddress((void**)&qkvT, g_qkvT);
    cudaGetSymbolAddress((void**)&projT, g_projT);
    cudaGetSymbolAddress((void**)&fc1T, g_fc1T);
    cudaGetSymbolAddress((void**)&fc2T, g_fc2T);

    cudaFuncSetAttribute(k_mma_gemm, cudaFuncAttributeMaxDynamicSharedMemorySize, GEMM_SMEM);
    cudaFuncSetAttribute(k_qk_gemm, cudaFuncAttributeMaxDynamicSharedMemorySize, QK_SMEM);
    cudaFuncSetAttribute(k_pv_gemm, cudaFuncAttributeMaxDynamicSharedMemorySize, PV_SMEM);

    dim3 tb(32, 8);
    // weight transposes
    k_transpose_w<<<dim3(3 * DIMC / 32, DIMC / 32), tb>>>(qkv_w, qkvT, DIMC, 3 * DIMC);
    k_transpose_w<<<dim3(DIMC / 32, DIMC / 32), tb>>>(proj_w, projT, DIMC, DIMC);
    k_transpose_w<<<dim3(MLPD / 32, DIMC / 32), tb>>>(fc1_w, fc1T, DIMC, MLPD);
    k_transpose_w<<<dim3(DIMC / 32, MLPD / 32), tb>>>(fc2_w, fc2T, MLPD, DIMC);

    // NCHW -> NHWC, LN1+window
    k_transpose_in<<<dim3(128, 24, BATCH), tb>>>(hidden, xnhwc);
    k_ln1_window<<<NROWS_WIN, 256>>>(xnhwc, ln1_w, ln1_b, xwin);
    // QKV GEMM -> fp16
    k_mma_gemm<<<dim3(3 * DIMC / 128, (NROWS_WIN + 127) / 128), 256, GEMM_SMEM>>>(
        xwin, qkvT, qkv_b, qkv, NROWS_WIN, 3 * DIMC, DIMC, 0, 1, nullptr);
    // attention
    k_vt<<<NBH, 256>>>(qkv, Vt);
    k_qk_gemm<<<dim3(2, 2, NBH), 256, QK_SMEM>>>(qkv, S);
    k_softmax<<<NBH, 392>>>(S, qkv, relh, relw);
    k_pv_gemm<<<dim3(1, 2, NBH), 256, PV_SMEM>>>(S, Vt, attno);
    // proj -> fp16
    k_mma_gemm<<<dim3(DIMC / 128, (NROWS_WIN + 127) / 128), 256, GEMM_SMEM>>>(
        attno, projT, proj_b, proj, NROWS_WIN, DIMC, DIMC, 0, 1, nullptr);
    // residual + LN2
    k_scatter_ln2<<<NROWS_IMG, 256>>>(xnhwc, proj, ln2_w, ln2_b, x1, yln);
    // FC1 + GELU -> fp16
    k_mma_gemm<<<dim3(MLPD / 128, NROWS_IMG / 128), 256, GEMM_SMEM>>>(
        yln, fc1T, fc1_b, h1, NROWS_IMG, MLPD, DIMC, 1, 1, nullptr);
    // FC2 -> fp32 with fused x1 residual
    k_mma_gemm<<<dim3(DIMC / 128, NROWS_IMG / 128), 256, GEMM_SMEM>>>(
        h1, fc2T, fc2_b, y2, NROWS_IMG, DIMC, MLPD, 0, 0, x1);
    // NHWC -> NCHW
    k_final<<<dim3(128, 24, BATCH), tb>>>(y2, out);
}

// round 16
// speedup vs baseline: 1.5514x; 1.0070x over previous
#include <cuda_runtime.h>
#include <cuda_fp16.h>
#include <math.h>
#include <stdint.h>

// ---------------- problem constants ----------------
#define DIMC    768
#define HEADS   12
#define HDIM    64
#define WS      14
#define NTOK    196
#define MLPD    3072
#define BATCH   4
#define IMGH    64
#define IMGW    64
#define NWIN    100
#define NROWS_WIN (NWIN*NTOK)
#define NROWS_IMG (BATCH*IMGH*IMGW)
#define NBH     (NWIN*HEADS)
#define SLD     224
#define SCALE_F 0.125f
#define EPS_F   1e-6f

// ---------------- scratch ----------------
__device__ float   g_xnhwc[BATCH*IMGH*IMGW*DIMC];
__device__ __half  g_xwin [NROWS_WIN*DIMC];
__device__ __half  g_qkv  [NROWS_WIN*3*DIMC];
__device__ __half  g_S    [(long)NBH*NTOK*SLD];
__device__ __half  g_Vt   [(long)NBH*HDIM*SLD];
__device__ __half  g_attno[NROWS_WIN*DIMC];
__device__ __half  g_proj [NROWS_WIN*DIMC];
__device__ float   g_x1   [NROWS_IMG*DIMC];
__device__ __half  g_yln  [NROWS_IMG*DIMC];
__device__ __half  g_h1   [NROWS_IMG*MLPD];
__device__ float   g_y2   [NROWS_IMG*DIMC];
__device__ __half  g_qkvT [3*DIMC*DIMC];
__device__ __half  g_projT[DIMC*DIMC];
__device__ __half  g_fc1T [MLPD*DIMC];
__device__ __half  g_fc2T [DIMC*MLPD];

// ================= helpers =================
__device__ __forceinline__ uint32_t smem_u32(const void* p) {
    uint32_t a;
    asm("{ .reg .u64 t; cvta.to.shared.u64 t, %1; cvt.u32.u64 %0, t; }" : "=r"(a) : "l"(p));
    return a;
}
__device__ __forceinline__ void cp_async16(uint32_t dst, const void* src) {
    asm volatile("cp.async.cg.shared.global [%0], [%1], 16;" :: "r"(dst), "l"(src));
}
#define CP_COMMIT() asm volatile("cp.async.commit_group;" ::: "memory")
#define CP_WAIT(n)  asm volatile("cp.async.wait_group %0;" :: "n"(n) : "memory")

__device__ __forceinline__ void mma_f16(float* c, const uint32_t* a, const uint32_t* b) {
    asm volatile(
        "mma.sync.aligned.m16n8k16.row.col.f32.f16.f16.f32 "
        "{%0,%1,%2,%3}, {%4,%5,%6,%7}, {%8,%9}, {%0,%1,%2,%3};"
        : "+f"(c[0]), "+f"(c[1]), "+f"(c[2]), "+f"(c[3])
        : "r"(a[0]), "r"(a[1]), "r"(a[2]), "r"(a[3]), "r"(b[0]), "r"(b[1]));
}
__device__ __forceinline__ void ldmx4(uint32_t& r0, uint32_t& r1, uint32_t& r2, uint32_t& r3,
                                      uint32_t addr) {
    asm volatile("ldmatrix.sync.aligned.m8n8.x4.shared.b16 {%0,%1,%2,%3}, [%4];"
        : "=r"(r0), "=r"(r1), "=r"(r2), "=r"(r3) : "r"(addr));
}

// ================= fp16 mma.sync GEMM: BKE=64 K-chunks, optional residual =====
#define BM 128
#define BN 128
#define BKE2 64
#define LDW2 36
#define TBUF2 (BM*LDW2)
#define GEMM_SMEM ((4*TBUF2 + 128) * 4)

__global__ void __launch_bounds__(256, 2)
k_mma_gemm(const __half* __restrict__ A, const __half* __restrict__ Bt,
           const float* __restrict__ bias, void* __restrict__ Cout,
           int M, int N, int K, int act, int outf16,
           const float* __restrict__ resid) {
    extern __shared__ float sm[];
    uint32_t* As = (uint32_t*)sm;
    uint32_t* Bs = As + 2*TBUF2;
    float* sbias = sm + 4*TBUF2;

    int tid = threadIdx.x, lane = tid & 31, wid = tid >> 5;
    int wm = wid >> 1, wn = wid & 1;
    int m0 = blockIdx.y * BM, n0 = blockIdx.x * BN;

    if (tid < 128) sbias[tid] = bias[n0 + tid];

    auto load_tile = [&](int kc, int bsel) {
        int k0 = kc * BKE2;
        uint32_t* abuf = As + bsel * TBUF2;
        uint32_t* bbuf = Bs + bsel * TBUF2;
        #pragma unroll
        for (int it = 0; it < 4; it++) {
            int idx = tid + it * 256;
            int r = idx >> 3, c = idx & 7;
            int ar = m0 + r;
            const __half* asrc = A + (long)(ar < M ? ar : M - 1) * K + k0 + c * 8;
            cp_async16(smem_u32(abuf + r * LDW2 + c * 4), asrc);
            const __half* bsrc = Bt + (long)(n0 + r) * K + k0 + c * 8;
            cp_async16(smem_u32(bbuf + r * LDW2 + c * 4), bsrc);
        }
        CP_COMMIT();
    };

    int m8 = lane >> 3, r8 = lane & 7;
    uint32_t aoff[2], boff[4];
    #pragma unroll
    for (int mt = 0; mt < 2; mt++)
        aoff[mt] = (uint32_t)((wm * 32 + mt * 16 + (m8 & 1) * 8 + r8) * LDW2 + (m8 >> 1) * 4);
    #pragma unroll
    for (int p = 0; p < 4; p++)
        boff[p] = (uint32_t)((wn * 64 + p * 16 + (m8 >> 1) * 8 + r8) * LDW2 + (m8 & 1) * 4);
    uint32_t a_base = smem_u32(As);
    uint32_t b_base = smem_u32(Bs);

    float acc[2][8][4];
    #pragma unroll
    for (int mt = 0; mt < 2; mt++)
        #pragma unroll
        for (int nt = 0; nt < 8; nt++)
            #pragma unroll
            for (int j = 0; j < 4; j++) acc[mt][nt][j] = 0.f;

    const int NKC = K / BKE2;
    load_tile(0, 0);
    for (int i = 0; i < NKC; i++) {
        int cur = i & 1;
        if (i + 1 < NKC) { load_tile(i + 1, cur ^ 1); CP_WAIT(1); }
        else             { CP_WAIT(0); }
        __syncthreads();
        uint32_t ab = a_base + cur * (TBUF2 * 4);
        uint32_t bb = b_base + cur * (TBUF2 * 4);
        #pragma unroll
        for (int ks = 0; ks < 4; ks++) {
            uint32_t af[2][4], bf[8][2];
            #pragma unroll
            for (int mt = 0; mt < 2; mt++)
                ldmx4(af[mt][0], af[mt][1], af[mt][2], af[mt][3],
                      ab + (aoff[mt] + ks * 8) * 4);
            #pragma unroll
            for (int p = 0; p < 4; p++)
                ldmx4(bf[2*p][0], bf[2*p][1], bf[2*p+1][0], bf[2*p+1][1],
                      bb + (boff[p] + ks * 8) * 4);
            #pragma unroll
            for (int mt = 0; mt < 2; mt++)
                #pragma unroll
                for (int nt = 0; nt < 8; nt++)
                    mma_f16(acc[mt][nt], af[mt], bf[nt]);
        }
        __syncthreads();
    }

    int rb = m0 + wm * 32 + (lane >> 2);
    int cb = wn * 64 + 2 * (lane & 3);
    #pragma unroll
    for (int mt = 0; mt < 2; mt++) {
        int r0 = rb + mt * 16, r1 = r0 + 8;
        #pragma unroll
        for (int nt = 0; nt < 8; nt++) {
            int cc = cb + nt * 8;
            float v0 = acc[mt][nt][0] + sbias[cc];
            float v1 = acc[mt][nt][1] + sbias[cc + 1];
            float v2 = acc[mt][nt][2] + sbias[cc];
            float v3 = acc[mt][nt][3] + sbias[cc + 1];
            if (act == 1) {
                v0 = 0.5f * v0 * (1.0f + erff(v0 * 0.70710678118654752f));
                v1 = 0.5f * v1 * (1.0f + erff(v1 * 0.70710678118654752f));
                v2 = 0.5f * v2 * (1.0f + erff(v2 * 0.70710678118654752f));
                v3 = 0.5f * v3 * (1.0f + erff(v3 * 0.70710678118654752f));
            }
            if (resid) {
                if (r0 < M) {
                    float2 rr = *(const float2*)(resid + (long)r0 * N + n0 + cc);
                    v0 += rr.x; v1 += rr.y;
                }
                if (r1 < M) {
                    float2 rr = *(const float2*)(resid + (long)r1 * N + n0 + cc);
                    v2 += rr.x; v3 += rr.y;
                }
            }
            if (outf16) {
                __half* C = (__half*)Cout;
                if (r0 < M) *(__half2*)(C + (long)r0 * N + n0 + cc) = __floats2half2_rn(v0, v1);
                if (r1 < M) *(__half2*)(C + (long)r1 * N + n0 + cc) = __floats2half2_rn(v2, v3);
            } else {
                float* C = (float*)Cout;
                if (r0 < M) *(float2*)(C + (long)r0 * N + n0 + cc) = make_float2(v0, v1);
                if (r1 < M) *(float2*)(C + (long)r1 * N + n0 + cc) = make_float2(v2, v3);
            }
        }
    }
}

// ================= attention kernels (BKE=32 / LDW=20) ===========
#define BKE 32
#define LDW 20
#define TBUF (BM*LDW)
#define QK_SMEM ((4*TBUF + 128) * 4)

__global__ void __launch_bounds__(256, 2)
k_qk_gemm(const __half* __restrict__ qkv, __half* __restrict__ S) {
    extern __shared__ float sm[];
    uint32_t* As = (uint32_t*)sm;
    uint32_t* Bs = As + 2*TBUF;

    int tid = threadIdx.x, lane = tid & 31, wid = tid >> 5;
    int wm = wid >> 1, wn = wid & 1;
    int m0 = blockIdx.y * BM, n0 = blockIdx.x * BN;
    int bz = blockIdx.z;
    int win = bz / HEADS, head = bz % HEADS;
    const __half* Qb = qkv + (long)win * NTOK * (3 * DIMC) + head * HDIM;
    const __half* Kb = Qb + DIMC;
    __half* Sb = S + (long)bz * NTOK * SLD;

    auto load_tile = [&](int kc, int bsel) {
        int k0 = kc * BKE;
        uint32_t* abuf = As + bsel * TBUF;
        uint32_t* bbuf = Bs + bsel * TBUF;
        #pragma unroll
        for (int it = 0; it < 2; it++) {
            int idx = tid + it * 256;
            int r = idx >> 2, c = idx & 3;
            int ar = m0 + r; ar = ar < NTOK ? ar : NTOK - 1;
            cp_async16(smem_u32(abuf + r * LDW + c * 4), Qb + (long)ar * (3 * DIMC) + k0 + c * 8);
            int br = n0 + r; br = br < NTOK ? br : NTOK - 1;
            cp_async16(smem_u32(bbuf + r * LDW + c * 4), Kb + (long)br * (3 * DIMC) + k0 + c * 8);
        }
        CP_COMMIT();
    };

    int m8 = lane >> 3, r8 = lane & 7;
    uint32_t aoff[2], boff[4];
    #pragma unroll
    for (int mt = 0; mt < 2; mt++)
        aoff[mt] = (uint32_t)((wm * 32 + mt * 16 + (m8 & 1) * 8 + r8) * LDW + (m8 >> 1) * 4);
    #pragma unroll
    for (int p = 0; p < 4; p++)
        boff[p] = (uint32_t)((wn * 64 + p * 16 + (m8 >> 1) * 8 + r8) * LDW + (m8 & 1) * 4);
    uint32_t a_base = smem_u32(As);
    uint32_t b_base = smem_u32(Bs);

    float acc[2][8][4];
    #pragma unroll
    for (int mt = 0; mt < 2; mt++)
        #pragma unroll
        for (int nt = 0; nt < 8; nt++)
            #pragma unroll
            for (int j = 0; j < 4; j++) acc[mt][nt][j] = 0.f;

    load_tile(0, 0);
    #pragma unroll
    for (int i = 0; i < 2; i++) {
        int cur = i & 1;
        if (i + 1 < 2) { load_tile(1, 1); CP_WAIT(1); }
        else           { CP_WAIT(0); }
        __syncthreads();
        uint32_t ab = a_base + cur * (TBUF * 4);
        uint32_t bb = b_base + cur * (TBUF * 4);
        #pragma unroll
        for (int ks = 0; ks < 2; ks++) {
            uint32_t af[2][4], bf[8][2];
            #pragma unroll
            for (int mt = 0; mt < 2; mt++)
                ldmx4(af[mt][0], af[mt][1], af[mt][2], af[mt][3],
                      ab + (aoff[mt] + ks * 8) * 4);
            #pragma unroll
            for (int p = 0; p < 4; p++)
                ldmx4(bf[2*p][0], bf[2*p][1], bf[2*p+1][0], bf[2*p+1][1],
                      bb + (boff[p] + ks * 8) * 4);
            #pragma unroll
            for (int mt = 0; mt < 2; mt++)
                #pragma unroll
                for (int nt = 0; nt < 8; nt++)
                    mma_f16(acc[mt][nt], af[mt], bf[nt]);
        }
        __syncthreads();
    }

    int rb = m0 + wm * 32 + (lane >> 2);
    int cb = wn * 64 + 2 * (lane & 3);
    #pragma unroll
    for (int mt = 0; mt < 2; mt++) {
        int r0 = rb + mt * 16, r1 = r0 + 8;
        #pragma unroll
        for (int nt = 0; nt < 8; nt++) {
            int cc = n0 + cb + nt * 8;
            if (cc + 1 < SLD) {
                if (r0 < NTOK) *(__half2*)(Sb + (long)r0 * SLD + cc) =
                    __floats2half2_rn(acc[mt][nt][0], acc[mt][nt][1]);
                if (r1 < NTOK) *(__half2*)(Sb + (long)r1 * SLD + cc) =
                    __floats2half2_rn(acc[mt][nt][2], acc[mt][nt][3]);
            }
        }
    }
}

// ================= V transpose prep (vectorized output) ======
#define LDV 66
__global__ void __launch_bounds__(256)
k_vt(const __half* __restrict__ qkv, __half* __restrict__ Vt) {
    __shared__ __half smv[NTOK * LDV];
    int bz = blockIdx.x;
    int win = bz / HEADS, head = bz % HEADS;
    const __half* Vb = qkv + (long)win * NTOK * (3 * DIMC) + 2 * DIMC + head * HDIM;
    int tid = threadIdx.x;
    for (int i = tid; i < NTOK * HDIM; i += 256) {
        int t = i >> 6, d = i & 63;
        smv[t * LDV + d] = Vb[(long)t * (3 * DIMC) + d];
    }
    __syncthreads();
    __half* out = Vt + (long)bz * HDIM * SLD;
    for (int o8 = tid; o8 < HDIM * SLD / 8; o8 += 256) {
        int o = o8 * 8;
        int n = o / SLD, k = o - n * SLD;
        __half buf[8];
        #pragma unroll
        for (int j = 0; j < 8; j++)
            buf[j] = (k + j < NTOK) ? smv[(k + j) * LDV + n] : __float2half_rn(0.f);
        *(float4*)(out + o) = *(float4*)buf;
    }
}

// ================= softmax + rel-pos bias (vectorized S access) ==============
#define RELSTRIDE 65
__global__ void __launch_bounds__(392, 2)
k_softmax(__half* __restrict__ S, const __half* __restrict__ qkv,
          const float* __restrict__ rel_pos_h, const float* __restrict__ rel_pos_w) {
    __shared__ float RH[27 * RELSTRIDE];
    __shared__ float RW[27 * RELSTRIDE];
    int bz = blockIdx.x;
    int win = bz / HEADS, head = bz % HEADS;
    int tid = threadIdx.x;
    for (int i = tid; i < 27 * HDIM; i += 392) {
        int r = i >> 6, d = i & 63;
        RH[r * RELSTRIDE + d] = rel_pos_h[i];
        RW[r * RELSTRIDE + d] = rel_pos_w[i];
    }
    __syncthreads();

    int q = tid >> 1, half = tid & 1;
    int qh = q / WS, qw = q % WS;
    unsigned pmask = ((tid & ~31) == 384) ? 0x000000ffu : 0xffffffffu;

    float qv[32];
    {
        const __half* qp = qkv + (long)win * NTOK * (3 * DIMC) + (long)q * (3 * DIMC)
                           + head * HDIM + half * 32;
        #pragma unroll
        for (int d = 0; d < 32; d += 2) {
            float2 f = __half22float2(*(const __half2*)(qp + d));
            qv[d] = f.x; qv[d + 1] = f.y;
        }
    }

    float rh[WS], rw[WS];
    #pragma unroll
    for (int kh = 0; kh < WS; kh++) {
        const float* ph = &RH[(qh - kh + WS - 1) * RELSTRIDE + half * 32];
        const float* pw = &RW[(qw - kh + WS - 1) * RELSTRIDE + half * 32];
        float sh = 0.f, sw = 0.f;
        #pragma unroll
        for (int d = 0; d < 32; d++) { sh = fmaf(qv[d], ph[d], sh); sw = fmaf(qv[d], pw[d], sw); }
        sh += __shfl_xor_sync(pmask, sh, 1);
        sw += __shfl_xor_sync(pmask, sw, 1);
        rh[kh] = sh; rw[kh] = sw;
    }

    __half* Srow = S + (long)bz * NTOK * SLD + (long)q * SLD;
    float m = -1e30f, l = 0.f;
    {
        int kh = 8 * half, kw = 0;
        #pragma unroll
        for (int c8 = 0; c8 < 14; c8++) {
            int col0 = half * 112 + c8 * 8;
            __half hbuf[8];
            *(float4*)hbuf = *(const float4*)(Srow + col0);
            #pragma unroll
            for (int j = 0; j < 8; j++) {
                int col = col0 + j;
                if (col < NTOK) {
                    float s = __half2float(hbuf[j]) * SCALE_F + rh[kh] + rw[kw];
                    if (s > m) { l = l * __expf(m - s) + 1.f; m = s; }
                    else       { l += __expf(s - m); }
                }
                if (++kw == WS) { kw = 0; kh++; }
            }
        }
    }
    float mo = __shfl_xor_sync(pmask, m, 1);
    float lo = __shfl_xor_sync(pmask, l, 1);
    float mj = fmaxf(m, mo);
    float lj = l * __expf(m - mj) + lo * __expf(mo - mj);
    float inv = 1.f / lj;
    {
        int kh = 8 * half, kw = 0;
        #pragma unroll
        for (int c8 = 0; c8 < 14; c8++) {
            int col0 = half * 112 + c8 * 8;
            __half hbuf[8];
            *(float4*)hbuf = *(const float4*)(Srow + col0);
            __half obuf[8];
            #pragma unroll
            for (int j = 0; j < 8; j++) {
                int col = col0 + j;
                if (col < NTOK) {
                    float s = __half2float(hbuf[j]) * SCALE_F + rh[kh] + rw[kw];
                    obuf[j] = __float2half_rn(__expf(s - mj) * inv);
                } else {
                    obuf[j] = __float2half_rn(0.f);
                }
                if (++kw == WS) { kw = 0; kh++; }
            }
            *(float4*)(Srow + col0) = *(float4*)obuf;
        }
    }
}

// ================= batched PV GEMM ==
#define TBUFA (BM*LDW)
#define TBUFB (64*LDW)
#define PV_SMEM ((2*TBUFA + 2*TBUFB) * 4)

__global__ void __launch_bounds__(256, 2)
k_pv_gemm(const __half* __restrict__ S, const __half* __restrict__ Vt,
          __half* __restrict__ attno) {
    extern __shared__ float sm[];
    uint32_t* As = (uint32_t*)sm;
    uint32_t* Bs = As + 2*TBUFA;

    int tid = threadIdx.x, lane = tid & 31, wid = tid >> 5;
    int m0 = blockIdx.y * BM;
    int bz = blockIdx.z;
    int win = bz / HEADS, head = bz % HEADS;
    const __half* Pb = S + (long)bz * NTOK * SLD;
    const __half* Vb = Vt + (long)bz * HDIM * SLD;
    __half* Cb = attno + (long)win * NTOK * DIMC + head * HDIM;

    auto load_tile = [&](int kc, int bsel) {
        int k0 = kc * BKE;
        uint32_t* abuf = As + bsel * TBUFA;
        uint32_t* bbuf = Bs + bsel * TBUFB;
        #pragma unroll
        for (int it = 0; it < 2; it++) {
            int idx = tid + it * 256;
            int r = idx >> 2, c = idx & 3;
            int ar = m0 + r; ar = ar < NTOK ? ar : NTOK - 1;
            cp_async16(smem_u32(abuf + r * LDW + c * 4), Pb + (long)ar * SLD + k0 + c * 8);
        }
        {
            int r = tid >> 2, c = tid & 3;
            cp_async16(smem_u32(bbuf + r * LDW + c * 4), Vb + (long)r * SLD + k0 + c * 8);
        }
        CP_COMMIT();
    };

    int m8 = lane >> 3, r8 = lane & 7;
    uint32_t aoff = (uint32_t)((wid * 16 + (m8 & 1) * 8 + r8) * LDW + (m8 >> 1) * 4);
    uint32_t boff[4];
    #pragma unroll
    for (int p = 0; p < 4; p++)
        boff[p] = (uint32_t)((p * 16 + (m8 >> 1) * 8 + r8) * LDW + (m8 & 1) * 4);
    uint32_t a_base = smem_u32(As);
    uint32_t b_base = smem_u32(Bs);

    float acc[8][4];
    #pragma unroll
    for (int nt = 0; nt < 8; nt++)
        #pragma unroll
        for (int j = 0; j < 4; j++) acc[nt][j] = 0.f;

    const int NKC = SLD / BKE;
    load_tile(0, 0);
    for (int i = 0; i < NKC; i++) {
        int cur = i & 1;
        if (i + 1 < NKC) { load_tile(i + 1, cur ^ 1); CP_WAIT(1); }
        else             { CP_WAIT(0); }
        __syncthreads();
        uint32_t ab = a_base + cur * (TBUFA * 4);
        uint32_t bb = b_base + cur * (TBUFB * 4);
        #pragma unroll
        for (int ks = 0; ks < 2; ks++) {
            uint32_t af[4], bf[8][2];
            ldmx4(af[0], af[1], af[2], af[3], ab + (aoff + ks * 8) * 4);
            #pragma unroll
            for (int p = 0; p < 4; p++)
                ldmx4(bf[2*p][0], bf[2*p][1], bf[2*p+1][0], bf[2*p+1][1],
                      bb + (boff[p] + ks * 8) * 4);
            #pragma unroll
            for (int nt = 0; nt < 8; nt++)
                mma_f16(acc[nt], af, bf[nt]);
        }
        __syncthreads();
    }

    int r0 = m0 + wid * 16 + (lane >> 2), r1 = r0 + 8;
    int cb = 2 * (lane & 3);
    #pragma unroll
    for (int nt = 0; nt < 8; nt++) {
        int cc = cb + nt * 8;
        if (r0 < NTOK) *(__half2*)(Cb + (long)r0 * DIMC + cc) =
            __floats2half2_rn(acc[nt][0], acc[nt][1]);
        if (r1 < NTOK) *(__half2*)(Cb + (long)r1 * DIMC + cc) =
            __floats2half2_rn(acc[nt][2], acc[nt][3]);
    }
}

// ---------------- NCHW -> NHWC transpose ----------------
__global__ void k_transpose_in(const float* __restrict__ in, float* __restrict__ out) {
    __shared__ float tile[32][33];
    int b = blockIdx.z, c0 = blockIdx.y * 32, s0 = blockIdx.x * 32;
    const float* ib = in + (long)b * DIMC * 4096;
    float* ob = out + (long)b * 4096 * DIMC;
    int x = threadIdx.x, y = threadIdx.y;
    #pragma unroll
    for (int i = 0; i < 32; i += 8)
        tile[y + i][x] = ib[(long)(c0 + y + i) * 4096 + s0 + x];
    __syncthreads();
    #pragma unroll
    for (int i = 0; i < 32; i += 8)
        ob[(long)(s0 + y + i) * DIMC + c0 + x] = tile[x][y + i];
}

// ---------------- weight transpose to fp16 ----------------
__global__ void k_transpose_w(const float* __restrict__ in, __half* __restrict__ out,
                              int R, int C) {
    __shared__ float tile[32][33];
    int r0 = blockIdx.y * 32, c0 = blockIdx.x * 32;
    int x = threadIdx.x, y = threadIdx.y;
    #pragma unroll
    for (int i = 0; i < 32; i += 8)
        tile[y + i][x] = in[(long)(r0 + y + i) * C + c0 + x];
    __syncthreads();
    #pragma unroll
    for (int i = 0; i < 32; i += 8)
        out[(long)(c0 + y + i) * R + r0 + x] = __float2half_rn(tile[x][y + i]);
}

// ---------------- block reduction (192 threads, 6 warps) ----------------
__device__ __forceinline__ float block_sum_192(float v, float* red) {
    int tid = threadIdx.x;
    #pragma unroll
    for (int o = 16; o > 0; o >>= 1) v += __shfl_xor_sync(0xffffffffu, v, o);
    if ((tid & 31) == 0) red[tid >> 5] = v;
    __syncthreads();
    float r = 0.f;
    if (tid < 8) {
        r = (tid < 6) ? red[tid] : 0.f;
        #pragma unroll
        for (int o = 4; o > 0; o >>= 1) r += __shfl_xor_sync(0xffu, r, o);
        if (tid == 0) red[0] = r;
    }
    __syncthreads();
    r = red[0];
    __syncthreads();
    return r;
}

// ---------------- LN1 + window partition (vectorized, 192 threads) ------------
__global__ void __launch_bounds__(192)
k_ln1_window(const float* __restrict__ xnhwc,
             const float* __restrict__ w, const float* __restrict__ bs,
             __half* __restrict__ xwin) {
    __shared__ float red[8];
    int idx = blockIdx.x;
    int win = idx / NTOK, t = idx % NTOK;
    int b = win / 25, wrem = win % 25;
    int gr = (wrem / 5) * WS + t / WS;
    int gc = (wrem % 5) * WS + t % WS;
    __half* orow = xwin + (long)idx * DIMC;
    int tid = threadIdx.x;
    int c4 = tid * 4;
    if (gr >= IMGH || gc >= IMGW) {
        __half z[4] = {__float2half_rn(0.f), __float2half_rn(0.f),
                       __float2half_rn(0.f), __float2half_rn(0.f)};
        *(uint2*)(orow + c4) = *(uint2*)z;
        return;
    }
    const float* irow = xnhwc + ((long)b * 4096 + gr * IMGW + gc) * DIMC;
    float4 v = *(const float4*)(irow + c4);
    float s = v.x + v.y + v.z + v.w;
    float s2 = v.x * v.x + v.y * v.y + v.z * v.z + v.w * v.w;
    float tot = block_sum_192(s, red);
    float tot2 = block_sum_192(s2, red);
    float mu = tot * (1.f / DIMC);
    float rstd = rsqrtf(tot2 * (1.f / DIMC) - mu * mu + EPS_F);
    float4 wv = *(const float4*)(w + c4);
    float4 bv = *(const float4*)(bs + c4);
    __half o[4];
    o[0] = __float2half_rn((v.x - mu) * rstd * wv.x + bv.x);
    o[1] = __float2half_rn((v.y - mu) * rstd * wv.y + bv.y);
    o[2] = __float2half_rn((v.z - mu) * rstd * wv.z + bv.z);
    o[3] = __float2half_rn((v.w - mu) * rstd * wv.w + bv.w);
    *(uint2*)(orow + c4) = *(uint2*)o;
}

// ---------------- fused: unpartition + residual + LN2 (vectorized, 192 thr) ---
__global__ void __launch_bounds__(192)
k_scatter_ln2(const float* __restrict__ xnhwc, const __half* __restrict__ proj,
              const float* __restrict__ w, const float* __restrict__ bs,
              float* __restrict__ x1, __half* __restrict__ yln) {
    __shared__ float red[8];
    int row = blockIdx.x;
    int b = row >> 12, sp = row & 4095;
    int r = sp >> 6, cw = sp & 63;
    int win = b * 25 + (r / WS) * 5 + (cw / WS);
    int t = (r % WS) * WS + (cw % WS);
    const __half* prow = proj + ((long)win * NTOK + t) * DIMC;
    const float* xrow = xnhwc + (long)row * DIMC;
    float* orow = x1 + (long)row * DIMC;
    __half* lrow = yln + (long)row * DIMC;
    int tid = threadIdx.x;
    int c4 = tid * 4;
    float4 xv = *(const float4*)(xrow + c4);
    __half pb[4];
    *(uint2*)pb = *(const uint2*)(prow + c4);
    float4 v;
    v.x = xv.x + __half2float(pb[0]);
    v.y = xv.y + __half2float(pb[1]);
    v.z = xv.z + __half2float(pb[2]);
    v.w = xv.w + __half2float(pb[3]);
    *(float4*)(orow + c4) = v;
    float s = v.x + v.y + v.z + v.w;
    float s2 = v.x * v.x + v.y * v.y + v.z * v.z + v.w * v.w;
    float tot = block_sum_192(s, red);
    float tot2 = block_sum_192(s2, red);
    float mu = tot * (1.f / DIMC);
    float rstd = rsqrtf(tot2 * (1.f / DIMC) - mu * mu + EPS_F);
    float4 wv = *(const float4*)(w + c4);
    float4 bv = *(const float4*)(bs + c4);
    __half o[4];
    o[0] = __float2half_rn((v.x - mu) * rstd * wv.x + bv.x);
    o[1] = __float2half_rn((v.y - mu) * rstd * wv.y + bv.y);
    o[2] = __float2half_rn((v.z - mu) * rstd * wv.z + bv.z);
    o[3] = __float2half_rn((v.w - mu) * rstd * wv.w + bv.w);
    *(uint2*)(lrow + c4) = *(uint2*)o;
}

// ---------------- final: y2 NHWC -> NCHW ----------------
__global__ void k_final(const float* __restrict__ y2, float* __restrict__ out) {
    __shared__ float tile[32][33];
    int b = blockIdx.z, s0 = blockIdx.x * 32, c0 = blockIdx.y * 32;
    int x = threadIdx.x, y = threadIdx.y;
    #pragma unroll
    for (int i = 0; i < 32; i += 8) {
        long row = (long)b * 4096 + s0 + y + i;
        tile[y + i][x] = y2[row * DIMC + c0 + x];
    }
    __syncthreads();
    #pragma unroll
    for (int i = 0; i < 32; i += 8)
        out[((long)b * DIMC + c0 + y + i) * 4096 + s0 + x] = tile[x][y + i];
}

// ---------------- launcher ----------------
extern "C" void kernel_launch(void* const* d_in, const int* in_sizes, int n_in,
                              void* d_out, int out_size) {
    const float* hidden = (const float*)d_in[0];
    const float* ln1_w = (const float*)d_in[1];
    const float* ln1_b = (const float*)d_in[2];
    const float* qkv_w = (const float*)d_in[3];
    const float* qkv_b = (const float*)d_in[4];
    const float* proj_w = (const float*)d_in[5];
    const float* proj_b = (const float*)d_in[6];
    const float* relh = (const float*)d_in[7];
    const float* relw = (const float*)d_in[8];
    const float* ln2_w = (const float*)d_in[9];
    const float* ln2_b = (const float*)d_in[10];
    const float* fc1_w = (const float*)d_in[11];
    const float* fc1_b = (const float*)d_in[12];
    const float* fc2_w = (const float*)d_in[13];
    const float* fc2_b = (const float*)d_in[14];
    float* out = (float*)d_out;

    float *xnhwc, *x1, *y2;
    __half *xwin, *qkv, *S, *Vt, *attno, *proj, *yln, *h1, *qkvT, *projT, *fc1T, *fc2T;
    cudaGetSymbolAddress((void**)&xnhwc, g_xnhwc);
    cudaGetSymbolAddress((void**)&xwin, g_xwin);
    cudaGetSymbolAddress((void**)&qkv, g_qkv);
    cudaGetSymbolAddress((void**)&S, g_S);
    cudaGetSymbolAddress((void**)&Vt, g_Vt);
    cudaGetSymbolAddress((void**)&attno, g_attno);
    cudaGetSymbolAddress((void**)&proj, g_proj);
    cudaGetSymbolAddress((void**)&x1, g_x1);
    cudaGetSymbolAddress((void**)&yln, g_yln);
    cudaGetSymbolAddress((void**)&h1, g_h1);
    cudaGetSymbolAddress((void**)&y2, g_y2);
    cudaGetSymbolAddress((void**)&qkvT, g_qkvT);
    cudaGetSymbolAddress((void**)&projT, g_projT);
    cudaGetSymbolAddress((void**)&fc1T, g_fc1T);
    cudaGetSymbolAddress((void**)&fc2T, g_fc2T);

    cudaFuncSetAttribute(k_mma_gemm, cudaFuncAttributeMaxDynamicSharedMemorySize, GEMM_SMEM);
    cudaFuncSetAttribute(k_qk_gemm, cudaFuncAttributeMaxDynamicSharedMemorySize, QK_SMEM);
    cudaFuncSetAttribute(k_pv_gemm, cudaFuncAttributeMaxDynamicSharedMemorySize, PV_SMEM);

    dim3 tb(32, 8);
    // weight transposes
    k_transpose_w<<<dim3(3 * DIMC / 32, DIMC / 32), tb>>>(qkv_w, qkvT, DIMC, 3 * DIMC);
    k_transpose_w<<<dim3(DIMC / 32, DIMC / 32), tb>>>(proj_w, projT, DIMC, DIMC);
    k_transpose_w<<<dim3(MLPD / 32, DIMC / 32), tb>>>(fc1_w, fc1T, DIMC, MLPD);
    k_transpose_w<<<dim3(DIMC / 32, MLPD / 32), tb>>>(fc2_w, fc2T, MLPD, DIMC);

    // NCHW -> NHWC, LN1+window
    k_transpose_in<<<dim3(128, 24, BATCH), tb>>>(hidden, xnhwc);
    k_ln1_window<<<NROWS_WIN, 192>>>(xnhwc, ln1_w, ln1_b, xwin);
    // QKV GEMM -> fp16
    k_mma_gemm<<<dim3(3 * DIMC / 128, (NROWS_WIN + 127) / 128), 256, GEMM_SMEM>>>(
        xwin, qkvT, qkv_b, qkv, NROWS_WIN, 3 * DIMC, DIMC, 0, 1, nullptr);
    // attention
    k_vt<<<NBH, 256>>>(qkv, Vt);
    k_qk_gemm<<<dim3(2, 2, NBH), 256, QK_SMEM>>>(qkv, S);
    k_softmax<<<NBH, 392>>>(S, qkv, relh, relw);
    k_pv_gemm<<<dim3(1, 2, NBH), 256, PV_SMEM>>>(S, Vt, attno);
    // proj -> fp16
    k_mma_gemm<<<dim3(DIMC / 128, (NROWS_WIN + 127) / 128), 256, GEMM_SMEM>>>(
        attno, projT, proj_b, proj, NROWS_WIN, DIMC, DIMC, 0, 1, nullptr);
    // residual + LN2
    k_scatter_ln2<<<NROWS_IMG, 192>>>(xnhwc, proj, ln2_w, ln2_b, x1, yln);
    // FC1 + GELU -> fp16
    k_mma_gemm<<<dim3(MLPD / 128, NROWS_IMG / 128), 256, GEMM_SMEM>>>(
        yln, fc1T, fc1_b, h1, NROWS_IMG, MLPD, DIMC, 1, 1, nullptr);
    // FC2 -> fp32 with fused x1 residual
    k_mma_gemm<<<dim3(DIMC / 128, NROWS_IMG / 128), 256, GEMM_SMEM>>>(
        h1, fc2T, fc2_b, y2, NROWS_IMG, DIMC, MLPD, 0, 0, x1);
    // NHWC -> NCHW
    k_final<<<dim3(128, 24, BATCH), tb>>>(y2, out);
}

// round 17
// speedup vs baseline: 1.5895x; 1.0246x over previous
#include <cuda_runtime.h>
#include <cuda_fp16.h>
#include <math.h>
#include <stdint.h>

// ---------------- problem constants ----------------
#define DIMC    768
#define HEADS   12
#define HDIM    64
#define WS      14
#define NTOK    196
#define MLPD    3072
#define BATCH   4
#define IMGH    64
#define IMGW    64
#define NWIN    100
#define NROWS_WIN (NWIN*NTOK)
#define NROWS_IMG (BATCH*IMGH*IMGW)
#define NBH     (NWIN*HEADS)
#define SLD     224
#define SCALE_F 0.125f
#define EPS_F   1e-6f

// ---------------- scratch ----------------
__device__ float   g_xnhwc[BATCH*IMGH*IMGW*DIMC];
__device__ __half  g_xwin [NROWS_WIN*DIMC];
__device__ __half  g_qkv  [NROWS_WIN*3*DIMC];
__device__ __half  g_S    [(long)NBH*NTOK*SLD];
__device__ __half  g_Vt   [(long)NBH*HDIM*SLD];
__device__ __half  g_attno[NROWS_WIN*DIMC];
__device__ __half  g_proj [NROWS_WIN*DIMC];
__device__ float   g_x1   [NROWS_IMG*DIMC];
__device__ __half  g_yln  [NROWS_IMG*DIMC];
__device__ __half  g_h1   [NROWS_IMG*MLPD];
__device__ float   g_y2   [NROWS_IMG*DIMC];
__device__ __half  g_qkvT [3*DIMC*DIMC];
__device__ __half  g_projT[DIMC*DIMC];
__device__ __half  g_fc1T [MLPD*DIMC];
__device__ __half  g_fc2T [DIMC*MLPD];

// ================= helpers =================
__device__ __forceinline__ uint32_t smem_u32(const void* p) {
    uint32_t a;
    asm("{ .reg .u64 t; cvta.to.shared.u64 t, %1; cvt.u32.u64 %0, t; }" : "=r"(a) : "l"(p));
    return a;
}
__device__ __forceinline__ void cp_async16(uint32_t dst, const void* src) {
    asm volatile("cp.async.cg.shared.global [%0], [%1], 16;" :: "r"(dst), "l"(src));
}
#define CP_COMMIT() asm volatile("cp.async.commit_group;" ::: "memory")
#define CP_WAIT(n)  asm volatile("cp.async.wait_group %0;" :: "n"(n) : "memory")

__device__ __forceinline__ void mma_f16(float* c, const uint32_t* a, const uint32_t* b) {
    asm volatile(
        "mma.sync.aligned.m16n8k16.row.col.f32.f16.f16.f32 "
        "{%0,%1,%2,%3}, {%4,%5,%6,%7}, {%8,%9}, {%0,%1,%2,%3};"
        : "+f"(c[0]), "+f"(c[1]), "+f"(c[2]), "+f"(c[3])
        : "r"(a[0]), "r"(a[1]), "r"(a[2]), "r"(a[3]), "r"(b[0]), "r"(b[1]));
}
__device__ __forceinline__ void ldmx4(uint32_t& r0, uint32_t& r1, uint32_t& r2, uint32_t& r3,
                                      uint32_t addr) {
    asm volatile("ldmatrix.sync.aligned.m8n8.x4.shared.b16 {%0,%1,%2,%3}, [%4];"
        : "=r"(r0), "=r"(r1), "=r"(r2), "=r"(r3) : "r"(addr));
}

// ================= fp16 mma.sync GEMM: BKE=64 K-chunks, optional residual =====
#define BM 128
#define BN 128
#define BKE2 64
#define LDW2 36
#define TBUF2 (BM*LDW2)
#define GEMM_SMEM ((4*TBUF2 + 128) * 4)

__global__ void __launch_bounds__(256, 2)
k_mma_gemm(const __half* __restrict__ A, const __half* __restrict__ Bt,
           const float* __restrict__ bias, void* __restrict__ Cout,
           int M, int N, int K, int act, int outf16,
           const float* __restrict__ resid) {
    extern __shared__ float sm[];
    uint32_t* As = (uint32_t*)sm;
    uint32_t* Bs = As + 2*TBUF2;
    float* sbias = sm + 4*TBUF2;

    int tid = threadIdx.x, lane = tid & 31, wid = tid >> 5;
    int wm = wid >> 1, wn = wid & 1;
    int m0 = blockIdx.y * BM, n0 = blockIdx.x * BN;

    if (tid < 128) sbias[tid] = bias[n0 + tid];

    auto load_tile = [&](int kc, int bsel) {
        int k0 = kc * BKE2;
        uint32_t* abuf = As + bsel * TBUF2;
        uint32_t* bbuf = Bs + bsel * TBUF2;
        #pragma unroll
        for (int it = 0; it < 4; it++) {
            int idx = tid + it * 256;
            int r = idx >> 3, c = idx & 7;
            int ar = m0 + r;
            const __half* asrc = A + (long)(ar < M ? ar : M - 1) * K + k0 + c * 8;
            cp_async16(smem_u32(abuf + r * LDW2 + c * 4), asrc);
            const __half* bsrc = Bt + (long)(n0 + r) * K + k0 + c * 8;
            cp_async16(smem_u32(bbuf + r * LDW2 + c * 4), bsrc);
        }
        CP_COMMIT();
    };

    int m8 = lane >> 3, r8 = lane & 7;
    uint32_t aoff[2], boff[4];
    #pragma unroll
    for (int mt = 0; mt < 2; mt++)
        aoff[mt] = (uint32_t)((wm * 32 + mt * 16 + (m8 & 1) * 8 + r8) * LDW2 + (m8 >> 1) * 4);
    #pragma unroll
    for (int p = 0; p < 4; p++)
        boff[p] = (uint32_t)((wn * 64 + p * 16 + (m8 >> 1) * 8 + r8) * LDW2 + (m8 & 1) * 4);
    uint32_t a_base = smem_u32(As);
    uint32_t b_base = smem_u32(Bs);

    float acc[2][8][4];
    #pragma unroll
    for (int mt = 0; mt < 2; mt++)
        #pragma unroll
        for (int nt = 0; nt < 8; nt++)
            #pragma unroll
            for (int j = 0; j < 4; j++) acc[mt][nt][j] = 0.f;

    const int NKC = K / BKE2;
    load_tile(0, 0);
    for (int i = 0; i < NKC; i++) {
        int cur = i & 1;
        if (i + 1 < NKC) { load_tile(i + 1, cur ^ 1); CP_WAIT(1); }
        else             { CP_WAIT(0); }
        __syncthreads();
        uint32_t ab = a_base + cur * (TBUF2 * 4);
        uint32_t bb = b_base + cur * (TBUF2 * 4);
        #pragma unroll
        for (int ks = 0; ks < 4; ks++) {
            uint32_t af[2][4], bf[8][2];
            #pragma unroll
            for (int mt = 0; mt < 2; mt++)
                ldmx4(af[mt][0], af[mt][1], af[mt][2], af[mt][3],
                      ab + (aoff[mt] + ks * 8) * 4);
            #pragma unroll
            for (int p = 0; p < 4; p++)
                ldmx4(bf[2*p][0], bf[2*p][1], bf[2*p+1][0], bf[2*p+1][1],
                      bb + (boff[p] + ks * 8) * 4);
            #pragma unroll
            for (int mt = 0; mt < 2; mt++)
                #pragma unroll
                for (int nt = 0; nt < 8; nt++)
                    mma_f16(acc[mt][nt], af[mt], bf[nt]);
        }
        __syncthreads();
    }

    int rb = m0 + wm * 32 + (lane >> 2);
    int cb = wn * 64 + 2 * (lane & 3);
    #pragma unroll
    for (int mt = 0; mt < 2; mt++) {
        int r0 = rb + mt * 16, r1 = r0 + 8;
        #pragma unroll
        for (int nt = 0; nt < 8; nt++) {
            int cc = cb + nt * 8;
            float v0 = acc[mt][nt][0] + sbias[cc];
            float v1 = acc[mt][nt][1] + sbias[cc + 1];
            float v2 = acc[mt][nt][2] + sbias[cc];
            float v3 = acc[mt][nt][3] + sbias[cc + 1];
            if (act == 1) {
                v0 = 0.5f * v0 * (1.0f + erff(v0 * 0.70710678118654752f));
                v1 = 0.5f * v1 * (1.0f + erff(v1 * 0.70710678118654752f));
                v2 = 0.5f * v2 * (1.0f + erff(v2 * 0.70710678118654752f));
                v3 = 0.5f * v3 * (1.0f + erff(v3 * 0.70710678118654752f));
            }
            if (resid) {
                if (r0 < M) {
                    float2 rr = *(const float2*)(resid + (long)r0 * N + n0 + cc);
                    v0 += rr.x; v1 += rr.y;
                }
                if (r1 < M) {
                    float2 rr = *(const float2*)(resid + (long)r1 * N + n0 + cc);
                    v2 += rr.x; v3 += rr.y;
                }
            }
            if (outf16) {
                __half* C = (__half*)Cout;
                if (r0 < M) *(__half2*)(C + (long)r0 * N + n0 + cc) = __floats2half2_rn(v0, v1);
                if (r1 < M) *(__half2*)(C + (long)r1 * N + n0 + cc) = __floats2half2_rn(v2, v3);
            } else {
                float* C = (float*)Cout;
                if (r0 < M) *(float2*)(C + (long)r0 * N + n0 + cc) = make_float2(v0, v1);
                if (r1 < M) *(float2*)(C + (long)r1 * N + n0 + cc) = make_float2(v2, v3);
            }
        }
    }
}

// ============ fused QK^T + rel-pos bias + softmax -> P (per win,head) =========
// grid (1, 2, NBH): each CTA computes 128 rows x 224 cols of S, softmaxes, writes P.
#define BKE 32
#define LDW 20
#define QS_ATB (128*LDW)           // A tile words per buffer
#define QS_BTB (224*LDW)           // B tile words per buffer
#define QS_SMEM ((2*QS_ATB + 2*QS_BTB) * 4)   // 55.0 KB
#define RELSTRIDE 65
// phase-2 smem offsets (floats)
#define O_RH   0
#define O_RW   (27*RELSTRIDE)
#define O_RHQ  (2*27*RELSTRIDE)
#define O_RWQ  (O_RHQ + 128*14)
#define O_RED1 (O_RWQ + 128*14)
#define O_RED2 (O_RED1 + 256)
#define O_KH   (O_RED2 + 256)
#define O_KW   (O_KH + 224)

__global__ void __launch_bounds__(256)
k_qk_softmax(const __half* __restrict__ qkv, __half* __restrict__ S,
             const float* __restrict__ rel_pos_h, const float* __restrict__ rel_pos_w) {
    extern __shared__ float sm[];
    uint32_t* As = (uint32_t*)sm;
    uint32_t* Bs = As + 2*QS_ATB;

    int tid = threadIdx.x, lane = tid & 31, wid = tid >> 5;
    int wm = wid >> 1, wn = wid & 1;
    int m0 = blockIdx.y * 128;
    int bz = blockIdx.z;
    int win = bz / HEADS, head = bz % HEADS;
    const __half* Qb = qkv + (long)win * NTOK * (3 * DIMC) + head * HDIM;
    const __half* Kb = Qb + DIMC;
    __half* Sb = S + (long)bz * NTOK * SLD;

    auto load_tile = [&](int kc, int bsel) {
        int k0 = kc * BKE;
        uint32_t* abuf = As + bsel * QS_ATB;
        uint32_t* bbuf = Bs + bsel * QS_BTB;
        #pragma unroll
        for (int it = 0; it < 2; it++) {             // A: 512 chunks
            int idx = tid + it * 256;
            int r = idx >> 2, c = idx & 3;
            int ar = m0 + r; ar = ar < NTOK ? ar : NTOK - 1;
            cp_async16(smem_u32(abuf + r * LDW + c * 4), Qb + (long)ar * (3 * DIMC) + k0 + c * 8);
        }
        #pragma unroll
        for (int it = 0; it < 4; it++) {             // B: 896 chunks
            int idx = tid + it * 256;
            if (idx < 896) {
                int r = idx >> 2, c = idx & 3;
                int br = r < NTOK ? r : NTOK - 1;
                cp_async16(smem_u32(bbuf + r * LDW + c * 4), Kb + (long)br * (3 * DIMC) + k0 + c * 8);
            }
        }
        CP_COMMIT();
    };

    int m8 = lane >> 3, r8 = lane & 7;
    uint32_t aoff[2], boff[7];
    #pragma unroll
    for (int mt = 0; mt < 2; mt++)
        aoff[mt] = (uint32_t)((wm * 32 + mt * 16 + (m8 & 1) * 8 + r8) * LDW + (m8 >> 1) * 4);
    #pragma unroll
    for (int p = 0; p < 7; p++)
        boff[p] = (uint32_t)((wn * 112 + p * 16 + (m8 >> 1) * 8 + r8) * LDW + (m8 & 1) * 4);
    uint32_t a_base = smem_u32(As);
    uint32_t b_base = smem_u32(Bs);

    float acc[2][14][4];
    #pragma unroll
    for (int mt = 0; mt < 2; mt++)
        #pragma unroll
        for (int nt = 0; nt < 14; nt++)
            #pragma unroll
            for (int j = 0; j < 4; j++) acc[mt][nt][j] = 0.f;

    load_tile(0, 0);
    #pragma unroll
    for (int i = 0; i < 2; i++) {     // K = 64 -> 2 chunks
        int cur = i & 1;
        if (i + 1 < 2) { load_tile(1, 1); CP_WAIT(1); }
        else           { CP_WAIT(0); }
        __syncthreads();
        uint32_t ab = a_base + cur * (QS_ATB * 4);
        uint32_t bb = b_base + cur * (QS_BTB * 4);
        #pragma unroll
        for (int ks = 0; ks < 2; ks++) {
            uint32_t af[2][4], bf[14][2];
            #pragma unroll
            for (int mt = 0; mt < 2; mt++)
                ldmx4(af[mt][0], af[mt][1], af[mt][2], af[mt][3],
                      ab + (aoff[mt] + ks * 8) * 4);
            #pragma unroll
            for (int p = 0; p < 7; p++)
                ldmx4(bf[2*p][0], bf[2*p][1], bf[2*p+1][0], bf[2*p+1][1],
                      bb + (boff[p] + ks * 8) * 4);
            #pragma unroll
            for (int mt = 0; mt < 2; mt++)
                #pragma unroll
                for (int nt = 0; nt < 14; nt++)
                    mma_f16(acc[mt][nt], af[mt], bf[nt]);
        }
        __syncthreads();
    }
    __syncthreads();   // done with tiles; repurpose smem

    // ---- phase 2: rel-pos tables + per-row bias dots ----
    float* RH  = sm + O_RH;
    float* RW  = sm + O_RW;
    float* RHq = sm + O_RHQ;
    float* RWq = sm + O_RWQ;
    float* red1 = sm + O_RED1;
    float* red2 = sm + O_RED2;
    int*   khtab = (int*)(sm + O_KH);
    int*   kwtab = (int*)(sm + O_KW);

    for (int i = tid; i < 27 * HDIM; i += 256) {
        int r = i >> 6, d = i & 63;
        RH[r * RELSTRIDE + d] = rel_pos_h[i];
        RW[r * RELSTRIDE + d] = rel_pos_w[i];
    }
    for (int i = tid; i < 224; i += 256) {
        khtab[i] = i / WS;
        kwtab[i] = i % WS;
    }
    __syncthreads();

    for (int i = tid; i < 128 * WS; i += 256) {
        int row = i / WS, kh = i % WS;
        int grow = m0 + row;
        float sh = 0.f, sw = 0.f;
        if (grow < NTOK) {
            int qh = grow / WS, qw = grow % WS;
            const __half* qp = Qb + (long)grow * (3 * DIMC);
            const float* ph = &RH[(qh - kh + WS - 1) * RELSTRIDE];
            const float* pw = &RW[(qw - kh + WS - 1) * RELSTRIDE];
            #pragma unroll
            for (int d = 0; d < HDIM; d += 2) {
                float2 qf = __half22float2(*(const __half2*)(qp + d));
                sh = fmaf(qf.x, ph[d], sh);   sh = fmaf(qf.y, ph[d + 1], sh);
                sw = fmaf(qf.x, pw[d], sw);   sw = fmaf(qf.y, pw[d + 1], sw);
            }
        }
        RHq[row * WS + kh] = sh;
        RWq[row * WS + kh] = sw;
    }
    __syncthreads();

    // ---- apply scale + bias, mask pad cols; per-row max ----
    int q8 = lane >> 2;
    int cbase = wn * 112 + 2 * (lane & 3);
    float rmax[2][2];
    #pragma unroll
    for (int mt = 0; mt < 2; mt++) { rmax[mt][0] = -1e30f; rmax[mt][1] = -1e30f; }
    #pragma unroll
    for (int mt = 0; mt < 2; mt++) {
        int lr0 = wm * 32 + mt * 16 + q8;          // local rows
        int lr1 = lr0 + 8;
        #pragma unroll
        for (int nt = 0; nt < 14; nt++) {
            int c0 = cbase + nt * 8, c1 = c0 + 1;
            float b00 = RHq[lr0 * WS + khtab[c0]] + RWq[lr0 * WS + kwtab[c0]];
            float b01 = RHq[lr0 * WS + khtab[c1]] + RWq[lr0 * WS + kwtab[c1]];
            float b10 = RHq[lr1 * WS + khtab[c0]] + RWq[lr1 * WS + kwtab[c0]];
            float b11 = RHq[lr1 * WS + khtab[c1]] + RWq[lr1 * WS + kwtab[c1]];
            float s0 = (c0 < NTOK) ? acc[mt][nt][0] * SCALE_F + b00 : -1e30f;
            float s1 = (c1 < NTOK) ? acc[mt][nt][1] * SCALE_F + b01 : -1e30f;
            float s2 = (c0 < NTOK) ? acc[mt][nt][2] * SCALE_F + b10 : -1e30f;
            float s3 = (c1 < NTOK) ? acc[mt][nt][3] * SCALE_F + b11 : -1e30f;
            acc[mt][nt][0] = s0; acc[mt][nt][1] = s1;
            acc[mt][nt][2] = s2; acc[mt][nt][3] = s3;
            rmax[mt][0] = fmaxf(rmax[mt][0], fmaxf(s0, s1));
            rmax[mt][1] = fmaxf(rmax[mt][1], fmaxf(s2, s3));
        }
        rmax[mt][0] = fmaxf(rmax[mt][0], __shfl_xor_sync(0xffffffffu, rmax[mt][0], 1));
        rmax[mt][0] = fmaxf(rmax[mt][0], __shfl_xor_sync(0xffffffffu, rmax[mt][0], 2));
        rmax[mt][1] = fmaxf(rmax[mt][1], __shfl_xor_sync(0xffffffffu, rmax[mt][1], 1));
        rmax[mt][1] = fmaxf(rmax[mt][1], __shfl_xor_sync(0xffffffffu, rmax[mt][1], 2));
        if ((lane & 3) == 0) {
            red1[(lr0)*2 + wn] = rmax[mt][0];
            red1[(lr1)*2 + wn] = rmax[mt][1];
        }
    }
    __syncthreads();

    // ---- exp + per-row sum ----
    float rsum[2][2] = {{0.f, 0.f}, {0.f, 0.f}};
    float mj[2][2];
    #pragma unroll
    for (int mt = 0; mt < 2; mt++) {
        int lr0 = wm * 32 + mt * 16 + q8, lr1 = lr0 + 8;
        mj[mt][0] = fmaxf(red1[lr0*2], red1[lr0*2+1]);
        mj[mt][1] = fmaxf(red1[lr1*2], red1[lr1*2+1]);
        #pragma unroll
        for (int nt = 0; nt < 14; nt++) {
            float e0 = __expf(acc[mt][nt][0] - mj[mt][0]);
            float e1 = __expf(acc[mt][nt][1] - mj[mt][0]);
            float e2 = __expf(acc[mt][nt][2] - mj[mt][1]);
            float e3 = __expf(acc[mt][nt][3] - mj[mt][1]);
            acc[mt][nt][0] = e0; acc[mt][nt][1] = e1;
            acc[mt][nt][2] = e2; acc[mt][nt][3] = e3;
            rsum[mt][0] += e0 + e1;
            rsum[mt][1] += e2 + e3;
        }
        rsum[mt][0] += __shfl_xor_sync(0xffffffffu, rsum[mt][0], 1);
        rsum[mt][0] += __shfl_xor_sync(0xffffffffu, rsum[mt][0], 2);
        rsum[mt][1] += __shfl_xor_sync(0xffffffffu, rsum[mt][1], 1);
        rsum[mt][1] += __shfl_xor_sync(0xffffffffu, rsum[mt][1], 2);
        if ((lane & 3) == 0) {
            red2[(lr0)*2 + wn] = rsum[mt][0];
            red2[(lr1)*2 + wn] = rsum[mt][1];
        }
    }
    __syncthreads();

    // ---- normalize + store P ----
    #pragma unroll
    for (int mt = 0; mt < 2; mt++) {
        int lr0 = wm * 32 + mt * 16 + q8, lr1 = lr0 + 8;
        int grow0 = m0 + lr0, grow1 = m0 + lr1;
        float inv0 = 1.f / (red2[lr0*2] + red2[lr0*2+1]);
        float inv1 = 1.f / (red2[lr1*2] + red2[lr1*2+1]);
        #pragma unroll
        for (int nt = 0; nt < 14; nt++) {
            int c0 = cbase + nt * 8;
            if (grow0 < NTOK)
                *(__half2*)(Sb + (long)grow0 * SLD + c0) =
                    __floats2half2_rn(acc[mt][nt][0] * inv0, acc[mt][nt][1] * inv0);
            if (grow1 < NTOK)
                *(__half2*)(Sb + (long)grow1 * SLD + c0) =
                    __floats2half2_rn(acc[mt][nt][2] * inv1, acc[mt][nt][3] * inv1);
        }
    }
}

// ================= V transpose prep (vectorized output) ======
#define LDV 66
__global__ void __launch_bounds__(256)
k_vt(const __half* __restrict__ qkv, __half* __restrict__ Vt) {
    __shared__ __half smv[NTOK * LDV];
    int bz = blockIdx.x;
    int win = bz / HEADS, head = bz % HEADS;
    const __half* Vb = qkv + (long)win * NTOK * (3 * DIMC) + 2 * DIMC + head * HDIM;
    int tid = threadIdx.x;
    for (int i = tid; i < NTOK * HDIM; i += 256) {
        int t = i >> 6, d = i & 63;
        smv[t * LDV + d] = Vb[(long)t * (3 * DIMC) + d];
    }
    __syncthreads();
    __half* out = Vt + (long)bz * HDIM * SLD;
    for (int o8 = tid; o8 < HDIM * SLD / 8; o8 += 256) {
        int o = o8 * 8;
        int n = o / SLD, k = o - n * SLD;
        __half buf[8];
        #pragma unroll
        for (int j = 0; j < 8; j++)
            buf[j] = (k + j < NTOK) ? smv[(k + j) * LDV + n] : __float2half_rn(0.f);
        *(float4*)(out + o) = *(float4*)buf;
    }
}

// ================= batched PV GEMM ==
#define TBUFA (BM*LDW)
#define TBUFB (64*LDW)
#define PV_SMEM ((2*TBUFA + 2*TBUFB) * 4)

__global__ void __launch_bounds__(256, 2)
k_pv_gemm(const __half* __restrict__ S, const __half* __restrict__ Vt,
          __half* __restrict__ attno) {
    extern __shared__ float sm[];
    uint32_t* As = (uint32_t*)sm;
    uint32_t* Bs = As + 2*TBUFA;

    int tid = threadIdx.x, lane = tid & 31, wid = tid >> 5;
    int m0 = blockIdx.y * BM;
    int bz = blockIdx.z;
    int win = bz / HEADS, head = bz % HEADS;
    const __half* Pb = S + (long)bz * NTOK * SLD;
    const __half* Vb = Vt + (long)bz * HDIM * SLD;
    __half* Cb = attno + (long)win * NTOK * DIMC + head * HDIM;

    auto load_tile = [&](int kc, int bsel) {
        int k0 = kc * BKE;
        uint32_t* abuf = As + bsel * TBUFA;
        uint32_t* bbuf = Bs + bsel * TBUFB;
        #pragma unroll
        for (int it = 0; it < 2; it++) {
            int idx = tid + it * 256;
            int r = idx >> 2, c = idx & 3;
            int ar = m0 + r; ar = ar < NTOK ? ar : NTOK - 1;
            cp_async16(smem_u32(abuf + r * LDW + c * 4), Pb + (long)ar * SLD + k0 + c * 8);
        }
        {
            int r = tid >> 2, c = tid & 3;
            cp_async16(smem_u32(bbuf + r * LDW + c * 4), Vb + (long)r * SLD + k0 + c * 8);
        }
        CP_COMMIT();
    };

    int m8 = lane >> 3, r8 = lane & 7;
    uint32_t aoff = (uint32_t)((wid * 16 + (m8 & 1) * 8 + r8) * LDW + (m8 >> 1) * 4);
    uint32_t boff[4];
    #pragma unroll
    for (int p = 0; p < 4; p++)
        boff[p] = (uint32_t)((p * 16 + (m8 >> 1) * 8 + r8) * LDW + (m8 & 1) * 4);
    uint32_t a_base = smem_u32(As);
    uint32_t b_base = smem_u32(Bs);

    float acc[8][4];
    #pragma unroll
    for (int nt = 0; nt < 8; nt++)
        #pragma unroll
        for (int j = 0; j < 4; j++) acc[nt][j] = 0.f;

    const int NKC = SLD / BKE;
    load_tile(0, 0);
    for (int i = 0; i < NKC; i++) {
        int cur = i & 1;
        if (i + 1 < NKC) { load_tile(i + 1, cur ^ 1); CP_WAIT(1); }
        else             { CP_WAIT(0); }
        __syncthreads();
        uint32_t ab = a_base + cur * (TBUFA * 4);
        uint32_t bb = b_base + cur * (TBUFB * 4);
        #pragma unroll
        for (int ks = 0; ks < 2; ks++) {
            uint32_t af[4], bf[8][2];
            ldmx4(af[0], af[1], af[2], af[3], ab + (aoff + ks * 8) * 4);
            #pragma unroll
            for (int p = 0; p < 4; p++)
                ldmx4(bf[2*p][0], bf[2*p][1], bf[2*p+1][0], bf[2*p+1][1],
                      bb + (boff[p] + ks * 8) * 4);
            #pragma unroll
            for (int nt = 0; nt < 8; nt++)
                mma_f16(acc[nt], af, bf[nt]);
        }
        __syncthreads();
    }

    int r0 = m0 + wid * 16 + (lane >> 2), r1 = r0 + 8;
    int cb = 2 * (lane & 3);
    #pragma unroll
    for (int nt = 0; nt < 8; nt++) {
        int cc = cb + nt * 8;
        if (r0 < NTOK) *(__half2*)(Cb + (long)r0 * DIMC + cc) =
            __floats2half2_rn(acc[nt][0], acc[nt][1]);
        if (r1 < NTOK) *(__half2*)(Cb + (long)r1 * DIMC + cc) =
            __floats2half2_rn(acc[nt][2], acc[nt][3]);
    }
}

// ---------------- NCHW -> NHWC transpose ----------------
__global__ void k_transpose_in(const float* __restrict__ in, float* __restrict__ out) {
    __shared__ float tile[32][33];
    int b = blockIdx.z, c0 = blockIdx.y * 32, s0 = blockIdx.x * 32;
    const float* ib = in + (long)b * DIMC * 4096;
    float* ob = out + (long)b * 4096 * DIMC;
    int x = threadIdx.x, y = threadIdx.y;
    #pragma unroll
    for (int i = 0; i < 32; i += 8)
        tile[y + i][x] = ib[(long)(c0 + y + i) * 4096 + s0 + x];
    __syncthreads();
    #pragma unroll
    for (int i = 0; i < 32; i += 8)
        ob[(long)(s0 + y + i) * DIMC + c0 + x] = tile[x][y + i];
}

// ---------------- weight transpose to fp16 ----------------
__global__ void k_transpose_w(const float* __restrict__ in, __half* __restrict__ out,
                              int R, int C) {
    __shared__ float tile[32][33];
    int r0 = blockIdx.y * 32, c0 = blockIdx.x * 32;
    int x = threadIdx.x, y = threadIdx.y;
    #pragma unroll
    for (int i = 0; i < 32; i += 8)
        tile[y + i][x] = in[(long)(r0 + y + i) * C + c0 + x];
    __syncthreads();
    #pragma unroll
    for (int i = 0; i < 32; i += 8)
        out[(long)(c0 + y + i) * R + r0 + x] = __float2half_rn(tile[x][y + i]);
}

// ---------------- block reduction (192 threads, 6 warps) ----------------
__device__ __forceinline__ float block_sum_192(float v, float* red) {
    int tid = threadIdx.x;
    #pragma unroll
    for (int o = 16; o > 0; o >>= 1) v += __shfl_xor_sync(0xffffffffu, v, o);
    if ((tid & 31) == 0) red[tid >> 5] = v;
    __syncthreads();
    float r = 0.f;
    if (tid < 8) {
        r = (tid < 6) ? red[tid] : 0.f;
        #pragma unroll
        for (int o = 4; o > 0; o >>= 1) r += __shfl_xor_sync(0xffu, r, o);
        if (tid == 0) red[0] = r;
    }
    __syncthreads();
    r = red[0];
    __syncthreads();
    return r;
}

// ---------------- LN1 + window partition (vectorized, 192 threads) ------------
__global__ void __launch_bounds__(192)
k_ln1_window(const float* __restrict__ xnhwc,
             const float* __restrict__ w, const float* __restrict__ bs,
             __half* __restrict__ xwin) {
    __shared__ float red[8];
    int idx = blockIdx.x;
    int win = idx / NTOK, t = idx % NTOK;
    int b = win / 25, wrem = win % 25;
    int gr = (wrem / 5) * WS + t / WS;
    int gc = (wrem % 5) * WS + t % WS;
    __half* orow = xwin + (long)idx * DIMC;
    int tid = threadIdx.x;
    int c4 = tid * 4;
    if (gr >= IMGH || gc >= IMGW) {
        __half z[4] = {__float2half_rn(0.f), __float2half_rn(0.f),
                       __float2half_rn(0.f), __float2half_rn(0.f)};
        *(uint2*)(orow + c4) = *(uint2*)z;
        return;
    }
    const float* irow = xnhwc + ((long)b * 4096 + gr * IMGW + gc) * DIMC;
    float4 v = *(const float4*)(irow + c4);
    float s = v.x + v.y + v.z + v.w;
    float s2 = v.x * v.x + v.y * v.y + v.z * v.z + v.w * v.w;
    float tot = block_sum_192(s, red);
    float tot2 = block_sum_192(s2, red);
    float mu = tot * (1.f / DIMC);
    float rstd = rsqrtf(tot2 * (1.f / DIMC) - mu * mu + EPS_F);
    float4 wv = *(const float4*)(w + c4);
    float4 bv = *(const float4*)(bs + c4);
    __half o[4];
    o[0] = __float2half_rn((v.x - mu) * rstd * wv.x + bv.x);
    o[1] = __float2half_rn((v.y - mu) * rstd * wv.y + bv.y);
    o[2] = __float2half_rn((v.z - mu) * rstd * wv.z + bv.z);
    o[3] = __float2half_rn((v.w - mu) * rstd * wv.w + bv.w);
    *(uint2*)(orow + c4) = *(uint2*)o;
}

// ---------------- fused: unpartition + residual + LN2 (vectorized, 192 thr) ---
__global__ void __launch_bounds__(192)
k_scatter_ln2(const float* __restrict__ xnhwc, const __half* __restrict__ proj,
              const float* __restrict__ w, const float* __restrict__ bs,
              float* __restrict__ x1, __half* __restrict__ yln) {
    __shared__ float red[8];
    int row = blockIdx.x;
    int b = row >> 12, sp = row & 4095;
    int r = sp >> 6, cw = sp & 63;
    int win = b * 25 + (r / WS) * 5 + (cw / WS);
    int t = (r % WS) * WS + (cw % WS);
    const __half* prow = proj + ((long)win * NTOK + t) * DIMC;
    const float* xrow = xnhwc + (long)row * DIMC;
    float* orow = x1 + (long)row * DIMC;
    __half* lrow = yln + (long)row * DIMC;
    int tid = threadIdx.x;
    int c4 = tid * 4;
    float4 xv = *(const float4*)(xrow + c4);
    __half pb[4];
    *(uint2*)pb = *(const uint2*)(prow + c4);
    float4 v;
    v.x = xv.x + __half2float(pb[0]);
    v.y = xv.y + __half2float(pb[1]);
    v.z = xv.z + __half2float(pb[2]);
    v.w = xv.w + __half2float(pb[3]);
    *(float4*)(orow + c4) = v;
    float s = v.x + v.y + v.z + v.w;
    float s2 = v.x * v.x + v.y * v.y + v.z * v.z + v.w * v.w;
    float tot = block_sum_192(s, red);
    float tot2 = block_sum_192(s2, red);
    float mu = tot * (1.f / DIMC);
    float rstd = rsqrtf(tot2 * (1.f / DIMC) - mu * mu + EPS_F);
    float4 wv = *(const float4*)(w + c4);
    float4 bv = *(const float4*)(bs + c4);
    __half o[4];
    o[0] = __float2half_rn((v.x - mu) * rstd * wv.x + bv.x);
    o[1] = __float2half_rn((v.y - mu) * rstd * wv.y + bv.y);
    o[2] = __float2half_rn((v.z - mu) * rstd * wv.z + bv.z);
    o[3] = __float2half_rn((v.w - mu) * rstd * wv.w + bv.w);
    *(uint2*)(lrow + c4) = *(uint2*)o;
}

// ---------------- final: y2 NHWC -> NCHW ----------------
__global__ void k_final(const float* __restrict__ y2, float* __restrict__ out) {
    __shared__ float tile[32][33];
    int b = blockIdx.z, s0 = blockIdx.x * 32, c0 = blockIdx.y * 32;
    int x = threadIdx.x, y = threadIdx.y;
    #pragma unroll
    for (int i = 0; i < 32; i += 8) {
        long row = (long)b * 4096 + s0 + y + i;
        tile[y + i][x] = y2[row * DIMC + c0 + x];
    }
    __syncthreads();
    #pragma unroll
    for (int i = 0; i < 32; i += 8)
        out[((long)b * DIMC + c0 + y + i) * 4096 + s0 + x] = tile[x][y + i];
}

// ---------------- launcher ----------------
extern "C" void kernel_launch(void* const* d_in, const int* in_sizes, int n_in,
                              void* d_out, int out_size) {
    const float* hidden = (const float*)d_in[0];
    const float* ln1_w = (const float*)d_in[1];
    const float* ln1_b = (const float*)d_in[2];
    const float* qkv_w = (const float*)d_in[3];
    const float* qkv_b = (const float*)d_in[4];
    const float* proj_w = (const float*)d_in[5];
    const float* proj_b = (const float*)d_in[6];
    const float* relh = (const float*)d_in[7];
    const float* relw = (const float*)d_in[8];
    const float* ln2_w = (const float*)d_in[9];
    const float* ln2_b = (const float*)d_in[10];
    const float* fc1_w = (const float*)d_in[11];
    const float* fc1_b = (const float*)d_in[12];
    const float* fc2_w = (const float*)d_in[13];
    const float* fc2_b = (const float*)d_in[14];
    float* out = (float*)d_out;

    float *xnhwc, *x1, *y2;
    __half *xwin, *qkv, *S, *Vt, *attno, *proj, *yln, *h1, *qkvT, *projT, *fc1T, *fc2T;
    cudaGetSymbolAddress((void**)&xnhwc, g_xnhwc);
    cudaGetSymbolAddress((void**)&xwin, g_xwin);
    cudaGetSymbolAddress((void**)&qkv, g_qkv);
    cudaGetSymbolAddress((void**)&S, g_S);
    cudaGetSymbolAddress((void**)&Vt, g_Vt);
    cudaGetSymbolAddress((void**)&attno, g_attno);
    cudaGetSymbolAddress((void**)&proj, g_proj);
    cudaGetSymbolAddress((void**)&x1, g_x1);
    cudaGetSymbolAddress((void**)&yln, g_yln);
    cudaGetSymbolAddress((void**)&h1, g_h1);
    cudaGetSymbolAddress((void**)&y2, g_y2);
    cudaGetSymbolAddress((void**)&qkvT, g_qkvT);
    cudaGetSymbolAddress((void**)&projT, g_projT);
    cudaGetSymbolAddress((void**)&fc1T, g_fc1T);
    cudaGetSymbolAddress((void**)&fc2T, g_fc2T);

    cudaFuncSetAttribute(k_mma_gemm, cudaFuncAttributeMaxDynamicSharedMemorySize, GEMM_SMEM);
    cudaFuncSetAttribute(k_qk_softmax, cudaFuncAttributeMaxDynamicSharedMemorySize, QS_SMEM);
    cudaFuncSetAttribute(k_pv_gemm, cudaFuncAttributeMaxDynamicSharedMemorySize, PV_SMEM);

    dim3 tb(32, 8);
    // weight transposes
    k_transpose_w<<<dim3(3 * DIMC / 32, DIMC / 32), tb>>>(qkv_w, qkvT, DIMC, 3 * DIMC);
    k_transpose_w<<<dim3(DIMC / 32, DIMC / 32), tb>>>(proj_w, projT, DIMC, DIMC);
    k_transpose_w<<<dim3(MLPD / 32, DIMC / 32), tb>>>(fc1_w, fc1T, DIMC, MLPD);
    k_transpose_w<<<dim3(DIMC / 32, MLPD / 32), tb>>>(fc2_w, fc2T, MLPD, DIMC);

    // NCHW -> NHWC, LN1+window
    k_transpose_in<<<dim3(128, 24, BATCH), tb>>>(hidden, xnhwc);
    k_ln1_window<<<NROWS_WIN, 192>>>(xnhwc, ln1_w, ln1_b, xwin);
    // QKV GEMM -> fp16
    k_mma_gemm<<<dim3(3 * DIMC / 128, (NROWS_WIN + 127) / 128), 256, GEMM_SMEM>>>(
        xwin, qkvT, qkv_b, qkv, NROWS_WIN, 3 * DIMC, DIMC, 0, 1, nullptr);
    // attention: Vt prep, fused QK+softmax -> P, PV
    k_vt<<<NBH, 256>>>(qkv, Vt);
    k_qk_softmax<<<dim3(1, 2, NBH), 256, QS_SMEM>>>(qkv, S, relh, relw);
    k_pv_gemm<<<dim3(1, 2, NBH), 256, PV_SMEM>>>(S, Vt, attno);
    // proj -> fp16
    k_mma_gemm<<<dim3(DIMC / 128, (NROWS_WIN + 127) / 128), 256, GEMM_SMEM>>>(
        attno, projT, proj_b, proj, NROWS_WIN, DIMC, DIMC, 0, 1, nullptr);
    // residual + LN2
    k_scatter_ln2<<<NROWS_IMG, 192>>>(xnhwc, proj, ln2_w, ln2_b, x1, yln);
    // FC1 + GELU -> fp16
    k_mma_gemm<<<dim3(MLPD / 128, NROWS_IMG / 128), 256, GEMM_SMEM>>>(
        yln, fc1T, fc1_b, h1, NROWS_IMG, MLPD, DIMC, 1, 1, nullptr);
    // FC2 -> fp32 with fused x1 residual
    k_mma_gemm<<<dim3(DIMC / 128, NROWS_IMG / 128), 256, GEMM_SMEM>>>(
        h1, fc2T, fc2_b, y2, NROWS_IMG, DIMC, MLPD, 0, 0, x1);
    // NHWC -> NCHW
    k_final<<<dim3(128, 24, BATCH), tb>>>(y2, out);
}